// round 1
// baseline (speedup 1.0000x reference)
#include <cuda_runtime.h>
#include <math.h>

// Problem constants
#define Bb  8
#define Ss  4096
#define Dd  512
#define Pp  128
#define Ll  4
#define DFf 2048
#define DHh 256
#define CC  2
#define BS  (Bb*Ss)
#define KV_SPLIT 8

// ---------------- scratch (static device globals; no allocs) ----------------
__device__ float g_h [BS*Dd];
__device__ float g_q [BS*Dd];
__device__ float g_k [BS*Dd];
__device__ float g_v [BS*Dd];
__device__ float g_t [BS*Dd];
__device__ float g_pq[BS*Pp];
__device__ float g_pk[BS*Pp];
__device__ float g_kvp[Bb*KV_SPLIT*Pp*Dd];
__device__ float g_kv [Bb*Pp*Dd];
__device__ float g_ksp[Bb*32*Pp];
__device__ float g_ks [Bb*Pp];
__device__ float g_z  [BS];
__device__ float g_m  [(size_t)BS*DFf];
__device__ float g_pp [Bb*32*Dd];
__device__ float g_pool[Bb*Dd];
__device__ float g_h1 [Bb*DHh];

// ---------------- helpers ----------------
__device__ __forceinline__ float gelu_tanh(float x){
    float u = 0.7978845608028654f*(x + 0.044715f*x*x*x);
    return 0.5f*x*(1.0f + tanhf(u));
}

#define BM 128
#define BN 128
#define BK 16

// C[M,N] = A[M,K] @ B[K,N] (+epilogue). Batched via blockIdx.z with strides.
// EPI: 0 = +bias ; 1 = +bias then elu()+1 ; 2 = +bias then gelu(tanh) ;
//      3 = no bias, scale by 1/(aux[row]+1e-6)
template<int EPI>
__global__ void __launch_bounds__(256)
sgemm_nn(const float* __restrict__ A, const float* __restrict__ Bm,
         const float* __restrict__ bias, const float* __restrict__ aux,
         float* __restrict__ Cm, int M, int N, int K,
         long sA, long sB, long sC)
{
    __shared__ float As[BK][BM];
    __shared__ float Bs[BK][BN];
    const int bx = blockIdx.x, by = blockIdx.y, bz = blockIdx.z;
    const float* Ab = A  + (long)bz*sA;
    const float* Bp = Bm + (long)bz*sB + bx*BN;
    float*       Cb = Cm + (long)bz*sC;
    const int tid = threadIdx.x;
    const int aRow = tid>>2, aCol = (tid&3)<<2;
    const int bRow = tid>>5, bCol = (tid&31)<<2;
    const int tr = tid>>4, tc = tid&15;
    const float* Ap = Ab + (long)(by*BM)*K;

    float acc[8][8];
    #pragma unroll
    for (int i=0;i<8;i++)
        #pragma unroll
        for (int j=0;j<8;j++) acc[i][j]=0.f;

    for (int k0=0; k0<K; k0+=BK){
        float4 a0 = *(const float4*)(Ap + (long)aRow*K      + k0 + aCol);
        float4 a1 = *(const float4*)(Ap + (long)(aRow+64)*K + k0 + aCol);
        As[aCol+0][aRow]=a0.x; As[aCol+1][aRow]=a0.y; As[aCol+2][aRow]=a0.z; As[aCol+3][aRow]=a0.w;
        As[aCol+0][aRow+64]=a1.x; As[aCol+1][aRow+64]=a1.y; As[aCol+2][aRow+64]=a1.z; As[aCol+3][aRow+64]=a1.w;
        *(float4*)&Bs[bRow  ][bCol] = *(const float4*)(Bp + (long)(k0+bRow  )*N + bCol);
        *(float4*)&Bs[bRow+8][bCol] = *(const float4*)(Bp + (long)(k0+bRow+8)*N + bCol);
        __syncthreads();
        #pragma unroll
        for (int kk=0; kk<BK; kk++){
            float4 ra0 = *(const float4*)&As[kk][tr*8];
            float4 ra1 = *(const float4*)&As[kk][tr*8+4];
            float4 rb0 = *(const float4*)&Bs[kk][tc*8];
            float4 rb1 = *(const float4*)&Bs[kk][tc*8+4];
            float ra[8]={ra0.x,ra0.y,ra0.z,ra0.w,ra1.x,ra1.y,ra1.z,ra1.w};
            float rb[8]={rb0.x,rb0.y,rb0.z,rb0.w,rb1.x,rb1.y,rb1.z,rb1.w};
            #pragma unroll
            for (int i=0;i<8;i++)
                #pragma unroll
                for (int j=0;j<8;j++)
                    acc[i][j] = fmaf(ra[i], rb[j], acc[i][j]);
        }
        __syncthreads();
    }

    const int col0 = bx*BN + tc*8;
    float bv[8];
    if (EPI != 3){
        #pragma unroll
        for (int j=0;j<8;j++) bv[j] = bias[col0+j];
    }
    const float* auxb = (EPI==3) ? (aux + (long)bz*M) : nullptr;
    #pragma unroll
    for (int i=0;i<8;i++){
        const int row = by*BM + tr*8 + i;
        float sc = 1.f;
        if (EPI==3) sc = 1.f/(auxb[row] + 1e-6f);
        float o[8];
        #pragma unroll
        for (int j=0;j<8;j++){
            float c = acc[i][j];
            if (EPI!=3) c += bv[j];
            if (EPI==1) c = (c>0.f) ? (c+1.f) : expf(c);   // elu(c)+1
            if (EPI==2) c = gelu_tanh(c);
            if (EPI==3) c *= sc;
            o[j]=c;
        }
        float4* dst = (float4*)(Cb + (long)row*N + col0);
        dst[0] = make_float4(o[0],o[1],o[2],o[3]);
        dst[1] = make_float4(o[4],o[5],o[6],o[7]);
    }
}

// Cpart = A^T @ B with split-K. A: [K,M] (lda=M==128), B: [K,N]. grid.z = batch*splits.
__global__ void __launch_bounds__(256)
sgemm_tn_splitk(const float* __restrict__ A, const float* __restrict__ Bm,
                float* __restrict__ Cpart, int M, int N, int K,
                long sA, long sB, int splits)
{
    __shared__ float As[BK][BM];
    __shared__ float Bs[BK][BN];
    const int bx = blockIdx.x, bz = blockIdx.z;
    const int b = bz / splits, sp = bz % splits;
    const int Kc = K / splits, kbeg = sp*Kc, kend = kbeg + Kc;
    const float* Ab = A  + (long)b*sA;
    const float* Bp = Bm + (long)b*sB + bx*BN;
    const int tid = threadIdx.x;
    const int atRow = tid>>5, atCol = (tid&31)<<2;
    const int tr = tid>>4, tc = tid&15;

    float acc[8][8];
    #pragma unroll
    for (int i=0;i<8;i++)
        #pragma unroll
        for (int j=0;j<8;j++) acc[i][j]=0.f;

    for (int k0=kbeg; k0<kend; k0+=BK){
        *(float4*)&As[atRow  ][atCol] = *(const float4*)(Ab + (long)(k0+atRow  )*M + atCol);
        *(float4*)&As[atRow+8][atCol] = *(const float4*)(Ab + (long)(k0+atRow+8)*M + atCol);
        *(float4*)&Bs[atRow  ][atCol] = *(const float4*)(Bp + (long)(k0+atRow  )*N + atCol);
        *(float4*)&Bs[atRow+8][atCol] = *(const float4*)(Bp + (long)(k0+atRow+8)*N + atCol);
        __syncthreads();
        #pragma unroll
        for (int kk=0; kk<BK; kk++){
            float4 ra0 = *(const float4*)&As[kk][tr*8];
            float4 ra1 = *(const float4*)&As[kk][tr*8+4];
            float4 rb0 = *(const float4*)&Bs[kk][tc*8];
            float4 rb1 = *(const float4*)&Bs[kk][tc*8+4];
            float ra[8]={ra0.x,ra0.y,ra0.z,ra0.w,ra1.x,ra1.y,ra1.z,ra1.w};
            float rb[8]={rb0.x,rb0.y,rb0.z,rb0.w,rb1.x,rb1.y,rb1.z,rb1.w};
            #pragma unroll
            for (int i=0;i<8;i++)
                #pragma unroll
                for (int j=0;j<8;j++)
                    acc[i][j] = fmaf(ra[i], rb[j], acc[i][j]);
        }
        __syncthreads();
    }

    float* Cb = Cpart + (long)bz*M*N;
    const int col0 = bx*BN + tc*8;
    #pragma unroll
    for (int i=0;i<8;i++){
        const int row = tr*8 + i;
        float4* dst = (float4*)(Cb + (long)row*N + col0);
        dst[0] = make_float4(acc[i][0],acc[i][1],acc[i][2],acc[i][3]);
        dst[1] = make_float4(acc[i][4],acc[i][5],acc[i][6],acc[i][7]);
    }
}

__global__ void reduce_splitk(const float* __restrict__ part, float* __restrict__ out,
                              int MN, int splits)
{
    long i = (long)blockIdx.x*blockDim.x + threadIdx.x;
    int b = (int)(i / MN); int r = (int)(i % MN);
    const float* p = part + ((long)b*splits)*MN + r;
    float s = 0.f;
    for (int j=0;j<splits;j++) s += p[(long)j*MN];
    out[i] = s;
}

// column sums over rows (fixed-order, split into chunks for parallelism)
__global__ void colsum_part(const float* __restrict__ in, float* __restrict__ part,
                            int rpc, int cols, long bstride)
{
    int b = blockIdx.y, ch = blockIdx.x, c = threadIdx.x;
    const float* p = in + (long)b*bstride + (long)ch*rpc*cols + c;
    float s = 0.f;
    #pragma unroll 4
    for (int r=0;r<rpc;r++) s += p[(long)r*cols];
    part[((long)b*gridDim.x + ch)*cols + c] = s;
}

__global__ void colsum_fin(const float* __restrict__ part, float* __restrict__ out,
                           int cols, int chunks, float scale)
{
    int b = blockIdx.x, c = threadIdx.x;
    float s = 0.f;
    for (int ch=0;ch<chunks;ch++) s += part[((long)b*chunks+ch)*cols + c];
    out[(long)b*cols + c] = s*scale;
}

// z[b,s] = dot(pq[b,s,:], ksum[b,:]) — warp per row
__global__ void z_kernel(const float* __restrict__ pq, const float* __restrict__ ksum,
                         float* __restrict__ z)
{
    int gw = (int)((blockIdx.x*(long)blockDim.x + threadIdx.x) >> 5);
    int lane = threadIdx.x & 31;
    if (gw >= BS) return;
    int b = gw >> 12;   // / 4096
    const float* pr = pq + (long)gw*Pp;
    const float* kr = ksum + b*Pp;
    float s = 0.f;
    #pragma unroll
    for (int p=lane; p<Pp; p+=32) s = fmaf(pr[p], kr[p], s);
    #pragma unroll
    for (int o=16;o;o>>=1) s += __shfl_xor_sync(0xffffffffu, s, o);
    if (!lane) z[gw] = s;
}

__global__ void ln_kernel(const float* __restrict__ in, const float* __restrict__ g,
                          const float* __restrict__ bta, float* __restrict__ out)
{
    long row = blockIdx.x;
    const float* p = in + row*Dd;
    int t = threadIdx.x;                       // 256 threads, 2 elems each
    float2 v = *(const float2*)(p + 2*t);
    float s  = v.x + v.y;
    float sq = v.x*v.x + v.y*v.y;
    #pragma unroll
    for (int o=16;o;o>>=1){
        s  += __shfl_xor_sync(0xffffffffu, s,  o);
        sq += __shfl_xor_sync(0xffffffffu, sq, o);
    }
    __shared__ float sh[8], shq[8];
    int w = t>>5, lane = t&31;
    if (!lane){ sh[w]=s; shq[w]=sq; }
    __syncthreads();
    float ts=0.f, tq=0.f;
    #pragma unroll
    for (int i=0;i<8;i++){ ts+=sh[i]; tq+=shq[i]; }
    float mu  = ts * (1.f/Dd);
    float var = tq * (1.f/Dd) - mu*mu;
    float r = rsqrtf(var + 1e-5f);
    float2 o;
    o.x = (v.x-mu)*r*g[2*t]   + bta[2*t];
    o.y = (v.y-mu)*r*g[2*t+1] + bta[2*t+1];
    *(float2*)(out + row*Dd + 2*t) = o;
}

__global__ void embed_kernel(const int* __restrict__ x, const float4* __restrict__ emb,
                             const float4* __restrict__ pos, float4* __restrict__ h)
{
    int token = blockIdx.x;
    int s = token & (Ss-1);
    int id = x[token];
    int t = threadIdx.x;                       // 128 threads * float4 = 512
    float4 e = emb[(long)id*(Dd/4) + t];
    float4 p = pos[(long)s *(Dd/4) + t];
    h[(long)token*(Dd/4) + t] = make_float4(e.x+p.x, e.y+p.y, e.z+p.z, e.w+p.w);
}

__global__ void head1_kernel(const float* __restrict__ pool, const float* __restrict__ Wh1,
                             const float* __restrict__ bh1, float* __restrict__ h1)
{
    int b = blockIdx.x;
    __shared__ float xr[Dd];
    for (int i=threadIdx.x; i<Dd; i+=blockDim.x) xr[i] = pool[(long)b*Dd + i];
    __syncthreads();
    int t = threadIdx.x;                       // DHh threads
    float s = bh1[t];
    #pragma unroll 4
    for (int k=0;k<Dd;k++) s = fmaf(xr[k], Wh1[(long)k*DHh + t], s);
    h1[(long)b*DHh + t] = fmaxf(s, 0.f);
}

__global__ void head2_kernel(const float* __restrict__ h1, const float* __restrict__ Wh2,
                             const float* __restrict__ bh2, float* __restrict__ out)
{
    int t = threadIdx.x;
    if (t < Bb*CC){
        int b = t / CC, c = t % CC;
        float s = bh2[c];
        #pragma unroll 4
        for (int k=0;k<DHh;k++) s = fmaf(h1[(long)b*DHh + k], Wh2[(long)k*CC + c], s);
        out[t] = s;
    }
}

// ---------------- launch ----------------
extern "C" void kernel_launch(void* const* d_in, const int* in_sizes, int n_in,
                              void* d_out, int out_size)
{
    const int*   x    = (const int*)  d_in[0];
    const float* emb  = (const float*)d_in[1];
    const float* pos  = (const float*)d_in[2];
    const float* Wq   = (const float*)d_in[3];
    const float* bq   = (const float*)d_in[4];
    const float* Wk   = (const float*)d_in[5];
    const float* bk   = (const float*)d_in[6];
    const float* Wv   = (const float*)d_in[7];
    const float* bv   = (const float*)d_in[8];
    const float* Wf   = (const float*)d_in[9];
    const float* bf   = (const float*)d_in[10];
    const float* Wo   = (const float*)d_in[11];
    const float* bo   = (const float*)d_in[12];
    const float* lng  = (const float*)d_in[13];
    const float* lnb  = (const float*)d_in[14];
    const float* W1   = (const float*)d_in[15];
    const float* b1   = (const float*)d_in[16];
    const float* W2   = (const float*)d_in[17];
    const float* b2   = (const float*)d_in[18];
    const float* Wh1  = (const float*)d_in[19];
    const float* bh1  = (const float*)d_in[20];
    const float* Wh2  = (const float*)d_in[21];
    const float* bh2  = (const float*)d_in[22];

    float *h,*q,*k,*v,*t,*pq,*pk,*kvp,*kv,*ksp,*ks,*z,*m,*pp,*pool,*h1;
    cudaGetSymbolAddress((void**)&h,  g_h);
    cudaGetSymbolAddress((void**)&q,  g_q);
    cudaGetSymbolAddress((void**)&k,  g_k);
    cudaGetSymbolAddress((void**)&v,  g_v);
    cudaGetSymbolAddress((void**)&t,  g_t);
    cudaGetSymbolAddress((void**)&pq, g_pq);
    cudaGetSymbolAddress((void**)&pk, g_pk);
    cudaGetSymbolAddress((void**)&kvp,g_kvp);
    cudaGetSymbolAddress((void**)&kv, g_kv);
    cudaGetSymbolAddress((void**)&ksp,g_ksp);
    cudaGetSymbolAddress((void**)&ks, g_ks);
    cudaGetSymbolAddress((void**)&z,  g_z);
    cudaGetSymbolAddress((void**)&m,  g_m);
    cudaGetSymbolAddress((void**)&pp, g_pp);
    cudaGetSymbolAddress((void**)&pool,g_pool);
    cudaGetSymbolAddress((void**)&h1, g_h1);

    embed_kernel<<<BS,128>>>(x, (const float4*)emb, (const float4*)pos, (float4*)h);

    const dim3 gDD(Dd/BN,  BS/BM, 1);     // M=32768, N=512
    const dim3 gDP(Pp/BN,  BS/BM, 1);     // M=32768, N=128
    const dim3 gDF(DFf/BN, BS/BM, 1);     // M=32768, N=2048

    for (int l=0; l<Ll; l++){
        const float* Wq_l = Wq + (long)l*Dd*Dd;  const float* bq_l = bq + l*Dd;
        const float* Wk_l = Wk + (long)l*Dd*Dd;  const float* bk_l = bk + l*Dd;
        const float* Wv_l = Wv + (long)l*Dd*Dd;  const float* bv_l = bv + l*Dd;
        const float* Wf_l = Wf + (long)l*Dd*Pp;  const float* bf_l = bf + l*Pp;
        const float* Wo_l = Wo + (long)l*Dd*Dd;  const float* bo_l = bo + l*Dd;
        const float* g_l  = lng + l*Dd;          const float* bL_l = lnb + l*Dd;
        const float* W1_l = W1 + (long)l*Dd*DFf; const float* b1_l = b1 + l*DFf;
        const float* W2_l = W2 + (long)l*DFf*Dd; const float* b2_l = b2 + l*Dd;

        // q,k,v = h@W + b
        sgemm_nn<0><<<gDD,256>>>(h, Wq_l, bq_l, nullptr, q, BS, Dd, Dd, 0,0,0);
        sgemm_nn<0><<<gDD,256>>>(h, Wk_l, bk_l, nullptr, k, BS, Dd, Dd, 0,0,0);
        sgemm_nn<0><<<gDD,256>>>(h, Wv_l, bv_l, nullptr, v, BS, Dd, Dd, 0,0,0);
        // pq,pk = elu(.@Wf+bf)+1
        sgemm_nn<1><<<gDP,256>>>(q, Wf_l, bf_l, nullptr, pq, BS, Pp, Dd, 0,0,0);
        sgemm_nn<1><<<gDP,256>>>(k, Wf_l, bf_l, nullptr, pk, BS, Pp, Dd, 0,0,0);
        // ksum[b,p] = sum_s pk
        colsum_part<<<dim3(32,Bb),Pp>>>(pk, ksp, Ss/32, Pp, (long)Ss*Pp);
        colsum_fin <<<Bb,Pp>>>(ksp, ks, Pp, 32, 1.f);
        // kv[b] = pk[b]^T @ v[b]  (split-K, deterministic reduce)
        sgemm_tn_splitk<<<dim3(Dd/BN,1,Bb*KV_SPLIT),256>>>(pk, v, kvp, Pp, Dd, Ss,
                                                           (long)Ss*Pp, (long)Ss*Dd, KV_SPLIT);
        reduce_splitk<<<(Bb*Pp*Dd)/256,256>>>(kvp, kv, Pp*Dd, KV_SPLIT);
        // z[b,s] = pq . ksum
        z_kernel<<<BS/8,256>>>(pq, ks, z);
        // t = (pq@kv) / (z+eps)   (batched, scale fused in epilogue)
        sgemm_nn<3><<<dim3(Dd/BN, Ss/BM, Bb),256>>>(pq, kv, nullptr, z, t,
                                                    Ss, Dd, Pp,
                                                    (long)Ss*Pp, (long)Pp*Dd, (long)Ss*Dd);
        // attn out = t@Wo + bo  -> q (reuse)
        sgemm_nn<0><<<gDD,256>>>(t, Wo_l, bo_l, nullptr, q, BS, Dd, Dd, 0,0,0);
        // a = layernorm -> t
        ln_kernel<<<BS,256>>>(q, g_l, bL_l, t);
        // m = gelu(a@W1+b1)
        sgemm_nn<2><<<gDF,256>>>(t, W1_l, b1_l, nullptr, m, BS, DFf, Dd, 0,0,0);
        // h = m@W2 + b2
        sgemm_nn<0><<<gDD,256>>>(m, W2_l, b2_l, nullptr, h, BS, Dd, DFf, 0,0,0);
    }

    // pooled = mean_s h
    colsum_part<<<dim3(32,Bb),Dd>>>(h, pp, Ss/32, Dd, (long)Ss*Dd);
    colsum_fin <<<Bb,Dd>>>(pp, pool, Dd, 32, 1.0f/Ss);
    // head
    head1_kernel<<<Bb,DHh>>>(pool, Wh1, bh1, h1);
    head2_kernel<<<1,32>>>(h1, Wh2, bh2, (float*)d_out);
}

// round 2
// speedup vs baseline: 1.0001x; 1.0001x over previous
#include <cuda_runtime.h>
#include <math.h>

// Problem constants
#define Bb  8
#define Ss  4096
#define Dd  512
#define Pp  128
#define Ll  4
#define DFf 2048
#define DHh 256
#define CC  2
#define BS  (Bb*Ss)
#define KV_SPLIT 8

// ---------------- scratch (static device globals; no allocs) ----------------
__device__ float g_h [BS*Dd];
__device__ float g_q [BS*Dd];
__device__ float g_k [BS*Dd];
__device__ float g_v [BS*Dd];
__device__ float g_t [BS*Dd];
__device__ float g_pq[BS*Pp];
__device__ float g_pk[BS*Pp];
__device__ float g_kvp[Bb*KV_SPLIT*Pp*Dd];
__device__ float g_kv [Bb*Pp*Dd];
__device__ float g_ksp[Bb*32*Pp];
__device__ float g_ks [Bb*Pp];
__device__ float g_z  [BS];
__device__ float g_m  [(size_t)BS*DFf];
__device__ float g_pp [Bb*32*Dd];
__device__ float g_pool[Bb*Dd];
__device__ float g_h1 [Bb*DHh];

// ---------------- helpers ----------------
__device__ __forceinline__ float gelu_tanh(float x){
    float u = 0.7978845608028654f*(x + 0.044715f*x*x*x);
    return 0.5f*x*(1.0f + tanhf(u));
}

#define BM 128
#define BN 128
#define BK 16

// C[M,N] = A[M,K] @ B[K,N] (+epilogue). Batched via blockIdx.z with strides.
// EPI: 0 = +bias ; 1 = +bias then elu()+1 ; 2 = +bias then gelu(tanh) ;
//      3 = no bias, scale by 1/(aux[row]+1e-6)
template<int EPI>
__global__ void __launch_bounds__(256)
sgemm_nn(const float* __restrict__ A, const float* __restrict__ Bm,
         const float* __restrict__ bias, const float* __restrict__ aux,
         float* __restrict__ Cm, int M, int N, int K,
         long sA, long sB, long sC)
{
    __shared__ float As[BK][BM];
    __shared__ float Bs[BK][BN];
    const int bx = blockIdx.x, by = blockIdx.y, bz = blockIdx.z;
    const float* Ab = A  + (long)bz*sA;
    const float* Bp = Bm + (long)bz*sB + bx*BN;
    float*       Cb = Cm + (long)bz*sC;
    const int tid = threadIdx.x;
    const int aRow = tid>>2, aCol = (tid&3)<<2;
    const int bRow = tid>>5, bCol = (tid&31)<<2;
    const int tr = tid>>4, tc = tid&15;
    const float* Ap = Ab + (long)(by*BM)*K;

    float acc[8][8];
    #pragma unroll
    for (int i=0;i<8;i++)
        #pragma unroll
        for (int j=0;j<8;j++) acc[i][j]=0.f;

    for (int k0=0; k0<K; k0+=BK){
        float4 a0 = *(const float4*)(Ap + (long)aRow*K      + k0 + aCol);
        float4 a1 = *(const float4*)(Ap + (long)(aRow+64)*K + k0 + aCol);
        As[aCol+0][aRow]=a0.x; As[aCol+1][aRow]=a0.y; As[aCol+2][aRow]=a0.z; As[aCol+3][aRow]=a0.w;
        As[aCol+0][aRow+64]=a1.x; As[aCol+1][aRow+64]=a1.y; As[aCol+2][aRow+64]=a1.z; As[aCol+3][aRow+64]=a1.w;
        *(float4*)&Bs[bRow  ][bCol] = *(const float4*)(Bp + (long)(k0+bRow  )*N + bCol);
        *(float4*)&Bs[bRow+8][bCol] = *(const float4*)(Bp + (long)(k0+bRow+8)*N + bCol);
        __syncthreads();
        #pragma unroll
        for (int kk=0; kk<BK; kk++){
            float4 ra0 = *(const float4*)&As[kk][tr*8];
            float4 ra1 = *(const float4*)&As[kk][tr*8+4];
            float4 rb0 = *(const float4*)&Bs[kk][tc*8];
            float4 rb1 = *(const float4*)&Bs[kk][tc*8+4];
            float ra[8]={ra0.x,ra0.y,ra0.z,ra0.w,ra1.x,ra1.y,ra1.z,ra1.w};
            float rb[8]={rb0.x,rb0.y,rb0.z,rb0.w,rb1.x,rb1.y,rb1.z,rb1.w};
            #pragma unroll
            for (int i=0;i<8;i++)
                #pragma unroll
                for (int j=0;j<8;j++)
                    acc[i][j] = fmaf(ra[i], rb[j], acc[i][j]);
        }
        __syncthreads();
    }

    const int col0 = bx*BN + tc*8;
    float bv[8];
    if (EPI != 3){
        #pragma unroll
        for (int j=0;j<8;j++) bv[j] = bias[col0+j];
    }
    const float* auxb = (EPI==3) ? (aux + (long)bz*M) : nullptr;
    #pragma unroll
    for (int i=0;i<8;i++){
        const int row = by*BM + tr*8 + i;
        float sc = 1.f;
        if (EPI==3) sc = 1.f/(auxb[row] + 1e-6f);
        float o[8];
        #pragma unroll
        for (int j=0;j<8;j++){
            float c = acc[i][j];
            if (EPI!=3) c += bv[j];
            if (EPI==1) c = (c>0.f) ? (c+1.f) : expf(c);   // elu(c)+1
            if (EPI==2) c = gelu_tanh(c);
            if (EPI==3) c *= sc;
            o[j]=c;
        }
        float4* dst = (float4*)(Cb + (long)row*N + col0);
        dst[0] = make_float4(o[0],o[1],o[2],o[3]);
        dst[1] = make_float4(o[4],o[5],o[6],o[7]);
    }
}

// Cpart = A^T @ B with split-K. A: [K,M] (lda=M==128), B: [K,N]. grid.z = batch*splits.
__global__ void __launch_bounds__(256)
sgemm_tn_splitk(const float* __restrict__ A, const float* __restrict__ Bm,
                float* __restrict__ Cpart, int M, int N, int K,
                long sA, long sB, int splits)
{
    __shared__ float As[BK][BM];
    __shared__ float Bs[BK][BN];
    const int bx = blockIdx.x, bz = blockIdx.z;
    const int b = bz / splits, sp = bz % splits;
    const int Kc = K / splits, kbeg = sp*Kc, kend = kbeg + Kc;
    const float* Ab = A  + (long)b*sA;
    const float* Bp = Bm + (long)b*sB + bx*BN;
    const int tid = threadIdx.x;
    const int atRow = tid>>5, atCol = (tid&31)<<2;
    const int tr = tid>>4, tc = tid&15;

    float acc[8][8];
    #pragma unroll
    for (int i=0;i<8;i++)
        #pragma unroll
        for (int j=0;j<8;j++) acc[i][j]=0.f;

    for (int k0=kbeg; k0<kend; k0+=BK){
        *(float4*)&As[atRow  ][atCol] = *(const float4*)(Ab + (long)(k0+atRow  )*M + atCol);
        *(float4*)&As[atRow+8][atCol] = *(const float4*)(Ab + (long)(k0+atRow+8)*M + atCol);
        *(float4*)&Bs[atRow  ][atCol] = *(const float4*)(Bp + (long)(k0+atRow  )*N + atCol);
        *(float4*)&Bs[atRow+8][atCol] = *(const float4*)(Bp + (long)(k0+atRow+8)*N + atCol);
        __syncthreads();
        #pragma unroll
        for (int kk=0; kk<BK; kk++){
            float4 ra0 = *(const float4*)&As[kk][tr*8];
            float4 ra1 = *(const float4*)&As[kk][tr*8+4];
            float4 rb0 = *(const float4*)&Bs[kk][tc*8];
            float4 rb1 = *(const float4*)&Bs[kk][tc*8+4];
            float ra[8]={ra0.x,ra0.y,ra0.z,ra0.w,ra1.x,ra1.y,ra1.z,ra1.w};
            float rb[8]={rb0.x,rb0.y,rb0.z,rb0.w,rb1.x,rb1.y,rb1.z,rb1.w};
            #pragma unroll
            for (int i=0;i<8;i++)
                #pragma unroll
                for (int j=0;j<8;j++)
                    acc[i][j] = fmaf(ra[i], rb[j], acc[i][j]);
        }
        __syncthreads();
    }

    float* Cb = Cpart + (long)bz*M*N;
    const int col0 = bx*BN + tc*8;
    #pragma unroll
    for (int i=0;i<8;i++){
        const int row = tr*8 + i;
        float4* dst = (float4*)(Cb + (long)row*N + col0);
        dst[0] = make_float4(acc[i][0],acc[i][1],acc[i][2],acc[i][3]);
        dst[1] = make_float4(acc[i][4],acc[i][5],acc[i][6],acc[i][7]);
    }
}

__global__ void reduce_splitk(const float* __restrict__ part, float* __restrict__ out,
                              int MN, int splits)
{
    long i = (long)blockIdx.x*blockDim.x + threadIdx.x;
    int b = (int)(i / MN); int r = (int)(i % MN);
    const float* p = part + ((long)b*splits)*MN + r;
    float s = 0.f;
    for (int j=0;j<splits;j++) s += p[(long)j*MN];
    out[i] = s;
}

// column sums over rows (fixed-order, split into chunks for parallelism)
__global__ void colsum_part(const float* __restrict__ in, float* __restrict__ part,
                            int rpc, int cols, long bstride)
{
    int b = blockIdx.y, ch = blockIdx.x, c = threadIdx.x;
    const float* p = in + (long)b*bstride + (long)ch*rpc*cols + c;
    float s = 0.f;
    #pragma unroll 4
    for (int r=0;r<rpc;r++) s += p[(long)r*cols];
    part[((long)b*gridDim.x + ch)*cols + c] = s;
}

__global__ void colsum_fin(const float* __restrict__ part, float* __restrict__ out,
                           int cols, int chunks, float scale)
{
    int b = blockIdx.x, c = threadIdx.x;
    float s = 0.f;
    for (int ch=0;ch<chunks;ch++) s += part[((long)b*chunks+ch)*cols + c];
    out[(long)b*cols + c] = s*scale;
}

// z[b,s] = dot(pq[b,s,:], ksum[b,:]) — warp per row
__global__ void z_kernel(const float* __restrict__ pq, const float* __restrict__ ksum,
                         float* __restrict__ z)
{
    int gw = (int)((blockIdx.x*(long)blockDim.x + threadIdx.x) >> 5);
    int lane = threadIdx.x & 31;
    if (gw >= BS) return;
    int b = gw >> 12;   // / 4096
    const float* pr = pq + (long)gw*Pp;
    const float* kr = ksum + b*Pp;
    float s = 0.f;
    #pragma unroll
    for (int p=lane; p<Pp; p+=32) s = fmaf(pr[p], kr[p], s);
    #pragma unroll
    for (int o=16;o;o>>=1) s += __shfl_xor_sync(0xffffffffu, s, o);
    if (!lane) z[gw] = s;
}

__global__ void ln_kernel(const float* __restrict__ in, const float* __restrict__ g,
                          const float* __restrict__ bta, float* __restrict__ out)
{
    long row = blockIdx.x;
    const float* p = in + row*Dd;
    int t = threadIdx.x;                       // 256 threads, 2 elems each
    float2 v = *(const float2*)(p + 2*t);
    float s  = v.x + v.y;
    float sq = v.x*v.x + v.y*v.y;
    #pragma unroll
    for (int o=16;o;o>>=1){
        s  += __shfl_xor_sync(0xffffffffu, s,  o);
        sq += __shfl_xor_sync(0xffffffffu, sq, o);
    }
    __shared__ float sh[8], shq[8];
    int w = t>>5, lane = t&31;
    if (!lane){ sh[w]=s; shq[w]=sq; }
    __syncthreads();
    float ts=0.f, tq=0.f;
    #pragma unroll
    for (int i=0;i<8;i++){ ts+=sh[i]; tq+=shq[i]; }
    float mu  = ts * (1.f/Dd);
    float var = tq * (1.f/Dd) - mu*mu;
    float r = rsqrtf(var + 1e-5f);
    float2 o;
    o.x = (v.x-mu)*r*g[2*t]   + bta[2*t];
    o.y = (v.y-mu)*r*g[2*t+1] + bta[2*t+1];
    *(float2*)(out + row*Dd + 2*t) = o;
}

__global__ void embed_kernel(const int* __restrict__ x, const float4* __restrict__ emb,
                             const float4* __restrict__ pos, float4* __restrict__ h)
{
    int token = blockIdx.x;
    int s = token & (Ss-1);
    int id = x[token];
    int t = threadIdx.x;                       // 128 threads * float4 = 512
    float4 e = emb[(long)id*(Dd/4) + t];
    float4 p = pos[(long)s *(Dd/4) + t];
    h[(long)token*(Dd/4) + t] = make_float4(e.x+p.x, e.y+p.y, e.z+p.z, e.w+p.w);
}

__global__ void head1_kernel(const float* __restrict__ pool, const float* __restrict__ Wh1,
                             const float* __restrict__ bh1, float* __restrict__ h1)
{
    int b = blockIdx.x;
    __shared__ float xr[Dd];
    for (int i=threadIdx.x; i<Dd; i+=blockDim.x) xr[i] = pool[(long)b*Dd + i];
    __syncthreads();
    int t = threadIdx.x;                       // DHh threads
    float s = bh1[t];
    #pragma unroll 4
    for (int k=0;k<Dd;k++) s = fmaf(xr[k], Wh1[(long)k*DHh + t], s);
    h1[(long)b*DHh + t] = fmaxf(s, 0.f);
}

__global__ void head2_kernel(const float* __restrict__ h1, const float* __restrict__ Wh2,
                             const float* __restrict__ bh2, float* __restrict__ out)
{
    int t = threadIdx.x;
    if (t < Bb*CC){
        int b = t / CC, c = t % CC;
        float s = bh2[c];
        #pragma unroll 4
        for (int k=0;k<DHh;k++) s = fmaf(h1[(long)b*DHh + k], Wh2[(long)k*CC + c], s);
        out[t] = s;
    }
}

// ---------------- launch ----------------
extern "C" void kernel_launch(void* const* d_in, const int* in_sizes, int n_in,
                              void* d_out, int out_size)
{
    const int*   x    = (const int*)  d_in[0];
    const float* emb  = (const float*)d_in[1];
    const float* pos  = (const float*)d_in[2];
    const float* Wq   = (const float*)d_in[3];
    const float* bq   = (const float*)d_in[4];
    const float* Wk   = (const float*)d_in[5];
    const float* bk   = (const float*)d_in[6];
    const float* Wv   = (const float*)d_in[7];
    const float* bv   = (const float*)d_in[8];
    const float* Wf   = (const float*)d_in[9];
    const float* bf   = (const float*)d_in[10];
    const float* Wo   = (const float*)d_in[11];
    const float* bo   = (const float*)d_in[12];
    const float* lng  = (const float*)d_in[13];
    const float* lnb  = (const float*)d_in[14];
    const float* W1   = (const float*)d_in[15];
    const float* b1   = (const float*)d_in[16];
    const float* W2   = (const float*)d_in[17];
    const float* b2   = (const float*)d_in[18];
    const float* Wh1  = (const float*)d_in[19];
    const float* bh1  = (const float*)d_in[20];
    const float* Wh2  = (const float*)d_in[21];
    const float* bh2  = (const float*)d_in[22];

    float *h,*q,*k,*v,*t,*pq,*pk,*kvp,*kv,*ksp,*ks,*z,*m,*pp,*pool,*h1;
    cudaGetSymbolAddress((void**)&h,  g_h);
    cudaGetSymbolAddress((void**)&q,  g_q);
    cudaGetSymbolAddress((void**)&k,  g_k);
    cudaGetSymbolAddress((void**)&v,  g_v);
    cudaGetSymbolAddress((void**)&t,  g_t);
    cudaGetSymbolAddress((void**)&pq, g_pq);
    cudaGetSymbolAddress((void**)&pk, g_pk);
    cudaGetSymbolAddress((void**)&kvp,g_kvp);
    cudaGetSymbolAddress((void**)&kv, g_kv);
    cudaGetSymbolAddress((void**)&ksp,g_ksp);
    cudaGetSymbolAddress((void**)&ks, g_ks);
    cudaGetSymbolAddress((void**)&z,  g_z);
    cudaGetSymbolAddress((void**)&m,  g_m);
    cudaGetSymbolAddress((void**)&pp, g_pp);
    cudaGetSymbolAddress((void**)&pool,g_pool);
    cudaGetSymbolAddress((void**)&h1, g_h1);

    embed_kernel<<<BS,128>>>(x, (const float4*)emb, (const float4*)pos, (float4*)h);

    const dim3 gDD(Dd/BN,  BS/BM, 1);     // M=32768, N=512
    const dim3 gDP(Pp/BN,  BS/BM, 1);     // M=32768, N=128
    const dim3 gDF(DFf/BN, BS/BM, 1);     // M=32768, N=2048

    for (int l=0; l<Ll; l++){
        const float* Wq_l = Wq + (long)l*Dd*Dd;  const float* bq_l = bq + l*Dd;
        const float* Wk_l = Wk + (long)l*Dd*Dd;  const float* bk_l = bk + l*Dd;
        const float* Wv_l = Wv + (long)l*Dd*Dd;  const float* bv_l = bv + l*Dd;
        const float* Wf_l = Wf + (long)l*Dd*Pp;  const float* bf_l = bf + l*Pp;
        const float* Wo_l = Wo + (long)l*Dd*Dd;  const float* bo_l = bo + l*Dd;
        const float* g_l  = lng + l*Dd;          const float* bL_l = lnb + l*Dd;
        const float* W1_l = W1 + (long)l*Dd*DFf; const float* b1_l = b1 + l*DFf;
        const float* W2_l = W2 + (long)l*DFf*Dd; const float* b2_l = b2 + l*Dd;

        // q,k,v = h@W + b
        sgemm_nn<0><<<gDD,256>>>(h, Wq_l, bq_l, nullptr, q, BS, Dd, Dd, 0,0,0);
        sgemm_nn<0><<<gDD,256>>>(h, Wk_l, bk_l, nullptr, k, BS, Dd, Dd, 0,0,0);
        sgemm_nn<0><<<gDD,256>>>(h, Wv_l, bv_l, nullptr, v, BS, Dd, Dd, 0,0,0);
        // pq,pk = elu(.@Wf+bf)+1
        sgemm_nn<1><<<gDP,256>>>(q, Wf_l, bf_l, nullptr, pq, BS, Pp, Dd, 0,0,0);
        sgemm_nn<1><<<gDP,256>>>(k, Wf_l, bf_l, nullptr, pk, BS, Pp, Dd, 0,0,0);
        // ksum[b,p] = sum_s pk
        colsum_part<<<dim3(32,Bb),Pp>>>(pk, ksp, Ss/32, Pp, (long)Ss*Pp);
        colsum_fin <<<Bb,Pp>>>(ksp, ks, Pp, 32, 1.f);
        // kv[b] = pk[b]^T @ v[b]  (split-K, deterministic reduce)
        sgemm_tn_splitk<<<dim3(Dd/BN,1,Bb*KV_SPLIT),256>>>(pk, v, kvp, Pp, Dd, Ss,
                                                           (long)Ss*Pp, (long)Ss*Dd, KV_SPLIT);
        reduce_splitk<<<(Bb*Pp*Dd)/256,256>>>(kvp, kv, Pp*Dd, KV_SPLIT);
        // z[b,s] = pq . ksum
        z_kernel<<<BS/8,256>>>(pq, ks, z);
        // t = (pq@kv) / (z+eps)   (batched, scale fused in epilogue)
        sgemm_nn<3><<<dim3(Dd/BN, Ss/BM, Bb),256>>>(pq, kv, nullptr, z, t,
                                                    Ss, Dd, Pp,
                                                    (long)Ss*Pp, (long)Pp*Dd, (long)Ss*Dd);
        // attn out = t@Wo + bo  -> q (reuse)
        sgemm_nn<0><<<gDD,256>>>(t, Wo_l, bo_l, nullptr, q, BS, Dd, Dd, 0,0,0);
        // a = layernorm -> t
        ln_kernel<<<BS,256>>>(q, g_l, bL_l, t);
        // m = gelu(a@W1+b1)
        sgemm_nn<2><<<gDF,256>>>(t, W1_l, b1_l, nullptr, m, BS, DFf, Dd, 0,0,0);
        // h = m@W2 + b2
        sgemm_nn<0><<<gDD,256>>>(m, W2_l, b2_l, nullptr, h, BS, Dd, DFf, 0,0,0);
    }

    // pooled = mean_s h
    colsum_part<<<dim3(32,Bb),Dd>>>(h, pp, Ss/32, Dd, (long)Ss*Dd);
    colsum_fin <<<Bb,Dd>>>(pp, pool, Dd, 32, 1.0f/Ss);
    // head
    head1_kernel<<<Bb,DHh>>>(pool, Wh1, bh1, h1);
    head2_kernel<<<1,32>>>(h1, Wh2, bh2, (float*)d_out);
}

// round 4
// speedup vs baseline: 1.5474x; 1.5472x over previous
#include <cuda_runtime.h>
#include <cuda_bf16.h>
#include <math.h>
#include <stdint.h>

#define Bb  8
#define Ss  4096
#define Dd  512
#define Pp  128
#define Ll  4
#define DFf 2048
#define DHh 256
#define CC  2
#define BS  (Bb*Ss)
#define KV_SPLIT 16

// ===================== PTX helpers (plain sm_80-level ISA only) =====================
__device__ __forceinline__ uint32_t smem_to_u32(const void* p) {
    uint32_t a;
    asm("{ .reg .u64 t; cvta.to.shared.u64 t, %1; cvt.u32.u64 %0, t; }" : "=r"(a) : "l"(p));
    return a;
}
#define CP_ASYNC16(s, g) \
    asm volatile("cp.async.cg.shared.global [%0], [%1], 16;" :: "r"(s), "l"(g) : "memory")
#define CP_COMMIT() asm volatile("cp.async.commit_group;" ::: "memory")
#define CP_WAIT2()  asm volatile("cp.async.wait_group 2;" ::: "memory")

__device__ __forceinline__ void ldsm4(uint32_t* r, uint32_t addr){
    asm volatile("ldmatrix.sync.aligned.m8n8.x4.shared.b16 {%0,%1,%2,%3}, [%4];"
        : "=r"(r[0]),"=r"(r[1]),"=r"(r[2]),"=r"(r[3]) : "r"(addr));
}
__device__ __forceinline__ void mma_bf16(float* d, const uint32_t* a, const uint32_t* b){
    asm volatile("mma.sync.aligned.m16n8k16.row.col.f32.bf16.bf16.f32 "
        "{%0,%1,%2,%3}, {%4,%5,%6,%7}, {%8,%9}, {%0,%1,%2,%3};"
        : "+f"(d[0]),"+f"(d[1]),"+f"(d[2]),"+f"(d[3])
        : "r"(a[0]),"r"(a[1]),"r"(a[2]),"r"(a[3]), "r"(b[0]),"r"(b[1]));
}

// ===================== device globals =====================
#define PL_D  ((long)BS*Dd)
#define PL_P  ((long)BS*Pp)
#define PL_F  ((long)BS*DFf)
__device__ __align__(256) __nv_bfloat16 g_hS [2*(size_t)BS*Dd];
__device__ __align__(256) __nv_bfloat16 g_qS [2*(size_t)BS*Dd];
__device__ __align__(256) __nv_bfloat16 g_kS [2*(size_t)BS*Dd];
__device__ __align__(256) __nv_bfloat16 g_vS [2*(size_t)BS*Dd];
__device__ __align__(256) __nv_bfloat16 g_tS [2*(size_t)BS*Dd];
__device__ __align__(256) __nv_bfloat16 g_pqS[2*(size_t)BS*Pp];
__device__ __align__(256) __nv_bfloat16 g_pkS[2*(size_t)BS*Pp];
__device__ __align__(256) __nv_bfloat16 g_mS [2*(size_t)BS*DFf];
__device__ __align__(256) __nv_bfloat16 g_kvtS[(size_t)Bb*2*Dd*Pp];
__device__ __align__(256) __nv_bfloat16 g_wq[(size_t)Ll*2*Dd*Dd];
__device__ __align__(256) __nv_bfloat16 g_wk[(size_t)Ll*2*Dd*Dd];
__device__ __align__(256) __nv_bfloat16 g_wv[(size_t)Ll*2*Dd*Dd];
__device__ __align__(256) __nv_bfloat16 g_wo[(size_t)Ll*2*Dd*Dd];
__device__ __align__(256) __nv_bfloat16 g_wf[(size_t)Ll*2*Pp*Dd];
__device__ __align__(256) __nv_bfloat16 g_w1[(size_t)Ll*2*DFf*Dd];
__device__ __align__(256) __nv_bfloat16 g_w2[(size_t)Ll*2*Dd*DFf];
__device__ float g_kvp[(size_t)Bb*KV_SPLIT*Pp*Dd];
__device__ float g_ksp[Bb*32*Pp];
__device__ float g_ks [Bb*Pp];
__device__ float g_z  [BS];
__device__ float g_pp [Bb*32*Dd];
__device__ float g_pool[Bb*Dd];
__device__ float g_h1 [Bb*DHh];

__device__ __forceinline__ float gelu_tanh(float x){
    float u = 0.7978845608028654f*(x + 0.044715f*x*x*x);
    return 0.5f*x*(1.0f + tanhf(u));
}
__device__ __forceinline__ float4 ld4_split(const __nv_bfloat16* hi, long plane, long idx){
    const __nv_bfloat162 h0 = *(const __nv_bfloat162*)(hi + idx);
    const __nv_bfloat162 h1 = *(const __nv_bfloat162*)(hi + idx + 2);
    const __nv_bfloat162 l0 = *(const __nv_bfloat162*)(hi + plane + idx);
    const __nv_bfloat162 l1 = *(const __nv_bfloat162*)(hi + plane + idx + 2);
    float4 r;
    r.x = __bfloat162float(h0.x) + __bfloat162float(l0.x);
    r.y = __bfloat162float(h0.y) + __bfloat162float(l0.y);
    r.z = __bfloat162float(h1.x) + __bfloat162float(l1.x);
    r.w = __bfloat162float(h1.y) + __bfloat162float(l1.y);
    return r;
}

// ===================== split-bf16 HMMA GEMM (mma.sync m16n8k16) =====================
// C[M,N] = act(A @ B^T).  A split [2][M,K] K-major, B split [2][N,K] K-major.
// Virtual K = 3K: seg 0 = Ah*Bh, seg 1 = Al*Bh, seg 2 = Ah*Bl.
// 128x128 tile, BK=32, 4-stage cp.async, 256 threads (8 warps = 4m x 2n, warp tile 32x64).
#define NSTG 4
#define STGB 16384          // A 8KB + B 8KB per stage
#define SMEMG (NSTG*STGB)   // 64KB

template<int EPI>  // 0:+bias  1:+bias,elu+1  2:+bias,gelu  3:*1/(aux[row]+1e-6)
__global__ void __launch_bounds__(256)
gemm_mma(const __nv_bfloat16* __restrict__ A, long a_plane,
         const __nv_bfloat16* __restrict__ Bw, long b_plane, long b_batch,
         const float* __restrict__ bias, const float* __restrict__ aux,
         __nv_bfloat16* __restrict__ C, long c_plane, int N, int K)
{
    extern __shared__ __align__(1024) char smem[];
    const uint32_t sb = smem_to_u32(smem);
    const int tid = threadIdx.x, wid = tid >> 5, lane = tid & 31;
    const int row0 = (blockIdx.z*gridDim.y + blockIdx.y)*128;
    const int col0 = blockIdx.x*128;
    const int kc32 = K >> 5;
    const int NC   = 3*kc32;
    const __nv_bfloat16* Bt = Bw + (long)blockIdx.z*b_batch;

    // producer lambda-ish: load chunk i into stage s
    auto load_chunk = [&](int i, int s){
        if (i < NC){
            const int seg = i / kc32;
            const int koff = (i - seg*kc32) << 5;
            const __nv_bfloat16* Ap = A  + (seg==1 ? a_plane : 0) + (long)row0*K + koff;
            const __nv_bfloat16* Bp = Bt + (seg==2 ? b_plane : 0) + (long)col0*K + koff;
            const uint32_t sA = sb + s*STGB, sB = sA + 8192;
            #pragma unroll
            for (int rep = 0; rep < 2; ++rep){
                const int t = tid + rep*256;
                const int r = t & 127, kc = t >> 7;
                const uint32_t d = (uint32_t)((kc*128 + r)*16);
                CP_ASYNC16(sA + d, Ap + (long)r*K + kc*8);
                CP_ASYNC16(sB + d, Bp + (long)r*K + kc*8);
            }
        }
        CP_COMMIT();
    };

    float acc[2][8][4];
    #pragma unroll
    for (int mt=0;mt<2;mt++)
        #pragma unroll
        for (int ni=0;ni<8;ni++)
            #pragma unroll
            for (int r=0;r<4;r++) acc[mt][ni][r]=0.f;

    // ldmatrix lane addressing (within tile)
    const int wm = (wid >> 1)*32, wn = (wid & 1)*64;
    const int a_mrow = wm + ((lane>>3)&1)*8 + (lane&7);    // + mt*16
    const int a_kc   = (lane>>4);                          // + 2*step
    const int b_nrow = wn + ((lane>>4)&1)*8 + (lane&7);    // + nt4*16
    const int b_kc   = ((lane>>3)&1);                      // + 2*step

    // prologue
    #pragma unroll
    for (int s = 0; s < NSTG-1; ++s) load_chunk(s, s);

    for (int i = 0; i < NC; ++i){
        CP_WAIT2();
        __syncthreads();
        load_chunk(i + NSTG-1, (i + NSTG-1) & (NSTG-1));
        const uint32_t sA = sb + (i & (NSTG-1))*STGB, sB = sA + 8192;
        #pragma unroll
        for (int step = 0; step < 2; ++step){
            uint32_t af[2][4];
            #pragma unroll
            for (int mt = 0; mt < 2; ++mt)
                ldsm4(af[mt], sA + (uint32_t)((((a_kc + 2*step)*128) + a_mrow + mt*16)*16));
            uint32_t bf[8][2];
            #pragma unroll
            for (int nt4 = 0; nt4 < 4; ++nt4){
                uint32_t r4[4];
                ldsm4(r4, sB + (uint32_t)((((b_kc + 2*step)*128) + b_nrow + nt4*16)*16));
                bf[2*nt4][0]=r4[0]; bf[2*nt4][1]=r4[1];
                bf[2*nt4+1][0]=r4[2]; bf[2*nt4+1][1]=r4[3];
            }
            #pragma unroll
            for (int mt = 0; mt < 2; ++mt)
                #pragma unroll
                for (int ni = 0; ni < 8; ++ni)
                    mma_bf16(acc[mt][ni], af[mt], bf[ni]);
        }
    }

    // ---- epilogue ----
    float bv0[8], bv1[8];
    if (EPI != 3){
        #pragma unroll
        for (int ni = 0; ni < 8; ++ni){
            const int col = col0 + wn + ni*8 + (lane&3)*2;
            bv0[ni] = bias[col]; bv1[ni] = bias[col+1];
        }
    }
    #pragma unroll
    for (int mt = 0; mt < 2; ++mt){
        #pragma unroll
        for (int h = 0; h < 2; ++h){
            const long row = row0 + wm + mt*16 + h*8 + (lane>>2);
            float sc = 1.f;
            if (EPI == 3) sc = 1.f/(aux[row] + 1e-6f);
            #pragma unroll
            for (int ni = 0; ni < 8; ++ni){
                const int col = col0 + wn + ni*8 + (lane&3)*2;
                float c0 = acc[mt][ni][2*h], c1 = acc[mt][ni][2*h+1];
                if (EPI != 3){ c0 += bv0[ni]; c1 += bv1[ni]; }
                if (EPI == 1){ c0 = (c0>0.f)?(c0+1.f):expf(c0); c1 = (c1>0.f)?(c1+1.f):expf(c1); }
                if (EPI == 2){ c0 = gelu_tanh(c0); c1 = gelu_tanh(c1); }
                if (EPI == 3){ c0 *= sc; c1 *= sc; }
                __nv_bfloat16 h0 = __float2bfloat16(c0), h1 = __float2bfloat16(c1);
                __nv_bfloat162 vh; vh.x = h0; vh.y = h1;
                __nv_bfloat162 vl;
                vl.x = __float2bfloat16(c0 - __bfloat162float(h0));
                vl.y = __float2bfloat16(c1 - __bfloat162float(h1));
                *(__nv_bfloat162*)(C + row*(long)N + col) = vh;
                *(__nv_bfloat162*)(C + c_plane + row*(long)N + col) = vl;
            }
        }
    }
}

// ===================== weight split+transpose: fp32 [L][K,N] -> bf16 [L][2][N][K] =====================
__global__ void wconv(const float* __restrict__ W, __nv_bfloat16* __restrict__ out, int K, int N)
{
    __shared__ float t[32][33];
    const int n0 = blockIdx.x*32, k0 = blockIdx.y*32, l = blockIdx.z;
    const float* Wl = W + (long)l*K*N;
    __nv_bfloat16* oh = out + (long)l*2*N*K;
    __nv_bfloat16* ol = oh + (long)N*K;
    for (int i = threadIdx.y; i < 32; i += 8)
        t[i][threadIdx.x] = Wl[(long)(k0+i)*N + n0 + threadIdx.x];
    __syncthreads();
    for (int i = threadIdx.y; i < 32; i += 8) {
        float v = t[threadIdx.x][i];
        long o = (long)(n0+i)*K + k0 + threadIdx.x;
        __nv_bfloat16 h = __float2bfloat16(v);
        oh[o] = h; ol[o] = __float2bfloat16(v - __bfloat162float(h));
    }
}

// ===================== kv einsum: kv[b] = pk[b]^T @ v[b]  (fp32 FFMA, split-K) =====================
#define BM 128
#define BN 128
#define BK 16
__global__ void __launch_bounds__(256)
kv_splitk(const __nv_bfloat16* __restrict__ Ah, const __nv_bfloat16* __restrict__ Bh,
          float* __restrict__ Cpart)
{
    __shared__ float As[BK][BM];
    __shared__ float Bs[BK][BN];
    const int bx = blockIdx.x, bz = blockIdx.z;
    const int b = bz / KV_SPLIT, sp = bz % KV_SPLIT;
    const int Kc = Ss / KV_SPLIT, kbeg = sp*Kc, kend = kbeg + Kc;
    const __nv_bfloat16* Ab = Ah + (long)b*Ss*Pp;
    const __nv_bfloat16* Bp = Bh + (long)b*Ss*Dd + bx*BN;
    const int tid = threadIdx.x;
    const int ar = tid>>5, ac = (tid&31)<<2;
    const int tr = tid>>4, tc = tid&15;
    float acc[8][8];
    #pragma unroll
    for (int i=0;i<8;i++){
        #pragma unroll
        for (int j=0;j<8;j++) acc[i][j]=0.f; }
    for (int k0=kbeg; k0<kend; k0+=BK){
        *(float4*)&As[ar  ][ac] = ld4_split(Ab, PL_P, (long)(k0+ar  )*Pp + ac);
        *(float4*)&As[ar+8][ac] = ld4_split(Ab, PL_P, (long)(k0+ar+8)*Pp + ac);
        *(float4*)&Bs[ar  ][ac] = ld4_split(Bp, PL_D, (long)(k0+ar  )*Dd + ac);
        *(float4*)&Bs[ar+8][ac] = ld4_split(Bp, PL_D, (long)(k0+ar+8)*Dd + ac);
        __syncthreads();
        #pragma unroll
        for (int kk=0; kk<BK; kk++){
            float4 a0 = *(const float4*)&As[kk][tr*8];
            float4 a1 = *(const float4*)&As[kk][tr*8+4];
            float4 b0 = *(const float4*)&Bs[kk][tc*8];
            float4 b1 = *(const float4*)&Bs[kk][tc*8+4];
            float ra[8]={a0.x,a0.y,a0.z,a0.w,a1.x,a1.y,a1.z,a1.w};
            float rb[8]={b0.x,b0.y,b0.z,b0.w,b1.x,b1.y,b1.z,b1.w};
            #pragma unroll
            for (int i=0;i<8;i++){
                #pragma unroll
                for (int j=0;j<8;j++) acc[i][j] = fmaf(ra[i], rb[j], acc[i][j]); }
        }
        __syncthreads();
    }
    float* Cb = Cpart + (long)bz*Pp*Dd;
    const int c0 = bx*BN + tc*8;
    #pragma unroll
    for (int i=0;i<8;i++){
        float4* d = (float4*)(Cb + (long)(tr*8+i)*Dd + c0);
        d[0] = make_float4(acc[i][0],acc[i][1],acc[i][2],acc[i][3]);
        d[1] = make_float4(acc[i][4],acc[i][5],acc[i][6],acc[i][7]);
    }
}

// reduce partials and write kv^T split-bf16: [b][2][Dd][Pp]
__global__ void reduce_kvt(const float* __restrict__ part, __nv_bfloat16* __restrict__ kvt)
{
    long i = (long)blockIdx.x*256 + threadIdx.x;
    int b = (int)(i / (Pp*Dd)); int r = (int)(i % (Pp*Dd));
    int p = r / Dd, d = r % Dd;
    const float* q = part + ((long)b*KV_SPLIT)*Pp*Dd + r;
    float s = 0.f;
    #pragma unroll
    for (int j=0;j<KV_SPLIT;j++) s += q[(long)j*Pp*Dd];
    __nv_bfloat16 h = __float2bfloat16(s);
    long o = (long)b*2*Dd*Pp + (long)d*Pp + p;
    kvt[o] = h; kvt[o + (long)Dd*Pp] = __float2bfloat16(s - __bfloat162float(h));
}

// column sums over split-bf16 input (fixed order, chunked)
__global__ void colsum_part(const __nv_bfloat16* __restrict__ in, long plane,
                            float* __restrict__ part, int rpc, int cols, long bstride)
{
    int b = blockIdx.y, ch = blockIdx.x, c = threadIdx.x;
    long base = (long)b*bstride + (long)ch*rpc*cols + c;
    float s = 0.f;
    #pragma unroll 4
    for (int r=0;r<rpc;r++){
        long idx = base + (long)r*cols;
        s += __bfloat162float(in[idx]) + __bfloat162float(in[plane+idx]);
    }
    part[((long)b*gridDim.x + ch)*cols + c] = s;
}
__global__ void colsum_fin(const float* __restrict__ part, float* __restrict__ out,
                           int cols, int chunks, float scale)
{
    int b = blockIdx.x, c = threadIdx.x;
    float s = 0.f;
    for (int ch=0;ch<chunks;ch++) s += part[((long)b*chunks+ch)*cols + c];
    out[(long)b*cols + c] = s*scale;
}

// z[b,s] = dot(pq_split[b,s,:], ksum[b,:])
__global__ void z_kernel(const __nv_bfloat16* __restrict__ pq, const float* __restrict__ ksum,
                         float* __restrict__ z)
{
    int gw = (int)((blockIdx.x*(long)blockDim.x + threadIdx.x) >> 5);
    int lane = threadIdx.x & 31;
    if (gw >= BS) return;
    int b = gw >> 12;
    const __nv_bfloat16* pr = pq + (long)gw*Pp;
    const float* kr = ksum + b*Pp;
    float s = 0.f;
    #pragma unroll
    for (int p=lane; p<Pp; p+=32)
        s = fmaf(__bfloat162float(pr[p]) + __bfloat162float(pr[PL_P+p]), kr[p], s);
    #pragma unroll
    for (int o=16;o;o>>=1) s += __shfl_xor_sync(0xffffffffu, s, o);
    if (!lane) z[gw] = s;
}

// layernorm: split in, split out
__global__ void ln_kernel(const __nv_bfloat16* __restrict__ in, const float* __restrict__ g,
                          const float* __restrict__ bta, __nv_bfloat16* __restrict__ out)
{
    long row = blockIdx.x;
    int t = threadIdx.x;
    long idx = row*Dd + 2*t;
    __nv_bfloat162 h2 = *(const __nv_bfloat162*)(in + idx);
    __nv_bfloat162 l2 = *(const __nv_bfloat162*)(in + PL_D + idx);
    float vx = __bfloat162float(h2.x) + __bfloat162float(l2.x);
    float vy = __bfloat162float(h2.y) + __bfloat162float(l2.y);
    float s  = vx + vy, sq = vx*vx + vy*vy;
    #pragma unroll
    for (int o=16;o;o>>=1){
        s  += __shfl_xor_sync(0xffffffffu, s,  o);
        sq += __shfl_xor_sync(0xffffffffu, sq, o);
    }
    __shared__ float sh[8], shq[8];
    int w = t>>5, lane = t&31;
    if (!lane){ sh[w]=s; shq[w]=sq; }
    __syncthreads();
    float ts=0.f, tq=0.f;
    #pragma unroll
    for (int i=0;i<8;i++){ ts+=sh[i]; tq+=shq[i]; }
    float mu = ts*(1.f/Dd);
    float rv = rsqrtf(tq*(1.f/Dd) - mu*mu + 1e-5f);
    float ox = (vx-mu)*rv*g[2*t]   + bta[2*t];
    float oy = (vy-mu)*rv*g[2*t+1] + bta[2*t+1];
    __nv_bfloat16 hx = __float2bfloat16(ox), hy = __float2bfloat16(oy);
    __nv_bfloat162 oh; oh.x = hx; oh.y = hy;
    __nv_bfloat162 ol;
    ol.x = __float2bfloat16(ox - __bfloat162float(hx));
    ol.y = __float2bfloat16(oy - __bfloat162float(hy));
    *(__nv_bfloat162*)(out + idx) = oh;
    *(__nv_bfloat162*)(out + PL_D + idx) = ol;
}

__global__ void embed_kernel(const int* __restrict__ x, const float* __restrict__ emb,
                             const float* __restrict__ pos, __nv_bfloat16* __restrict__ h)
{
    int token = blockIdx.x;
    int s = token & (Ss-1);
    int id = x[token];
    int t = threadIdx.x;
    float2 e = *(const float2*)(emb + (long)id*Dd + 2*t);
    float2 p = *(const float2*)(pos + (long)s*Dd + 2*t);
    float vx = e.x + p.x, vy = e.y + p.y;
    __nv_bfloat16 hx = __float2bfloat16(vx), hy = __float2bfloat16(vy);
    __nv_bfloat162 oh; oh.x = hx; oh.y = hy;
    __nv_bfloat162 ol;
    ol.x = __float2bfloat16(vx - __bfloat162float(hx));
    ol.y = __float2bfloat16(vy - __bfloat162float(hy));
    long idx = (long)token*Dd + 2*t;
    *(__nv_bfloat162*)(h + idx) = oh;
    *(__nv_bfloat162*)(h + PL_D + idx) = ol;
}

__global__ void head1_kernel(const float* __restrict__ pool, const float* __restrict__ Wh1,
                             const float* __restrict__ bh1, float* __restrict__ h1)
{
    int b = blockIdx.x;
    __shared__ float xr[Dd];
    for (int i=threadIdx.x; i<Dd; i+=blockDim.x) xr[i] = pool[(long)b*Dd + i];
    __syncthreads();
    int t = threadIdx.x;
    float s = bh1[t];
    #pragma unroll 4
    for (int k=0;k<Dd;k++) s = fmaf(xr[k], Wh1[(long)k*DHh + t], s);
    h1[(long)b*DHh + t] = fmaxf(s, 0.f);
}
__global__ void head2_kernel(const float* __restrict__ h1, const float* __restrict__ Wh2,
                             const float* __restrict__ bh2, float* __restrict__ out)
{
    int t = threadIdx.x;
    if (t < Bb*CC){
        int b = t / CC, c = t % CC;
        float s = bh2[c];
        #pragma unroll 4
        for (int k=0;k<DHh;k++) s = fmaf(h1[(long)b*DHh + k], Wh2[(long)k*CC + c], s);
        out[t] = s;
    }
}

// ===================== launch =====================
extern "C" void kernel_launch(void* const* d_in, const int* in_sizes, int n_in,
                              void* d_out, int out_size)
{
    const int*   x   = (const int*)  d_in[0];
    const float* emb = (const float*)d_in[1];
    const float* pos = (const float*)d_in[2];
    const float* Wq  = (const float*)d_in[3];   const float* bq = (const float*)d_in[4];
    const float* Wk  = (const float*)d_in[5];   const float* bk = (const float*)d_in[6];
    const float* Wv  = (const float*)d_in[7];   const float* bv = (const float*)d_in[8];
    const float* Wf  = (const float*)d_in[9];   const float* bf = (const float*)d_in[10];
    const float* Wo  = (const float*)d_in[11];  const float* bo = (const float*)d_in[12];
    const float* lng = (const float*)d_in[13];  const float* lnb= (const float*)d_in[14];
    const float* W1  = (const float*)d_in[15];  const float* b1 = (const float*)d_in[16];
    const float* W2  = (const float*)d_in[17];  const float* b2 = (const float*)d_in[18];
    const float* Wh1 = (const float*)d_in[19];  const float* bh1= (const float*)d_in[20];
    const float* Wh2 = (const float*)d_in[21];  const float* bh2= (const float*)d_in[22];

    __nv_bfloat16 *hS,*qS,*kS,*vS,*tS,*pqS,*pkS,*mS,*kvtS,*wq,*wk,*wv,*wo,*wf,*w1,*w2;
    float *kvp,*ksp,*ks,*z,*pp,*pool,*h1;
    cudaGetSymbolAddress((void**)&hS,  g_hS);   cudaGetSymbolAddress((void**)&qS,  g_qS);
    cudaGetSymbolAddress((void**)&kS,  g_kS);   cudaGetSymbolAddress((void**)&vS,  g_vS);
    cudaGetSymbolAddress((void**)&tS,  g_tS);   cudaGetSymbolAddress((void**)&pqS, g_pqS);
    cudaGetSymbolAddress((void**)&pkS, g_pkS);  cudaGetSymbolAddress((void**)&mS,  g_mS);
    cudaGetSymbolAddress((void**)&kvtS,g_kvtS);
    cudaGetSymbolAddress((void**)&wq, g_wq); cudaGetSymbolAddress((void**)&wk, g_wk);
    cudaGetSymbolAddress((void**)&wv, g_wv); cudaGetSymbolAddress((void**)&wo, g_wo);
    cudaGetSymbolAddress((void**)&wf, g_wf); cudaGetSymbolAddress((void**)&w1, g_w1);
    cudaGetSymbolAddress((void**)&w2, g_w2);
    cudaGetSymbolAddress((void**)&kvp, g_kvp); cudaGetSymbolAddress((void**)&ksp, g_ksp);
    cudaGetSymbolAddress((void**)&ks,  g_ks);  cudaGetSymbolAddress((void**)&z,   g_z);
    cudaGetSymbolAddress((void**)&pp,  g_pp);  cudaGetSymbolAddress((void**)&pool,g_pool);
    cudaGetSymbolAddress((void**)&h1,  g_h1);

    cudaFuncSetAttribute(gemm_mma<0>, cudaFuncAttributeMaxDynamicSharedMemorySize, SMEMG);
    cudaFuncSetAttribute(gemm_mma<1>, cudaFuncAttributeMaxDynamicSharedMemorySize, SMEMG);
    cudaFuncSetAttribute(gemm_mma<2>, cudaFuncAttributeMaxDynamicSharedMemorySize, SMEMG);
    cudaFuncSetAttribute(gemm_mma<3>, cudaFuncAttributeMaxDynamicSharedMemorySize, SMEMG);

    // weight conversion
    dim3 wt(32,8);
    wconv<<<dim3(Dd/32,  Dd/32,  Ll), wt>>>(Wq, wq, Dd, Dd);
    wconv<<<dim3(Dd/32,  Dd/32,  Ll), wt>>>(Wk, wk, Dd, Dd);
    wconv<<<dim3(Dd/32,  Dd/32,  Ll), wt>>>(Wv, wv, Dd, Dd);
    wconv<<<dim3(Dd/32,  Dd/32,  Ll), wt>>>(Wo, wo, Dd, Dd);
    wconv<<<dim3(Pp/32,  Dd/32,  Ll), wt>>>(Wf, wf, Dd, Pp);
    wconv<<<dim3(DFf/32, Dd/32,  Ll), wt>>>(W1, w1, Dd, DFf);
    wconv<<<dim3(Dd/32,  DFf/32, Ll), wt>>>(W2, w2, DFf, Dd);

    embed_kernel<<<BS,256>>>(x, emb, pos, hS);

    const dim3 gDD(Dd/128, BS/128, 1);
    const dim3 gDP(1,      BS/128, 1);
    const dim3 gDF(DFf/128,BS/128, 1);
    const dim3 gAT(Dd/128, Ss/128, Bb);

    for (int l=0; l<Ll; l++){
        const long wDD = (long)2*Dd*Dd, wDP = (long)2*Pp*Dd, wDF = (long)2*DFf*Dd;
        gemm_mma<0><<<gDD,256,SMEMG>>>(hS, PL_D, wq + l*wDD, (long)Dd*Dd, 0, bq + l*Dd, nullptr, qS, PL_D, Dd, Dd);
        gemm_mma<0><<<gDD,256,SMEMG>>>(hS, PL_D, wk + l*wDD, (long)Dd*Dd, 0, bk + l*Dd, nullptr, kS, PL_D, Dd, Dd);
        gemm_mma<0><<<gDD,256,SMEMG>>>(hS, PL_D, wv + l*wDD, (long)Dd*Dd, 0, bv + l*Dd, nullptr, vS, PL_D, Dd, Dd);
        gemm_mma<1><<<gDP,256,SMEMG>>>(qS, PL_D, wf + l*wDP, (long)Pp*Dd, 0, bf + l*Pp, nullptr, pqS, PL_P, Pp, Dd);
        gemm_mma<1><<<gDP,256,SMEMG>>>(kS, PL_D, wf + l*wDP, (long)Pp*Dd, 0, bf + l*Pp, nullptr, pkS, PL_P, Pp, Dd);
        colsum_part<<<dim3(32,Bb),Pp>>>(pkS, PL_P, ksp, Ss/32, Pp, (long)Ss*Pp);
        colsum_fin <<<Bb,Pp>>>(ksp, ks, Pp, 32, 1.f);
        kv_splitk<<<dim3(Dd/128,1,Bb*KV_SPLIT),256>>>(pkS, vS, kvp);
        reduce_kvt<<<(Bb*Pp*Dd)/256,256>>>(kvp, kvtS);
        z_kernel<<<BS/8,256>>>(pqS, ks, z);
        gemm_mma<3><<<gAT,256,SMEMG>>>(pqS, PL_P, kvtS, (long)Dd*Pp, (long)2*Dd*Pp,
                                       nullptr, z, tS, PL_D, Dd, Pp);
        gemm_mma<0><<<gDD,256,SMEMG>>>(tS, PL_D, wo + l*wDD, (long)Dd*Dd, 0, bo + l*Dd, nullptr, qS, PL_D, Dd, Dd);
        ln_kernel<<<BS,256>>>(qS, lng + l*Dd, lnb + l*Dd, tS);
        gemm_mma<2><<<gDF,256,SMEMG>>>(tS, PL_D, w1 + l*wDF, (long)DFf*Dd, 0, b1 + l*DFf, nullptr, mS, PL_F, DFf, Dd);
        gemm_mma<0><<<gDD,256,SMEMG>>>(mS, PL_F, w2 + l*wDF, (long)Dd*DFf, 0, b2 + l*Dd, nullptr, hS, PL_D, Dd, DFf);
    }

    colsum_part<<<dim3(32,Bb),Dd>>>(hS, PL_D, pp, Ss/32, Dd, (long)Ss*Dd);
    colsum_fin <<<Bb,Dd>>>(pp, pool, Dd, 32, 1.0f/Ss);
    head1_kernel<<<Bb,DHh>>>(pool, Wh1, bh1, h1);
    head2_kernel<<<1,32>>>(h1, Wh2, bh2, (float*)d_out);
}

// round 5
// speedup vs baseline: 1.6332x; 1.0555x over previous
#include <cuda_runtime.h>
#include <cuda_bf16.h>
#include <math.h>
#include <stdint.h>

#define Bb  8
#define Ss  4096
#define Dd  512
#define Pp  128
#define Ll  4
#define DFf 2048
#define DHh 256
#define CC  2
#define BS  (Bb*Ss)
#define KVS 16

// ===================== PTX helpers (plain sm_80-level ISA only) =====================
__device__ __forceinline__ uint32_t smem_to_u32(const void* p) {
    uint32_t a;
    asm("{ .reg .u64 t; cvta.to.shared.u64 t, %1; cvt.u32.u64 %0, t; }" : "=r"(a) : "l"(p));
    return a;
}
#define CP_ASYNC16(s, g) \
    asm volatile("cp.async.cg.shared.global [%0], [%1], 16;" :: "r"(s), "l"(g) : "memory")
#define CP_COMMIT() asm volatile("cp.async.commit_group;" ::: "memory")
#define CP_WAIT2()  asm volatile("cp.async.wait_group 2;" ::: "memory")

__device__ __forceinline__ void ldsm4(uint32_t* r, uint32_t addr){
    asm volatile("ldmatrix.sync.aligned.m8n8.x4.shared.b16 {%0,%1,%2,%3}, [%4];"
        : "=r"(r[0]),"=r"(r[1]),"=r"(r[2]),"=r"(r[3]) : "r"(addr));
}
__device__ __forceinline__ void mma_bf16(float* d, const uint32_t* a, const uint32_t* b){
    asm volatile("mma.sync.aligned.m16n8k16.row.col.f32.bf16.bf16.f32 "
        "{%0,%1,%2,%3}, {%4,%5,%6,%7}, {%8,%9}, {%0,%1,%2,%3};"
        : "+f"(d[0]),"+f"(d[1]),"+f"(d[2]),"+f"(d[3])
        : "r"(a[0]),"r"(a[1]),"r"(a[2]),"r"(a[3]), "r"(b[0]),"r"(b[1]));
}

// ===================== device globals =====================
#define PL_D  ((long)BS*Dd)
#define PL_P  ((long)BS*Pp)
#define PL_F  ((long)BS*DFf)
__device__ __align__(256) __nv_bfloat16 g_hS [2*(size_t)BS*Dd];
__device__ __align__(256) __nv_bfloat16 g_qS [2*(size_t)BS*Dd];
__device__ __align__(256) __nv_bfloat16 g_kS [2*(size_t)BS*Dd];
__device__ __align__(256) __nv_bfloat16 g_vT [2*(size_t)BS*Dd];   // [b][2][D][S]
__device__ __align__(256) __nv_bfloat16 g_tS [2*(size_t)BS*Dd];
__device__ __align__(256) __nv_bfloat16 g_pqS[2*(size_t)BS*Pp];
__device__ __align__(256) __nv_bfloat16 g_pkT[2*(size_t)BS*Pp];   // [b][2][P][S]
__device__ __align__(256) __nv_bfloat16 g_mS [2*(size_t)BS*DFf];
__device__ __align__(256) __nv_bfloat16 g_kvtS[(size_t)Bb*2*Dd*Pp]; // [b][2][D][P]
__device__ __align__(256) __nv_bfloat16 g_wq[(size_t)Ll*2*Dd*Dd];
__device__ __align__(256) __nv_bfloat16 g_wk[(size_t)Ll*2*Dd*Dd];
__device__ __align__(256) __nv_bfloat16 g_wv[(size_t)Ll*2*Dd*Dd];
__device__ __align__(256) __nv_bfloat16 g_wo[(size_t)Ll*2*Dd*Dd];
__device__ __align__(256) __nv_bfloat16 g_wf[(size_t)Ll*2*Pp*Dd];
__device__ __align__(256) __nv_bfloat16 g_w1[(size_t)Ll*2*DFf*Dd];
__device__ __align__(256) __nv_bfloat16 g_w2[(size_t)Ll*2*Dd*DFf];
__device__ float g_kvp[(size_t)Bb*KVS*Pp*Dd];
__device__ float g_ks [Bb*Pp];
__device__ float g_z  [BS];
__device__ float g_pp [Bb*32*Dd];
__device__ float g_pool[Bb*Dd];
__device__ float g_h1 [Bb*DHh];

__device__ __forceinline__ float gelu_tanh(float x){
    float u = 0.7978845608028654f*(x + 0.044715f*x*x*x);
    return 0.5f*x*(1.0f + tanhf(u));
}

// ===================== split-bf16 HMMA GEMM, fragment-reuse mainloop =====================
// C = act(A @ B^T).  A split [2][M,K] K-major, B split [2][N,K] K-major.
// Per K-32 chunk, stage Ah/Al/Bh/Bl (8KB each) and issue the 3 combos from regs.
// 128x128 tile, 4-stage cp.async, 256 threads (8 warps = 4m x 2n, warp tile 32x64).
#define NSTG 4
#define STGB 32768
#define SMEMG (NSTG*STGB)   // 128KB

template<int EPI, int TOUT>  // EPI 0:+bias 1:+bias,elu+1 2:+bias,gelu 3:*1/(aux+eps); TOUT 0:normal split, 1:transposed split [b][2][N][Ss]
__global__ void __launch_bounds__(256)
gemm_mma(const __nv_bfloat16* __restrict__ A, long a_plane,
         const __nv_bfloat16* __restrict__ Bw, long b_plane, long b_batch,
         const float* __restrict__ bias, const float* __restrict__ aux,
         __nv_bfloat16* __restrict__ C, long c_plane, int N, int K)
{
    extern __shared__ __align__(1024) char smem[];
    const uint32_t sb = smem_to_u32(smem);
    const int tid = threadIdx.x, wid = tid >> 5, lane = tid & 31;
    const int row0 = (blockIdx.z*gridDim.y + blockIdx.y)*128;
    const int col0 = blockIdx.x*128;
    const int kc32 = K >> 5;
    const __nv_bfloat16* Bt = Bw + (long)blockIdx.z*b_batch;

    auto load_chunk = [&](int i, int s){
        if (i < kc32){
            const int koff = i << 5;
            const uint32_t stg = sb + s*STGB;
            #pragma unroll
            for (int pl = 0; pl < 4; ++pl){
                const __nv_bfloat16* g = (pl < 2)
                    ? (A  + ((pl&1) ? a_plane : 0) + (long)row0*K + koff)
                    : (Bt + ((pl&1) ? b_plane : 0) + (long)col0*K + koff);
                #pragma unroll
                for (int rep = 0; rep < 2; ++rep){
                    const int t = tid + rep*256;
                    const int r = t & 127, kc = t >> 7;
                    CP_ASYNC16(stg + pl*8192 + (uint32_t)((kc*128 + r)*16), g + (long)r*K + kc*8);
                }
            }
        }
        CP_COMMIT();
    };

    float acc[2][8][4];
    #pragma unroll
    for (int mt=0;mt<2;mt++)
        #pragma unroll
        for (int ni=0;ni<8;ni++)
            #pragma unroll
            for (int r=0;r<4;r++) acc[mt][ni][r]=0.f;

    const int wm = (wid >> 1)*32, wn = (wid & 1)*64;
    const int a_mrow = wm + ((lane>>3)&1)*8 + (lane&7);
    const int a_kc   = (lane>>4);
    const int b_nrow = wn + ((lane>>4)&1)*8 + (lane&7);
    const int b_kc   = ((lane>>3)&1);

    #pragma unroll
    for (int s = 0; s < NSTG-1; ++s) load_chunk(s, s);

    for (int i = 0; i < kc32; ++i){
        CP_WAIT2();
        __syncthreads();
        load_chunk(i + NSTG-1, (i + NSTG-1) & (NSTG-1));
        const uint32_t stg = sb + (i & (NSTG-1))*STGB;
        const uint32_t pAh = stg, pAl = stg + 8192, pBh = stg + 16384, pBl = stg + 24576;
        #pragma unroll
        for (int step = 0; step < 2; ++step){
            uint32_t ah[2][4], al[2][4];
            #pragma unroll
            for (int mt = 0; mt < 2; ++mt){
                const uint32_t aoff = (uint32_t)((((a_kc + 2*step)*128) + a_mrow + mt*16)*16);
                ldsm4(ah[mt], pAh + aoff);
                ldsm4(al[mt], pAl + aoff);
            }
            #pragma unroll
            for (int nt4 = 0; nt4 < 4; ++nt4){
                const uint32_t boff = (uint32_t)((((b_kc + 2*step)*128) + b_nrow + nt4*16)*16);
                uint32_t bh[4], bl[4];
                ldsm4(bh, pBh + boff);
                ldsm4(bl, pBl + boff);
                #pragma unroll
                for (int mt = 0; mt < 2; ++mt){
                    mma_bf16(acc[mt][2*nt4  ], ah[mt], bh);
                    mma_bf16(acc[mt][2*nt4+1], ah[mt], bh+2);
                    mma_bf16(acc[mt][2*nt4  ], al[mt], bh);
                    mma_bf16(acc[mt][2*nt4+1], al[mt], bh+2);
                    mma_bf16(acc[mt][2*nt4  ], ah[mt], bl);
                    mma_bf16(acc[mt][2*nt4+1], ah[mt], bl+2);
                }
            }
        }
    }

    // ---- epilogue ----
    float bv0[8], bv1[8];
    if (EPI != 3){
        #pragma unroll
        for (int ni = 0; ni < 8; ++ni){
            const int col = col0 + wn + ni*8 + (lane&3)*2;
            bv0[ni] = bias[col]; bv1[ni] = bias[col+1];
        }
    }
    #pragma unroll
    for (int mt = 0; mt < 2; ++mt){
        #pragma unroll
        for (int h = 0; h < 2; ++h){
            const long row = row0 + wm + mt*16 + h*8 + (lane>>2);
            float sc = 1.f;
            if (EPI == 3) sc = 1.f/(aux[row] + 1e-6f);
            const int bt = (int)(row >> 12), st = (int)(row & (Ss-1));
            __nv_bfloat16* tHi = (TOUT==1) ? (C + (long)bt*2*N*Ss) : nullptr;
            __nv_bfloat16* tLo = (TOUT==1) ? (tHi + (long)N*Ss) : nullptr;
            #pragma unroll
            for (int ni = 0; ni < 8; ++ni){
                const int col = col0 + wn + ni*8 + (lane&3)*2;
                float c0 = acc[mt][ni][2*h], c1 = acc[mt][ni][2*h+1];
                if (EPI != 3){ c0 += bv0[ni]; c1 += bv1[ni]; }
                if (EPI == 1){ c0 = (c0>0.f)?(c0+1.f):expf(c0); c1 = (c1>0.f)?(c1+1.f):expf(c1); }
                if (EPI == 2){ c0 = gelu_tanh(c0); c1 = gelu_tanh(c1); }
                if (EPI == 3){ c0 *= sc; c1 *= sc; }
                __nv_bfloat16 h0 = __float2bfloat16(c0), h1 = __float2bfloat16(c1);
                __nv_bfloat16 l0 = __float2bfloat16(c0 - __bfloat162float(h0));
                __nv_bfloat16 l1 = __float2bfloat16(c1 - __bfloat162float(h1));
                if (TOUT == 0){
                    __nv_bfloat162 vh; vh.x = h0; vh.y = h1;
                    __nv_bfloat162 vl; vl.x = l0; vl.y = l1;
                    *(__nv_bfloat162*)(C + row*(long)N + col) = vh;
                    *(__nv_bfloat162*)(C + c_plane + row*(long)N + col) = vl;
                } else {
                    tHi[(long)col*Ss + st]     = h0;
                    tHi[(long)(col+1)*Ss + st] = h1;
                    tLo[(long)col*Ss + st]     = l0;
                    tLo[(long)(col+1)*Ss + st] = l1;
                }
            }
        }
    }
}

// ===================== kv gemm: kv^T[b] = vT[b] @ pkT[b]^T, split-K fp32 partials =====================
// A = vT [D, Ss] K-major (lda=Ss), B = pkT [P, Ss] K-major. grid (1, Dd/128, Bb*KVS).
__global__ void __launch_bounds__(256)
gemm_kv(const __nv_bfloat16* __restrict__ vT, const __nv_bfloat16* __restrict__ pkT,
        float* __restrict__ part)
{
    extern __shared__ __align__(1024) char smem[];
    const uint32_t sb = smem_to_u32(smem);
    const int tid = threadIdx.x, wid = tid >> 5, lane = tid & 31;
    const int bz = blockIdx.z, b = bz >> 4, sp = bz & (KVS-1);
    const int row0 = blockIdx.y*128;
    const int kbeg = sp*(Ss/KVS);
    const int kc32 = (Ss/KVS) >> 5;   // 8
    const __nv_bfloat16* A  = vT  + (long)b*2*Dd*Ss + kbeg;
    const __nv_bfloat16* Bp = pkT + (long)b*2*Pp*Ss + kbeg;
    const long a_plane = (long)Dd*Ss, b_plane = (long)Pp*Ss;

    auto load_chunk = [&](int i, int s){
        if (i < kc32){
            const int koff = i << 5;
            const uint32_t stg = sb + s*STGB;
            #pragma unroll
            for (int pl = 0; pl < 4; ++pl){
                const __nv_bfloat16* g = (pl < 2)
                    ? (A  + ((pl&1) ? a_plane : 0) + (long)row0*Ss + koff)
                    : (Bp + ((pl&1) ? b_plane : 0) + koff);
                #pragma unroll
                for (int rep = 0; rep < 2; ++rep){
                    const int t = tid + rep*256;
                    const int r = t & 127, kc = t >> 7;
                    CP_ASYNC16(stg + pl*8192 + (uint32_t)((kc*128 + r)*16), g + (long)r*Ss + kc*8);
                }
            }
        }
        CP_COMMIT();
    };

    float acc[2][8][4];
    #pragma unroll
    for (int mt=0;mt<2;mt++)
        #pragma unroll
        for (int ni=0;ni<8;ni++)
            #pragma unroll
            for (int r=0;r<4;r++) acc[mt][ni][r]=0.f;

    const int wm = (wid >> 1)*32, wn = (wid & 1)*64;
    const int a_mrow = wm + ((lane>>3)&1)*8 + (lane&7);
    const int a_kc   = (lane>>4);
    const int b_nrow = wn + ((lane>>4)&1)*8 + (lane&7);
    const int b_kc   = ((lane>>3)&1);

    #pragma unroll
    for (int s = 0; s < NSTG-1; ++s) load_chunk(s, s);

    for (int i = 0; i < kc32; ++i){
        CP_WAIT2();
        __syncthreads();
        load_chunk(i + NSTG-1, (i + NSTG-1) & (NSTG-1));
        const uint32_t stg = sb + (i & (NSTG-1))*STGB;
        const uint32_t pAh = stg, pAl = stg + 8192, pBh = stg + 16384, pBl = stg + 24576;
        #pragma unroll
        for (int step = 0; step < 2; ++step){
            uint32_t ah[2][4], al[2][4];
            #pragma unroll
            for (int mt = 0; mt < 2; ++mt){
                const uint32_t aoff = (uint32_t)((((a_kc + 2*step)*128) + a_mrow + mt*16)*16);
                ldsm4(ah[mt], pAh + aoff);
                ldsm4(al[mt], pAl + aoff);
            }
            #pragma unroll
            for (int nt4 = 0; nt4 < 4; ++nt4){
                const uint32_t boff = (uint32_t)((((b_kc + 2*step)*128) + b_nrow + nt4*16)*16);
                uint32_t bh[4], bl[4];
                ldsm4(bh, pBh + boff);
                ldsm4(bl, pBl + boff);
                #pragma unroll
                for (int mt = 0; mt < 2; ++mt){
                    mma_bf16(acc[mt][2*nt4  ], ah[mt], bh);
                    mma_bf16(acc[mt][2*nt4+1], ah[mt], bh+2);
                    mma_bf16(acc[mt][2*nt4  ], al[mt], bh);
                    mma_bf16(acc[mt][2*nt4+1], al[mt], bh+2);
                    mma_bf16(acc[mt][2*nt4  ], ah[mt], bl);
                    mma_bf16(acc[mt][2*nt4+1], ah[mt], bl+2);
                }
            }
        }
    }

    float* Cb = part + (long)bz*Dd*Pp;
    #pragma unroll
    for (int mt = 0; mt < 2; ++mt){
        #pragma unroll
        for (int h = 0; h < 2; ++h){
            const int row = row0 + wm + mt*16 + h*8 + (lane>>2);
            #pragma unroll
            for (int ni = 0; ni < 8; ++ni){
                const int col = wn + ni*8 + (lane&3)*2;
                *(float2*)(Cb + (long)row*Pp + col) =
                    make_float2(acc[mt][ni][2*h], acc[mt][ni][2*h+1]);
            }
        }
    }
}

// reduce partials -> kv^T split-bf16 [b][2][Dd][Pp]
__global__ void reduce_kvt(const float* __restrict__ part, __nv_bfloat16* __restrict__ kvt)
{
    long i = (long)blockIdx.x*256 + threadIdx.x;   // over Bb*Dd*Pp
    int b = (int)(i / (Dd*Pp)); int r = (int)(i % (Dd*Pp));
    const float* q = part + ((long)b*KVS)*Dd*Pp + r;
    float s = 0.f;
    #pragma unroll
    for (int j=0;j<KVS;j++) s += q[(long)j*Dd*Pp];
    __nv_bfloat16 h = __float2bfloat16(s);
    long o = (long)b*2*Dd*Pp + r;
    kvt[o] = h; kvt[o + (long)Dd*Pp] = __float2bfloat16(s - __bfloat162float(h));
}

// ===================== weight split+transpose: fp32 [L][K,N] -> bf16 [L][2][N][K] =====================
__global__ void wconv(const float* __restrict__ W, __nv_bfloat16* __restrict__ out, int K, int N)
{
    __shared__ float t[32][33];
    const int n0 = blockIdx.x*32, k0 = blockIdx.y*32, l = blockIdx.z;
    const float* Wl = W + (long)l*K*N;
    __nv_bfloat16* oh = out + (long)l*2*N*K;
    __nv_bfloat16* ol = oh + (long)N*K;
    for (int i = threadIdx.y; i < 32; i += 8)
        t[i][threadIdx.x] = Wl[(long)(k0+i)*N + n0 + threadIdx.x];
    __syncthreads();
    for (int i = threadIdx.y; i < 32; i += 8) {
        float v = t[threadIdx.x][i];
        long o = (long)(n0+i)*K + k0 + threadIdx.x;
        __nv_bfloat16 h = __float2bfloat16(v);
        oh[o] = h; ol[o] = __float2bfloat16(v - __bfloat162float(h));
    }
}

// ksum[b,p] = sum_s pkT (hi+lo); deterministic block tree reduce
__global__ void ksum_kernel(const __nv_bfloat16* __restrict__ pkT, float* __restrict__ ks)
{
    const int p = blockIdx.x, b = blockIdx.y, t = threadIdx.x;
    const __nv_bfloat16* hi = pkT + ((long)b*2*Pp + p)*Ss;
    const __nv_bfloat16* lo = hi + (long)Pp*Ss;
    float s = 0.f;
    for (int i = t; i < Ss; i += 256)
        s += __bfloat162float(hi[i]) + __bfloat162float(lo[i]);
    __shared__ float sh[256];
    sh[t] = s; __syncthreads();
    #pragma unroll
    for (int o = 128; o > 0; o >>= 1){
        if (t < o) sh[t] += sh[t+o];
        __syncthreads();
    }
    if (!t) ks[b*Pp + p] = sh[0];
}

// column sums over split-bf16 input (for final mean pool)
__global__ void colsum_part(const __nv_bfloat16* __restrict__ in, long plane,
                            float* __restrict__ part, int rpc, int cols, long bstride)
{
    int b = blockIdx.y, ch = blockIdx.x, c = threadIdx.x;
    long base = (long)b*bstride + (long)ch*rpc*cols + c;
    float s = 0.f;
    #pragma unroll 4
    for (int r=0;r<rpc;r++){
        long idx = base + (long)r*cols;
        s += __bfloat162float(in[idx]) + __bfloat162float(in[plane+idx]);
    }
    part[((long)b*gridDim.x + ch)*cols + c] = s;
}
__global__ void colsum_fin(const float* __restrict__ part, float* __restrict__ out,
                           int cols, int chunks, float scale)
{
    int b = blockIdx.x, c = threadIdx.x;
    float s = 0.f;
    for (int ch=0;ch<chunks;ch++) s += part[((long)b*chunks+ch)*cols + c];
    out[(long)b*cols + c] = s*scale;
}

// z[b,s] = dot(pq_split[b,s,:], ksum[b,:])
__global__ void z_kernel(const __nv_bfloat16* __restrict__ pq, const float* __restrict__ ksum,
                         float* __restrict__ z)
{
    int gw = (int)((blockIdx.x*(long)blockDim.x + threadIdx.x) >> 5);
    int lane = threadIdx.x & 31;
    if (gw >= BS) return;
    int b = gw >> 12;
    const __nv_bfloat16* pr = pq + (long)gw*Pp;
    const float* kr = ksum + b*Pp;
    float s = 0.f;
    #pragma unroll
    for (int p=lane; p<Pp; p+=32)
        s = fmaf(__bfloat162float(pr[p]) + __bfloat162float(pr[PL_P+p]), kr[p], s);
    #pragma unroll
    for (int o=16;o;o>>=1) s += __shfl_xor_sync(0xffffffffu, s, o);
    if (!lane) z[gw] = s;
}

// layernorm: split in, split out
__global__ void ln_kernel(const __nv_bfloat16* __restrict__ in, const float* __restrict__ g,
                          const float* __restrict__ bta, __nv_bfloat16* __restrict__ out)
{
    long row = blockIdx.x;
    int t = threadIdx.x;
    long idx = row*Dd + 2*t;
    __nv_bfloat162 h2 = *(const __nv_bfloat162*)(in + idx);
    __nv_bfloat162 l2 = *(const __nv_bfloat162*)(in + PL_D + idx);
    float vx = __bfloat162float(h2.x) + __bfloat162float(l2.x);
    float vy = __bfloat162float(h2.y) + __bfloat162float(l2.y);
    float s  = vx + vy, sq = vx*vx + vy*vy;
    #pragma unroll
    for (int o=16;o;o>>=1){
        s  += __shfl_xor_sync(0xffffffffu, s,  o);
        sq += __shfl_xor_sync(0xffffffffu, sq, o);
    }
    __shared__ float sh[8], shq[8];
    int w = t>>5, lane = t&31;
    if (!lane){ sh[w]=s; shq[w]=sq; }
    __syncthreads();
    float ts=0.f, tq=0.f;
    #pragma unroll
    for (int i=0;i<8;i++){ ts+=sh[i]; tq+=shq[i]; }
    float mu = ts*(1.f/Dd);
    float rv = rsqrtf(tq*(1.f/Dd) - mu*mu + 1e-5f);
    float ox = (vx-mu)*rv*g[2*t]   + bta[2*t];
    float oy = (vy-mu)*rv*g[2*t+1] + bta[2*t+1];
    __nv_bfloat16 hx = __float2bfloat16(ox), hy = __float2bfloat16(oy);
    __nv_bfloat162 oh; oh.x = hx; oh.y = hy;
    __nv_bfloat162 ol;
    ol.x = __float2bfloat16(ox - __bfloat162float(hx));
    ol.y = __float2bfloat16(oy - __bfloat162float(hy));
    *(__nv_bfloat162*)(out + idx) = oh;
    *(__nv_bfloat162*)(out + PL_D + idx) = ol;
}

__global__ void embed_kernel(const int* __restrict__ x, const float* __restrict__ emb,
                             const float* __restrict__ pos, __nv_bfloat16* __restrict__ h)
{
    int token = blockIdx.x;
    int s = token & (Ss-1);
    int id = x[token];
    int t = threadIdx.x;
    float2 e = *(const float2*)(emb + (long)id*Dd + 2*t);
    float2 p = *(const float2*)(pos + (long)s*Dd + 2*t);
    float vx = e.x + p.x, vy = e.y + p.y;
    __nv_bfloat16 hx = __float2bfloat16(vx), hy = __float2bfloat16(vy);
    __nv_bfloat162 oh; oh.x = hx; oh.y = hy;
    __nv_bfloat162 ol;
    ol.x = __float2bfloat16(vx - __bfloat162float(hx));
    ol.y = __float2bfloat16(vy - __bfloat162float(hy));
    long idx = (long)token*Dd + 2*t;
    *(__nv_bfloat162*)(h + idx) = oh;
    *(__nv_bfloat162*)(h + PL_D + idx) = ol;
}

__global__ void head1_kernel(const float* __restrict__ pool, const float* __restrict__ Wh1,
                             const float* __restrict__ bh1, float* __restrict__ h1)
{
    int b = blockIdx.x;
    __shared__ float xr[Dd];
    for (int i=threadIdx.x; i<Dd; i+=blockDim.x) xr[i] = pool[(long)b*Dd + i];
    __syncthreads();
    int t = threadIdx.x;
    float s = bh1[t];
    #pragma unroll 4
    for (int k=0;k<Dd;k++) s = fmaf(xr[k], Wh1[(long)k*DHh + t], s);
    h1[(long)b*DHh + t] = fmaxf(s, 0.f);
}
__global__ void head2_kernel(const float* __restrict__ h1, const float* __restrict__ Wh2,
                             const float* __restrict__ bh2, float* __restrict__ out)
{
    int t = threadIdx.x;
    if (t < Bb*CC){
        int b = t / CC, c = t % CC;
        float s = bh2[c];
        #pragma unroll 4
        for (int k=0;k<DHh;k++) s = fmaf(h1[(long)b*DHh + k], Wh2[(long)k*CC + c], s);
        out[t] = s;
    }
}

// ===================== launch =====================
extern "C" void kernel_launch(void* const* d_in, const int* in_sizes, int n_in,
                              void* d_out, int out_size)
{
    const int*   x   = (const int*)  d_in[0];
    const float* emb = (const float*)d_in[1];
    const float* pos = (const float*)d_in[2];
    const float* Wq  = (const float*)d_in[3];   const float* bq = (const float*)d_in[4];
    const float* Wk  = (const float*)d_in[5];   const float* bk = (const float*)d_in[6];
    const float* Wv  = (const float*)d_in[7];   const float* bv = (const float*)d_in[8];
    const float* Wf  = (const float*)d_in[9];   const float* bf = (const float*)d_in[10];
    const float* Wo  = (const float*)d_in[11];  const float* bo = (const float*)d_in[12];
    const float* lng = (const float*)d_in[13];  const float* lnb= (const float*)d_in[14];
    const float* W1  = (const float*)d_in[15];  const float* b1 = (const float*)d_in[16];
    const float* W2  = (const float*)d_in[17];  const float* b2 = (const float*)d_in[18];
    const float* Wh1 = (const float*)d_in[19];  const float* bh1= (const float*)d_in[20];
    const float* Wh2 = (const float*)d_in[21];  const float* bh2= (const float*)d_in[22];

    __nv_bfloat16 *hS,*qS,*kS,*vT,*tS,*pqS,*pkT,*mS,*kvtS,*wq,*wk,*wv,*wo,*wf,*w1,*w2;
    float *kvp,*ks,*z,*pp,*pool,*h1;
    cudaGetSymbolAddress((void**)&hS,  g_hS);   cudaGetSymbolAddress((void**)&qS,  g_qS);
    cudaGetSymbolAddress((void**)&kS,  g_kS);   cudaGetSymbolAddress((void**)&vT,  g_vT);
    cudaGetSymbolAddress((void**)&tS,  g_tS);   cudaGetSymbolAddress((void**)&pqS, g_pqS);
    cudaGetSymbolAddress((void**)&pkT, g_pkT);  cudaGetSymbolAddress((void**)&mS,  g_mS);
    cudaGetSymbolAddress((void**)&kvtS,g_kvtS);
    cudaGetSymbolAddress((void**)&wq, g_wq); cudaGetSymbolAddress((void**)&wk, g_wk);
    cudaGetSymbolAddress((void**)&wv, g_wv); cudaGetSymbolAddress((void**)&wo, g_wo);
    cudaGetSymbolAddress((void**)&wf, g_wf); cudaGetSymbolAddress((void**)&w1, g_w1);
    cudaGetSymbolAddress((void**)&w2, g_w2);
    cudaGetSymbolAddress((void**)&kvp, g_kvp);
    cudaGetSymbolAddress((void**)&ks,  g_ks);  cudaGetSymbolAddress((void**)&z,   g_z);
    cudaGetSymbolAddress((void**)&pp,  g_pp);  cudaGetSymbolAddress((void**)&pool,g_pool);
    cudaGetSymbolAddress((void**)&h1,  g_h1);

    cudaFuncSetAttribute(gemm_mma<0,0>, cudaFuncAttributeMaxDynamicSharedMemorySize, SMEMG);
    cudaFuncSetAttribute(gemm_mma<0,1>, cudaFuncAttributeMaxDynamicSharedMemorySize, SMEMG);
    cudaFuncSetAttribute(gemm_mma<1,0>, cudaFuncAttributeMaxDynamicSharedMemorySize, SMEMG);
    cudaFuncSetAttribute(gemm_mma<1,1>, cudaFuncAttributeMaxDynamicSharedMemorySize, SMEMG);
    cudaFuncSetAttribute(gemm_mma<2,0>, cudaFuncAttributeMaxDynamicSharedMemorySize, SMEMG);
    cudaFuncSetAttribute(gemm_mma<3,0>, cudaFuncAttributeMaxDynamicSharedMemorySize, SMEMG);
    cudaFuncSetAttribute(gemm_kv,       cudaFuncAttributeMaxDynamicSharedMemorySize, SMEMG);

    // weight conversion
    dim3 wt(32,8);
    wconv<<<dim3(Dd/32,  Dd/32,  Ll), wt>>>(Wq, wq, Dd, Dd);
    wconv<<<dim3(Dd/32,  Dd/32,  Ll), wt>>>(Wk, wk, Dd, Dd);
    wconv<<<dim3(Dd/32,  Dd/32,  Ll), wt>>>(Wv, wv, Dd, Dd);
    wconv<<<dim3(Dd/32,  Dd/32,  Ll), wt>>>(Wo, wo, Dd, Dd);
    wconv<<<dim3(Pp/32,  Dd/32,  Ll), wt>>>(Wf, wf, Dd, Pp);
    wconv<<<dim3(DFf/32, Dd/32,  Ll), wt>>>(W1, w1, Dd, DFf);
    wconv<<<dim3(Dd/32,  DFf/32, Ll), wt>>>(W2, w2, DFf, Dd);

    embed_kernel<<<BS,256>>>(x, emb, pos, hS);

    const dim3 gDD(Dd/128, BS/128, 1);
    const dim3 gDP(1,      BS/128, 1);
    const dim3 gDF(DFf/128,BS/128, 1);
    const dim3 gAT(Dd/128, Ss/128, Bb);
    const dim3 gKV(1, Dd/128, Bb*KVS);

    for (int l=0; l<Ll; l++){
        const long wDD = (long)2*Dd*Dd, wDP = (long)2*Pp*Dd, wDF = (long)2*DFf*Dd;
        gemm_mma<0,0><<<gDD,256,SMEMG>>>(hS, PL_D, wq + l*wDD, (long)Dd*Dd, 0, bq + l*Dd, nullptr, qS, PL_D, Dd, Dd);
        gemm_mma<0,0><<<gDD,256,SMEMG>>>(hS, PL_D, wk + l*wDD, (long)Dd*Dd, 0, bk + l*Dd, nullptr, kS, PL_D, Dd, Dd);
        gemm_mma<0,1><<<gDD,256,SMEMG>>>(hS, PL_D, wv + l*wDD, (long)Dd*Dd, 0, bv + l*Dd, nullptr, vT, 0, Dd, Dd);
        gemm_mma<1,0><<<gDP,256,SMEMG>>>(qS, PL_D, wf + l*wDP, (long)Pp*Dd, 0, bf + l*Pp, nullptr, pqS, PL_P, Pp, Dd);
        gemm_mma<1,1><<<gDP,256,SMEMG>>>(kS, PL_D, wf + l*wDP, (long)Pp*Dd, 0, bf + l*Pp, nullptr, pkT, 0, Pp, Dd);
        ksum_kernel<<<dim3(Pp,Bb),256>>>(pkT, ks);
        gemm_kv<<<gKV,256,SMEMG>>>(vT, pkT, kvp);
        reduce_kvt<<<(Bb*Dd*Pp)/256,256>>>(kvp, kvtS);
        z_kernel<<<BS/8,256>>>(pqS, ks, z);
        gemm_mma<3,0><<<gAT,256,SMEMG>>>(pqS, PL_P, kvtS, (long)Dd*Pp, (long)2*Dd*Pp,
                                         nullptr, z, tS, PL_D, Dd, Pp);
        gemm_mma<0,0><<<gDD,256,SMEMG>>>(tS, PL_D, wo + l*wDD, (long)Dd*Dd, 0, bo + l*Dd, nullptr, qS, PL_D, Dd, Dd);
        ln_kernel<<<BS,256>>>(qS, lng + l*Dd, lnb + l*Dd, tS);
        gemm_mma<2,0><<<gDF,256,SMEMG>>>(tS, PL_D, w1 + l*wDF, (long)DFf*Dd, 0, b1 + l*DFf, nullptr, mS, PL_F, DFf, Dd);
        gemm_mma<0,0><<<gDD,256,SMEMG>>>(mS, PL_F, w2 + l*wDF, (long)Dd*DFf, 0, b2 + l*Dd, nullptr, hS, PL_D, Dd, DFf);
    }

    colsum_part<<<dim3(32,Bb),Dd>>>(hS, PL_D, pp, Ss/32, Dd, (long)Ss*Dd);
    colsum_fin <<<Bb,Dd>>>(pp, pool, Dd, 32, 1.0f/Ss);
    head1_kernel<<<Bb,DHh>>>(pool, Wh1, bh1, h1);
    head2_kernel<<<1,32>>>(h1, Wh2, bh2, (float*)d_out);
}

// round 6
// speedup vs baseline: 3.3004x; 2.0208x over previous
#include <cuda_runtime.h>
#include <cuda_bf16.h>
#include <math.h>
#include <stdint.h>

#define Bb  8
#define Ss  4096
#define Dd  512
#define Pp  128
#define Ll  4
#define DFf 2048
#define DHh 256
#define CC  2
#define BS  (Bb*Ss)
#define KVS 16

// ===================== PTX helpers (sm_90 core features only) =====================
__device__ __forceinline__ uint32_t smem_to_u32(const void* p) {
    uint32_t a;
    asm("{ .reg .u64 t; cvta.to.shared.u64 t, %1; cvt.u32.u64 %0, t; }" : "=r"(a) : "l"(p));
    return a;
}
#define MBARRIER_INIT(m, c) \
    asm volatile("mbarrier.init.shared.b64 [%0], %1;" :: "r"((uint32_t)(m)), "r"((uint32_t)(c)) : "memory")
#define MBARRIER_EXPECT_TX(m, b) \
    asm volatile("mbarrier.arrive.expect_tx.shared.b64 _, [%0], %1;" :: "r"((uint32_t)(m)), "r"((uint32_t)(b)) : "memory")
#define MBARRIER_ARRIVE(m) \
    asm volatile("mbarrier.arrive.shared.b64 _, [%0];" :: "r"((uint32_t)(m)) : "memory")
#define MBARRIER_WAIT_PARITY(m, par) do { \
    uint32_t _m=(uint32_t)(m), _p=(uint32_t)(par), _d; \
    asm volatile("{\n\t.reg .pred p;\n\tmbarrier.try_wait.parity.acquire.cta.shared::cta.b64 p, [%1], %2;\n\tselp.b32 %0,1,0,p;\n\t}" \
        : "=r"(_d) : "r"(_m), "r"(_p) : "memory"); \
    if (!_d) { \
        asm volatile("{\n\t.reg .pred P1;\n\tWL_%=:\n\tmbarrier.try_wait.parity.acquire.cta.shared::cta.b64 P1, [%0], %1, 0x989680;\n\t@P1 bra.uni WD_%=;\n\tbra.uni WL_%=;\n\tWD_%=:\n\t}" \
            :: "r"(_m), "r"(_p) : "memory"); \
    } \
} while(0)
__device__ __forceinline__ void bulk_g2s(uint32_t dst, const void* src, uint32_t bytes, uint32_t mbar){
    asm volatile("cp.async.bulk.shared::cluster.global.mbarrier::complete_tx::bytes [%0], [%1], %2, [%3];"
        :: "r"(dst), "l"(src), "r"(bytes), "r"(mbar) : "memory");
}
__device__ __forceinline__ void ldsm4(uint32_t* r, uint32_t addr){
    asm volatile("ldmatrix.sync.aligned.m8n8.x4.shared.b16 {%0,%1,%2,%3}, [%4];"
        : "=r"(r[0]),"=r"(r[1]),"=r"(r[2]),"=r"(r[3]) : "r"(addr));
}
__device__ __forceinline__ void mma_bf16(float* d, const uint32_t* a, const uint32_t* b){
    asm volatile("mma.sync.aligned.m16n8k16.row.col.f32.bf16.bf16.f32 "
        "{%0,%1,%2,%3}, {%4,%5,%6,%7}, {%8,%9}, {%0,%1,%2,%3};"
        : "+f"(d[0]),"+f"(d[1]),"+f"(d[2]),"+f"(d[3])
        : "r"(a[0]),"r"(a[1]),"r"(a[2]),"r"(a[3]), "r"(b[0]),"r"(b[1]));
}

// ===================== chunk-packed layout =====================
// Matrix [Rows, K] K-major stored as blocks: blk = row/128, chunk kcI = k/32.
// element index = ((blk*2+pl)*KC + kcI)*4096 + (((k>>3)&3)*128 + (row&127))*8 + (k&7)
__device__ __forceinline__ long cidx(int KC, int pl, int blk, int r, int k){
    return (((long)(blk*2 + pl)*KC + (k>>5)) << 12) + ((((k>>3)&3)*128 + r) << 3) + (k&7);
}

// ===================== device globals =====================
__device__ __align__(256) __nv_bfloat16 g_hS [2*(size_t)BS*Dd];
__device__ __align__(256) __nv_bfloat16 g_qS [2*(size_t)BS*Dd];
__device__ __align__(256) __nv_bfloat16 g_kS [2*(size_t)BS*Dd];
__device__ __align__(256) __nv_bfloat16 g_vT [2*(size_t)BS*Dd];   // per b: [D rows][Ss] chunked
__device__ __align__(256) __nv_bfloat16 g_tS [2*(size_t)BS*Dd];
__device__ __align__(256) __nv_bfloat16 g_pqS[2*(size_t)BS*Pp];
__device__ __align__(256) __nv_bfloat16 g_pkT[2*(size_t)BS*Pp];   // per b: [P rows][Ss] chunked
__device__ __align__(256) __nv_bfloat16 g_mS [2*(size_t)BS*DFf];
__device__ __align__(256) __nv_bfloat16 g_kvtS[(size_t)Bb*2*Dd*Pp]; // per b: [D rows][P] chunked
__device__ __align__(256) __nv_bfloat16 g_wq[(size_t)Ll*2*Dd*Dd];
__device__ __align__(256) __nv_bfloat16 g_wk[(size_t)Ll*2*Dd*Dd];
__device__ __align__(256) __nv_bfloat16 g_wv[(size_t)Ll*2*Dd*Dd];
__device__ __align__(256) __nv_bfloat16 g_wo[(size_t)Ll*2*Dd*Dd];
__device__ __align__(256) __nv_bfloat16 g_wf[(size_t)Ll*2*Pp*Dd];
__device__ __align__(256) __nv_bfloat16 g_w1[(size_t)Ll*2*DFf*Dd];
__device__ __align__(256) __nv_bfloat16 g_w2[(size_t)Ll*2*Dd*DFf];
__device__ float g_kvp[(size_t)Bb*KVS*Pp*Dd];
__device__ float g_ks [Bb*Pp];
__device__ float g_z  [BS];
__device__ float g_pp [Bb*32*Dd];
__device__ float g_pool[Bb*Dd];
__device__ float g_h1 [Bb*DHh];

__device__ __forceinline__ float gelu_tanh(float x){
    float u = 0.7978845608028654f*(x + 0.044715f*x*x*x);
    return 0.5f*x*(1.0f + tanhf(u));
}

// ===================== bulk-pipelined split-bf16 HMMA GEMM =====================
// Stage covers K=64 (2 layout-chunks/plane): [Ah 16K][Al 16K][Bh 16K][Bl 16K] = 64KB.
#define NSTG 3
#define STGB 65536
#define SMEMG (1024 + NSTG*STGB)

template<int EPI, int TOUT>  // EPI 0:+bias 1:+bias,elu+1 2:+bias,gelu 3:*1/(aux+eps); TOUT 0:chunked [M,N], 1:transposed chunked [N rows][Ss]
__global__ void __launch_bounds__(256)
gemm_mma(const __nv_bfloat16* __restrict__ A, int KCa,
         const __nv_bfloat16* __restrict__ Bw, int KCb, long b_batch,
         const float* __restrict__ bias, const float* __restrict__ aux,
         __nv_bfloat16* __restrict__ C, int N, int K)
{
    extern __shared__ __align__(1024) char smem[];
    const uint32_t sb = smem_to_u32(smem);
    const int tid = threadIdx.x, wid = tid >> 5, lane = tid & 31;
    const int rowblk = blockIdx.z*gridDim.y + blockIdx.y;
    const int nblk = blockIdx.x;
    const int row0 = rowblk*128, col0 = nblk*128;
    const int niter = K >> 6;
    const uint32_t FULL0 = sb, EMPTY0 = sb + 32;
    const uint32_t STG0 = sb + 1024;
    const __nv_bfloat16* Bt = Bw + (long)blockIdx.z*b_batch;

    if (tid == 0){
        #pragma unroll
        for (int s = 0; s < NSTG; ++s){ MBARRIER_INIT(FULL0+8*s, 1); MBARRIER_INIT(EMPTY0+8*s, 256); }
    }
    __syncthreads();

    auto issue = [&](int j){
        const int s = j % NSTG;
        if (j >= NSTG) MBARRIER_WAIT_PARITY(EMPTY0+8*s, ((j/NSTG)-1)&1);
        MBARRIER_EXPECT_TX(FULL0+8*s, 65536u);
        const uint32_t dst = STG0 + s*STGB;
        #pragma unroll
        for (int pl = 0; pl < 2; ++pl){
            bulk_g2s(dst + pl*16384,
                     A  + (((long)(rowblk*2+pl)*KCa + j*2) << 12), 16384u, FULL0+8*s);
            bulk_g2s(dst + 32768 + pl*16384,
                     Bt + (((long)(nblk*2+pl)*KCb + j*2) << 12), 16384u, FULL0+8*s);
        }
    };
    if (tid == 0){
        const int pro = (niter < NSTG-1) ? niter : NSTG-1;
        for (int j = 0; j < pro; ++j) issue(j);
    }

    float acc[2][8][4];
    #pragma unroll
    for (int mt=0;mt<2;mt++)
        #pragma unroll
        for (int ni=0;ni<8;ni++)
            #pragma unroll
            for (int r=0;r<4;r++) acc[mt][ni][r]=0.f;

    const int wm = (wid >> 1)*32, wn = (wid & 1)*64;
    const int a_mrow = wm + ((lane>>3)&1)*8 + (lane&7);
    const int a_kc   = (lane>>4);
    const int b_nrow = wn + ((lane>>4)&1)*8 + (lane&7);
    const int b_kc   = ((lane>>3)&1);

    for (int it = 0; it < niter; ++it){
        const int s = it % NSTG;
        if (tid == 0 && it + NSTG-1 < niter) issue(it + NSTG-1);
        MBARRIER_WAIT_PARITY(FULL0+8*s, (it/NSTG)&1);
        const uint32_t stg = STG0 + s*STGB;
        #pragma unroll
        for (int step = 0; step < 4; ++step){
            const int ga = a_kc + 2*step, gb = b_kc + 2*step;
            uint32_t ah[2][4], al[2][4];
            #pragma unroll
            for (int mt = 0; mt < 2; ++mt){
                const uint32_t aoff = stg + (uint32_t)((ga>>2)*8192 + (((ga&3)*128) + a_mrow + mt*16)*16);
                ldsm4(ah[mt], aoff);
                ldsm4(al[mt], aoff + 16384);
            }
            #pragma unroll
            for (int nt4 = 0; nt4 < 4; ++nt4){
                const uint32_t boff = stg + 32768 + (uint32_t)((gb>>2)*8192 + (((gb&3)*128) + b_nrow + nt4*16)*16);
                uint32_t bh[4], bl[4];
                ldsm4(bh, boff);
                ldsm4(bl, boff + 16384);
                #pragma unroll
                for (int mt = 0; mt < 2; ++mt){
                    mma_bf16(acc[mt][2*nt4  ], ah[mt], bh);
                    mma_bf16(acc[mt][2*nt4+1], ah[mt], bh+2);
                    mma_bf16(acc[mt][2*nt4  ], al[mt], bh);
                    mma_bf16(acc[mt][2*nt4+1], al[mt], bh+2);
                    mma_bf16(acc[mt][2*nt4  ], ah[mt], bl);
                    mma_bf16(acc[mt][2*nt4+1], ah[mt], bl+2);
                }
            }
        }
        MBARRIER_ARRIVE(EMPTY0+8*s);
    }

    // ---- epilogue ----
    float bv0[8], bv1[8];
    if (EPI != 3){
        #pragma unroll
        for (int ni = 0; ni < 8; ++ni){
            const int col = col0 + wn + ni*8 + (lane&3)*2;
            bv0[ni] = bias[col]; bv1[ni] = bias[col+1];
        }
    }
    const int KCo = N >> 5;
    #pragma unroll
    for (int mt = 0; mt < 2; ++mt){
        #pragma unroll
        for (int h = 0; h < 2; ++h){
            const long row = row0 + wm + mt*16 + h*8 + (lane>>2);
            float sc = 1.f;
            if (EPI == 3) sc = 1.f/(aux[row] + 1e-6f);
            const int r = (int)(row & 127);
            const int bt = (int)(row >> 12), st = (int)(row & (Ss-1));
            __nv_bfloat16* tB = (TOUT==1) ? (C + (long)bt*2*N*(long)Ss) : nullptr;
            #pragma unroll
            for (int ni = 0; ni < 8; ++ni){
                const int col = col0 + wn + ni*8 + (lane&3)*2;
                float c0 = acc[mt][ni][2*h], c1 = acc[mt][ni][2*h+1];
                if (EPI != 3){ c0 += bv0[ni]; c1 += bv1[ni]; }
                if (EPI == 1){ c0 = (c0>0.f)?(c0+1.f):expf(c0); c1 = (c1>0.f)?(c1+1.f):expf(c1); }
                if (EPI == 2){ c0 = gelu_tanh(c0); c1 = gelu_tanh(c1); }
                if (EPI == 3){ c0 *= sc; c1 *= sc; }
                __nv_bfloat16 h0 = __float2bfloat16(c0), h1 = __float2bfloat16(c1);
                __nv_bfloat16 l0 = __float2bfloat16(c0 - __bfloat162float(h0));
                __nv_bfloat16 l1 = __float2bfloat16(c1 - __bfloat162float(h1));
                if (TOUT == 0){
                    __nv_bfloat162 vh; vh.x = h0; vh.y = h1;
                    __nv_bfloat162 vl; vl.x = l0; vl.y = l1;
                    *(__nv_bfloat162*)(C + cidx(KCo, 0, rowblk, r, col)) = vh;
                    *(__nv_bfloat162*)(C + cidx(KCo, 1, rowblk, r, col)) = vl;
                } else {
                    tB[cidx(Ss>>5, 0, col>>7,     col&127,     st)] = h0;
                    tB[cidx(Ss>>5, 0, (col+1)>>7, (col+1)&127, st)] = h1;
                    tB[cidx(Ss>>5, 1, col>>7,     col&127,     st)] = l0;
                    tB[cidx(Ss>>5, 1, (col+1)>>7, (col+1)&127, st)] = l1;
                }
            }
        }
    }
}

// ===================== kv gemm: kv^T[b] = vT[b] @ pkT[b]^T, split-K fp32 partials =====================
__global__ void __launch_bounds__(256)
gemm_kv(const __nv_bfloat16* __restrict__ vT, const __nv_bfloat16* __restrict__ pkT,
        float* __restrict__ part)
{
    extern __shared__ __align__(1024) char smem[];
    const uint32_t sb = smem_to_u32(smem);
    const int tid = threadIdx.x, wid = tid >> 5, lane = tid & 31;
    const int bz = blockIdx.z, b = bz >> 4, sp = bz & (KVS-1);
    const int ablk = blockIdx.y, row0 = ablk*128;
    const int niter = (Ss/KVS) >> 6;   // 4
    const int kchunk0 = sp*((Ss/KVS) >> 5);
    const uint32_t FULL0 = sb, EMPTY0 = sb + 32;
    const uint32_t STG0 = sb + 1024;
    const __nv_bfloat16* A  = vT  + (long)b*2*Dd*Ss;
    const __nv_bfloat16* Bp = pkT + (long)b*2*Pp*Ss;

    if (tid == 0){
        #pragma unroll
        for (int s = 0; s < NSTG; ++s){ MBARRIER_INIT(FULL0+8*s, 1); MBARRIER_INIT(EMPTY0+8*s, 256); }
    }
    __syncthreads();

    auto issue = [&](int j){
        const int s = j % NSTG;
        if (j >= NSTG) MBARRIER_WAIT_PARITY(EMPTY0+8*s, ((j/NSTG)-1)&1);
        MBARRIER_EXPECT_TX(FULL0+8*s, 65536u);
        const uint32_t dst = STG0 + s*STGB;
        #pragma unroll
        for (int pl = 0; pl < 2; ++pl){
            bulk_g2s(dst + pl*16384,
                     A  + (((long)(ablk*2+pl)*(Ss>>5) + kchunk0 + j*2) << 12), 16384u, FULL0+8*s);
            bulk_g2s(dst + 32768 + pl*16384,
                     Bp + (((long)pl*(Ss>>5) + kchunk0 + j*2) << 12), 16384u, FULL0+8*s);
        }
    };
    if (tid == 0){ for (int j = 0; j < NSTG-1; ++j) issue(j); }

    float acc[2][8][4];
    #pragma unroll
    for (int mt=0;mt<2;mt++)
        #pragma unroll
        for (int ni=0;ni<8;ni++)
            #pragma unroll
            for (int r=0;r<4;r++) acc[mt][ni][r]=0.f;

    const int wm = (wid >> 1)*32, wn = (wid & 1)*64;
    const int a_mrow = wm + ((lane>>3)&1)*8 + (lane&7);
    const int a_kc   = (lane>>4);
    const int b_nrow = wn + ((lane>>4)&1)*8 + (lane&7);
    const int b_kc   = ((lane>>3)&1);

    for (int it = 0; it < niter; ++it){
        const int s = it % NSTG;
        if (tid == 0 && it + NSTG-1 < niter) issue(it + NSTG-1);
        MBARRIER_WAIT_PARITY(FULL0+8*s, (it/NSTG)&1);
        const uint32_t stg = STG0 + s*STGB;
        #pragma unroll
        for (int step = 0; step < 4; ++step){
            const int ga = a_kc + 2*step, gb = b_kc + 2*step;
            uint32_t ah[2][4], al[2][4];
            #pragma unroll
            for (int mt = 0; mt < 2; ++mt){
                const uint32_t aoff = stg + (uint32_t)((ga>>2)*8192 + (((ga&3)*128) + a_mrow + mt*16)*16);
                ldsm4(ah[mt], aoff);
                ldsm4(al[mt], aoff + 16384);
            }
            #pragma unroll
            for (int nt4 = 0; nt4 < 4; ++nt4){
                const uint32_t boff = stg + 32768 + (uint32_t)((gb>>2)*8192 + (((gb&3)*128) + b_nrow + nt4*16)*16);
                uint32_t bh[4], bl[4];
                ldsm4(bh, boff);
                ldsm4(bl, boff + 16384);
                #pragma unroll
                for (int mt = 0; mt < 2; ++mt){
                    mma_bf16(acc[mt][2*nt4  ], ah[mt], bh);
                    mma_bf16(acc[mt][2*nt4+1], ah[mt], bh+2);
                    mma_bf16(acc[mt][2*nt4  ], al[mt], bh);
                    mma_bf16(acc[mt][2*nt4+1], al[mt], bh+2);
                    mma_bf16(acc[mt][2*nt4  ], ah[mt], bl);
                    mma_bf16(acc[mt][2*nt4+1], ah[mt], bl+2);
                }
            }
        }
        MBARRIER_ARRIVE(EMPTY0+8*s);
    }

    float* Cb = part + (long)bz*Dd*Pp;
    #pragma unroll
    for (int mt = 0; mt < 2; ++mt){
        #pragma unroll
        for (int h = 0; h < 2; ++h){
            const int row = row0 + wm + mt*16 + h*8 + (lane>>2);
            #pragma unroll
            for (int ni = 0; ni < 8; ++ni){
                const int col = wn + ni*8 + (lane&3)*2;
                *(float2*)(Cb + (long)row*Pp + col) =
                    make_float2(acc[mt][ni][2*h], acc[mt][ni][2*h+1]);
            }
        }
    }
}

// reduce partials -> kvtS chunked [D rows][P] per batch
__global__ void reduce_kvt(const float* __restrict__ part, __nv_bfloat16* __restrict__ kvt)
{
    long i = (long)blockIdx.x*256 + threadIdx.x;   // over Bb*Dd*Pp
    int b = (int)(i / (Dd*Pp)); int r0 = (int)(i % (Dd*Pp));
    int d = r0 >> 7, p = r0 & 127;
    const float* q = part + ((long)b*KVS)*Dd*Pp + r0;
    float s = 0.f;
    #pragma unroll
    for (int j = 0; j < KVS; j++) s += q[(long)j*Dd*Pp];
    __nv_bfloat16 h = __float2bfloat16(s);
    __nv_bfloat16* base = kvt + (long)b*2*Dd*Pp;
    base[cidx(4, 0, d>>7, d&127, p)] = h;
    base[cidx(4, 1, d>>7, d&127, p)] = __float2bfloat16(s - __bfloat162float(h));
}

// ===================== weight conversion: fp32 [L][K,N] -> chunked split [L][N rows][K] =====================
__global__ void wconv(const float* __restrict__ W, __nv_bfloat16* __restrict__ out, int K, int N)
{
    __shared__ float t[32][33];
    const int n0 = blockIdx.x*32, k0 = blockIdx.y*32, l = blockIdx.z;
    const float* Wl = W + (long)l*K*N;
    __nv_bfloat16* ob = out + (long)l*2*N*K;
    const int KC = K >> 5;
    for (int i = threadIdx.y; i < 32; i += 8)
        t[i][threadIdx.x] = Wl[(long)(k0+i)*N + n0 + threadIdx.x];
    __syncthreads();
    for (int i = threadIdx.y; i < 32; i += 8) {
        float v = t[threadIdx.x][i];
        const int n = n0 + i, k = k0 + threadIdx.x;
        __nv_bfloat16 h = __float2bfloat16(v);
        ob[cidx(KC, 0, n>>7, n&127, k)] = h;
        ob[cidx(KC, 1, n>>7, n&127, k)] = __float2bfloat16(v - __bfloat162float(h));
    }
}

// ksum[b,p] = sum_s pkT(hi+lo), chunked read, deterministic tree
__global__ void ksum_kernel(const __nv_bfloat16* __restrict__ pkT, float* __restrict__ ks)
{
    const int p = blockIdx.x, b = blockIdx.y, t = threadIdx.x;
    const __nv_bfloat16* base = pkT + (long)b*2*Pp*Ss;
    float s = 0.f;
    for (int o = t; o < 512; o += 256){        // octet index: kcI=o>>2, kc8=o&3
        #pragma unroll
        for (int pl = 0; pl < 2; ++pl){
            long e = (((long)(pl*(Ss>>5)) + (o>>2)) << 12) + (((o&3)*128 + p) << 3);
            uint4 v = *(const uint4*)(base + e);
            const __nv_bfloat162* pv = (const __nv_bfloat162*)&v;
            #pragma unroll
            for (int q = 0; q < 4; ++q)
                s += __bfloat162float(pv[q].x) + __bfloat162float(pv[q].y);
        }
    }
    __shared__ float sh[256];
    sh[t] = s; __syncthreads();
    #pragma unroll
    for (int o = 128; o > 0; o >>= 1){
        if (t < o) sh[t] += sh[t+o];
        __syncthreads();
    }
    if (!t) ks[b*Pp + p] = sh[0];
}

// z[b,s] = dot(pq(hi+lo), ksum)
__global__ void z_kernel(const __nv_bfloat16* __restrict__ pq, const float* __restrict__ ksum,
                         float* __restrict__ z)
{
    int gw = (int)((blockIdx.x*(long)blockDim.x + threadIdx.x) >> 5);
    int lane = threadIdx.x & 31;
    if (gw >= BS) return;
    const int b = gw >> 12, blk = gw >> 7, r = gw & 127;
    const float* kr = ksum + b*Pp;
    const int p0 = lane*4;
    float s = 0.f;
    #pragma unroll
    for (int pl = 0; pl < 2; ++pl){
        long e = (((long)(blk*2+pl)*4 + (p0>>5)) << 12) + ((((p0>>3)&3)*128 + r) << 3) + (p0&7);
        uint2 v = *(const uint2*)(pq + e);
        const __nv_bfloat162* pv = (const __nv_bfloat162*)&v;
        s = fmaf(__bfloat162float(pv[0].x), kr[p0],   s);
        s = fmaf(__bfloat162float(pv[0].y), kr[p0+1], s);
        s = fmaf(__bfloat162float(pv[1].x), kr[p0+2], s);
        s = fmaf(__bfloat162float(pv[1].y), kr[p0+3], s);
    }
    #pragma unroll
    for (int o = 16; o; o >>= 1) s += __shfl_xor_sync(0xffffffffu, s, o);
    if (!lane) z[gw] = s;
}

// layernorm on chunked split data
__global__ void ln_kernel(const __nv_bfloat16* __restrict__ in, const float* __restrict__ g,
                          const float* __restrict__ bta, __nv_bfloat16* __restrict__ out)
{
    const int row = blockIdx.x, t = threadIdx.x;
    const int blk = row >> 7, r = row & 127, d = 2*t;
    const long eh = cidx(16, 0, blk, r, d);
    const long el = cidx(16, 1, blk, r, d);
    __nv_bfloat162 h2 = *(const __nv_bfloat162*)(in + eh);
    __nv_bfloat162 l2 = *(const __nv_bfloat162*)(in + el);
    float vx = __bfloat162float(h2.x) + __bfloat162float(l2.x);
    float vy = __bfloat162float(h2.y) + __bfloat162float(l2.y);
    float s  = vx + vy, sq = vx*vx + vy*vy;
    #pragma unroll
    for (int o = 16; o; o >>= 1){
        s  += __shfl_xor_sync(0xffffffffu, s,  o);
        sq += __shfl_xor_sync(0xffffffffu, sq, o);
    }
    __shared__ float sh[8], shq[8];
    int w = t >> 5, lane = t & 31;
    if (!lane){ sh[w] = s; shq[w] = sq; }
    __syncthreads();
    float ts = 0.f, tq = 0.f;
    #pragma unroll
    for (int i = 0; i < 8; i++){ ts += sh[i]; tq += shq[i]; }
    float mu = ts*(1.f/Dd);
    float rv = rsqrtf(tq*(1.f/Dd) - mu*mu + 1e-5f);
    float ox = (vx-mu)*rv*g[d]   + bta[d];
    float oy = (vy-mu)*rv*g[d+1] + bta[d+1];
    __nv_bfloat16 hx = __float2bfloat16(ox), hy = __float2bfloat16(oy);
    __nv_bfloat162 oh; oh.x = hx; oh.y = hy;
    __nv_bfloat162 ol;
    ol.x = __float2bfloat16(ox - __bfloat162float(hx));
    ol.y = __float2bfloat16(oy - __bfloat162float(hy));
    *(__nv_bfloat162*)(out + eh) = oh;
    *(__nv_bfloat162*)(out + el) = ol;
}

__global__ void embed_kernel(const int* __restrict__ x, const float* __restrict__ emb,
                             const float* __restrict__ pos, __nv_bfloat16* __restrict__ h)
{
    const int token = blockIdx.x, t = threadIdx.x;
    const int s = token & (Ss-1), id = x[token];
    const int blk = token >> 7, r = token & 127, d = 2*t;
    float2 e = *(const float2*)(emb + (long)id*Dd + d);
    float2 p = *(const float2*)(pos + (long)s*Dd + d);
    float vx = e.x + p.x, vy = e.y + p.y;
    __nv_bfloat16 hx = __float2bfloat16(vx), hy = __float2bfloat16(vy);
    __nv_bfloat162 oh; oh.x = hx; oh.y = hy;
    __nv_bfloat162 ol;
    ol.x = __float2bfloat16(vx - __bfloat162float(hx));
    ol.y = __float2bfloat16(vy - __bfloat162float(hy));
    *(__nv_bfloat162*)(h + cidx(16, 0, blk, r, d)) = oh;
    *(__nv_bfloat162*)(h + cidx(16, 1, blk, r, d)) = ol;
}

// partial col sums of hS (chunked) for mean pool
__global__ void colsum_part(const __nv_bfloat16* __restrict__ in, float* __restrict__ part)
{
    const int b = blockIdx.y, ch = blockIdx.x, c = threadIdx.x;  // 512 threads
    const int blkg = b*32 + ch;
    float s = 0.f;
    #pragma unroll
    for (int pl = 0; pl < 2; ++pl){
        long base = (((long)(blkg*2+pl)*16 + (c>>5)) << 12) + (((c>>3)&3)*128 << 3) + (c&7);
        #pragma unroll 4
        for (int i = 0; i < 128; ++i)
            s += __bfloat162float(in[base + i*8]);
    }
    part[((long)b*32 + ch)*Dd + c] = s;
}
__global__ void colsum_fin(const float* __restrict__ part, float* __restrict__ out,
                           int cols, int chunks, float scale)
{
    int b = blockIdx.x, c = threadIdx.x;
    float s = 0.f;
    for (int ch = 0; ch < chunks; ch++) s += part[((long)b*chunks+ch)*cols + c];
    out[(long)b*cols + c] = s*scale;
}

__global__ void head1_kernel(const float* __restrict__ pool, const float* __restrict__ Wh1,
                             const float* __restrict__ bh1, float* __restrict__ h1)
{
    int b = blockIdx.x;
    __shared__ float xr[Dd];
    for (int i = threadIdx.x; i < Dd; i += blockDim.x) xr[i] = pool[(long)b*Dd + i];
    __syncthreads();
    int t = threadIdx.x;
    float s = bh1[t];
    #pragma unroll 4
    for (int k = 0; k < Dd; k++) s = fmaf(xr[k], Wh1[(long)k*DHh + t], s);
    h1[(long)b*DHh + t] = fmaxf(s, 0.f);
}
__global__ void head2_kernel(const float* __restrict__ h1, const float* __restrict__ Wh2,
                             const float* __restrict__ bh2, float* __restrict__ out)
{
    int t = threadIdx.x;
    if (t < Bb*CC){
        int b = t / CC, c = t % CC;
        float s = bh2[c];
        #pragma unroll 4
        for (int k = 0; k < DHh; k++) s = fmaf(h1[(long)b*DHh + k], Wh2[(long)k*CC + c], s);
        out[t] = s;
    }
}

// ===================== launch =====================
extern "C" void kernel_launch(void* const* d_in, const int* in_sizes, int n_in,
                              void* d_out, int out_size)
{
    const int*   x   = (const int*)  d_in[0];
    const float* emb = (const float*)d_in[1];
    const float* pos = (const float*)d_in[2];
    const float* Wq  = (const float*)d_in[3];   const float* bq = (const float*)d_in[4];
    const float* Wk  = (const float*)d_in[5];   const float* bk = (const float*)d_in[6];
    const float* Wv  = (const float*)d_in[7];   const float* bv = (const float*)d_in[8];
    const float* Wf  = (const float*)d_in[9];   const float* bf = (const float*)d_in[10];
    const float* Wo  = (const float*)d_in[11];  const float* bo = (const float*)d_in[12];
    const float* lng = (const float*)d_in[13];  const float* lnb= (const float*)d_in[14];
    const float* W1  = (const float*)d_in[15];  const float* b1 = (const float*)d_in[16];
    const float* W2  = (const float*)d_in[17];  const float* b2 = (const float*)d_in[18];
    const float* Wh1 = (const float*)d_in[19];  const float* bh1= (const float*)d_in[20];
    const float* Wh2 = (const float*)d_in[21];  const float* bh2= (const float*)d_in[22];

    __nv_bfloat16 *hS,*qS,*kS,*vT,*tS,*pqS,*pkT,*mS,*kvtS,*wq,*wk,*wv,*wo,*wf,*w1,*w2;
    float *kvp,*ks,*z,*pp,*pool,*h1;
    cudaGetSymbolAddress((void**)&hS,  g_hS);   cudaGetSymbolAddress((void**)&qS,  g_qS);
    cudaGetSymbolAddress((void**)&kS,  g_kS);   cudaGetSymbolAddress((void**)&vT,  g_vT);
    cudaGetSymbolAddress((void**)&tS,  g_tS);   cudaGetSymbolAddress((void**)&pqS, g_pqS);
    cudaGetSymbolAddress((void**)&pkT, g_pkT);  cudaGetSymbolAddress((void**)&mS,  g_mS);
    cudaGetSymbolAddress((void**)&kvtS,g_kvtS);
    cudaGetSymbolAddress((void**)&wq, g_wq); cudaGetSymbolAddress((void**)&wk, g_wk);
    cudaGetSymbolAddress((void**)&wv, g_wv); cudaGetSymbolAddress((void**)&wo, g_wo);
    cudaGetSymbolAddress((void**)&wf, g_wf); cudaGetSymbolAddress((void**)&w1, g_w1);
    cudaGetSymbolAddress((void**)&w2, g_w2);
    cudaGetSymbolAddress((void**)&kvp, g_kvp);
    cudaGetSymbolAddress((void**)&ks,  g_ks);  cudaGetSymbolAddress((void**)&z,   g_z);
    cudaGetSymbolAddress((void**)&pp,  g_pp);  cudaGetSymbolAddress((void**)&pool,g_pool);
    cudaGetSymbolAddress((void**)&h1,  g_h1);

    cudaFuncSetAttribute(gemm_mma<0,0>, cudaFuncAttributeMaxDynamicSharedMemorySize, SMEMG);
    cudaFuncSetAttribute(gemm_mma<0,1>, cudaFuncAttributeMaxDynamicSharedMemorySize, SMEMG);
    cudaFuncSetAttribute(gemm_mma<1,0>, cudaFuncAttributeMaxDynamicSharedMemorySize, SMEMG);
    cudaFuncSetAttribute(gemm_mma<1,1>, cudaFuncAttributeMaxDynamicSharedMemorySize, SMEMG);
    cudaFuncSetAttribute(gemm_mma<2,0>, cudaFuncAttributeMaxDynamicSharedMemorySize, SMEMG);
    cudaFuncSetAttribute(gemm_mma<3,0>, cudaFuncAttributeMaxDynamicSharedMemorySize, SMEMG);
    cudaFuncSetAttribute(gemm_kv,       cudaFuncAttributeMaxDynamicSharedMemorySize, SMEMG);

    dim3 wt(32, 8);
    const dim3 gDD(Dd/128, BS/128, 1);
    const dim3 gDP(1,      BS/128, 1);
    const dim3 gDF(DFf/128,BS/128, 1);
    const dim3 gAT(Dd/128, Ss/128, Bb);
    const dim3 gKV(1, Dd/128, Bb*KVS);
    const long wDD = (long)2*Dd*Dd, wDP = (long)2*Pp*Dd, wDF = (long)2*DFf*Dd;

    // launch order: embed(0), 4x wconv(1-4), first gemm at index 5 (ncu -s 5 captures it)
    embed_kernel<<<BS,256>>>(x, emb, pos, hS);
    wconv<<<dim3(Dd/32,  Dd/32,  Ll), wt>>>(Wq, wq, Dd, Dd);
    wconv<<<dim3(Dd/32,  Dd/32,  Ll), wt>>>(Wk, wk, Dd, Dd);
    wconv<<<dim3(Dd/32,  Dd/32,  Ll), wt>>>(Wv, wv, Dd, Dd);
    wconv<<<dim3(Pp/32,  Dd/32,  Ll), wt>>>(Wf, wf, Dd, Pp);

    for (int l = 0; l < Ll; l++){
        gemm_mma<0,0><<<gDD,256,SMEMG>>>(hS, 16, wq + l*wDD, 16, 0, bq + l*Dd, nullptr, qS, Dd, Dd);
        gemm_mma<0,0><<<gDD,256,SMEMG>>>(hS, 16, wk + l*wDD, 16, 0, bk + l*Dd, nullptr, kS, Dd, Dd);
        gemm_mma<0,1><<<gDD,256,SMEMG>>>(hS, 16, wv + l*wDD, 16, 0, bv + l*Dd, nullptr, vT, Dd, Dd);
        if (l == 0){
            wconv<<<dim3(Dd/32,  Dd/32,  Ll), wt>>>(Wo, wo, Dd, Dd);
            wconv<<<dim3(DFf/32, Dd/32,  Ll), wt>>>(W1, w1, Dd, DFf);
            wconv<<<dim3(Dd/32,  DFf/32, Ll), wt>>>(W2, w2, DFf, Dd);
        }
        gemm_mma<1,0><<<gDP,256,SMEMG>>>(qS, 16, wf + l*wDP, 16, 0, bf + l*Pp, nullptr, pqS, Pp, Dd);
        gemm_mma<1,1><<<gDP,256,SMEMG>>>(kS, 16, wf + l*wDP, 16, 0, bf + l*Pp, nullptr, pkT, Pp, Dd);
        ksum_kernel<<<dim3(Pp,Bb),256>>>(pkT, ks);
        gemm_kv<<<gKV,256,SMEMG>>>(vT, pkT, kvp);
        reduce_kvt<<<(Bb*Dd*Pp)/256,256>>>(kvp, kvtS);
        z_kernel<<<BS/8,256>>>(pqS, ks, z);
        gemm_mma<3,0><<<gAT,256,SMEMG>>>(pqS, 4, kvtS, 4, (long)2*Dd*Pp, nullptr, z, tS, Dd, Pp);
        gemm_mma<0,0><<<gDD,256,SMEMG>>>(tS, 16, wo + l*wDD, 16, 0, bo + l*Dd, nullptr, qS, Dd, Dd);
        ln_kernel<<<BS,256>>>(qS, lng + l*Dd, lnb + l*Dd, tS);
        gemm_mma<2,0><<<gDF,256,SMEMG>>>(tS, 16, w1 + l*wDF, 16, 0, b1 + l*DFf, nullptr, mS, DFf, Dd);
        gemm_mma<0,0><<<gDD,256,SMEMG>>>(mS, 64, w2 + l*wDF, 64, 0, b2 + l*Dd, nullptr, hS, Dd, DFf);
    }

    colsum_part<<<dim3(32,Bb),Dd>>>(hS, pp);
    colsum_fin <<<Bb,Dd>>>(pp, pool, Dd, 32, 1.0f/Ss);
    head1_kernel<<<Bb,DHh>>>(pool, Wh1, bh1, h1);
    head2_kernel<<<1,32>>>(h1, Wh2, bh2, (float*)d_out);
}

// round 7
// speedup vs baseline: 3.7627x; 1.1401x over previous
#include <cuda_runtime.h>
#include <cuda_bf16.h>
#include <math.h>
#include <stdint.h>

#define Bb  8
#define Ss  4096
#define Dd  512
#define Pp  128
#define Ll  4
#define DFf 2048
#define DHh 256
#define CC  2
#define BS  (Bb*Ss)
#define KVS 16

// ===================== PTX helpers (sm_90 core features only) =====================
__device__ __forceinline__ uint32_t smem_to_u32(const void* p) {
    uint32_t a;
    asm("{ .reg .u64 t; cvta.to.shared.u64 t, %1; cvt.u32.u64 %0, t; }" : "=r"(a) : "l"(p));
    return a;
}
#define MBARRIER_INIT(m, c) \
    asm volatile("mbarrier.init.shared.b64 [%0], %1;" :: "r"((uint32_t)(m)), "r"((uint32_t)(c)) : "memory")
#define MBARRIER_EXPECT_TX(m, b) \
    asm volatile("mbarrier.arrive.expect_tx.shared.b64 _, [%0], %1;" :: "r"((uint32_t)(m)), "r"((uint32_t)(b)) : "memory")
#define MBARRIER_ARRIVE(m) \
    asm volatile("mbarrier.arrive.shared.b64 _, [%0];" :: "r"((uint32_t)(m)) : "memory")
#define MBARRIER_WAIT_PARITY(m, par) do { \
    uint32_t _m=(uint32_t)(m), _p=(uint32_t)(par), _d; \
    asm volatile("{\n\t.reg .pred p;\n\tmbarrier.try_wait.parity.acquire.cta.shared::cta.b64 p, [%1], %2;\n\tselp.b32 %0,1,0,p;\n\t}" \
        : "=r"(_d) : "r"(_m), "r"(_p) : "memory"); \
    if (!_d) { \
        asm volatile("{\n\t.reg .pred P1;\n\tWL_%=:\n\tmbarrier.try_wait.parity.acquire.cta.shared::cta.b64 P1, [%0], %1, 0x989680;\n\t@P1 bra.uni WD_%=;\n\tbra.uni WL_%=;\n\tWD_%=:\n\t}" \
            :: "r"(_m), "r"(_p) : "memory"); \
    } \
} while(0)
__device__ __forceinline__ void bulk_g2s(uint32_t dst, const void* src, uint32_t bytes, uint32_t mbar){
    asm volatile("cp.async.bulk.shared::cluster.global.mbarrier::complete_tx::bytes [%0], [%1], %2, [%3];"
        :: "r"(dst), "l"(src), "r"(bytes), "r"(mbar) : "memory");
}
__device__ __forceinline__ void ldsm4(uint32_t* r, uint32_t addr){
    asm volatile("ldmatrix.sync.aligned.m8n8.x4.shared.b16 {%0,%1,%2,%3}, [%4];"
        : "=r"(r[0]),"=r"(r[1]),"=r"(r[2]),"=r"(r[3]) : "r"(addr));
}
__device__ __forceinline__ void mma_bf16(float* d, const uint32_t* a, const uint32_t* b){
    asm volatile("mma.sync.aligned.m16n8k16.row.col.f32.bf16.bf16.f32 "
        "{%0,%1,%2,%3}, {%4,%5,%6,%7}, {%8,%9}, {%0,%1,%2,%3};"
        : "+f"(d[0]),"+f"(d[1]),"+f"(d[2]),"+f"(d[3])
        : "r"(a[0]),"r"(a[1]),"r"(a[2]),"r"(a[3]), "r"(b[0]),"r"(b[1]));
}

// ===================== chunk-packed layout =====================
// Matrix [Rows, K] K-major: blk = row/128, chunk = k/32.
// elem = ((blk*2+pl)*KC + k/32)*4096 + (((k>>3)&3)*128 + (row&127))*8 + (k&7)
__device__ __forceinline__ long cidx(int KC, int pl, int blk, int r, int k){
    return (((long)(blk*2 + pl)*KC + (k>>5)) << 12) + ((((k>>3)&3)*128 + r) << 3) + (k&7);
}

// ===================== device globals =====================
__device__ __align__(256) __nv_bfloat16 g_hS [2*(size_t)BS*Dd];
__device__ __align__(256) __nv_bfloat16 g_qS [2*(size_t)BS*Dd];
__device__ __align__(256) __nv_bfloat16 g_vT [2*(size_t)BS*Dd];   // per b: [D rows][Ss] chunked
__device__ __align__(256) __nv_bfloat16 g_tS [2*(size_t)BS*Dd];
__device__ __align__(256) __nv_bfloat16 g_pqS[2*(size_t)BS*Pp];
__device__ __align__(256) __nv_bfloat16 g_pkT[2*(size_t)BS*Pp];   // per b: [P rows][Ss] chunked
__device__ __align__(256) __nv_bfloat16 g_mS [2*(size_t)BS*DFf];
__device__ __align__(256) __nv_bfloat16 g_kvtS[(size_t)Bb*2*Dd*Pp]; // per b: [D rows][P] chunked
__device__ __align__(256) __nv_bfloat16 g_wv[(size_t)Ll*2*Dd*Dd];
__device__ __align__(256) __nv_bfloat16 g_wo[(size_t)Ll*2*Dd*Dd];
__device__ __align__(256) __nv_bfloat16 g_w1[(size_t)Ll*2*DFf*Dd];
__device__ __align__(256) __nv_bfloat16 g_w2[(size_t)Ll*2*Dd*DFf];
__device__ __align__(256) __nv_bfloat16 g_wqf[(size_t)Ll*2*Pp*Dd];  // folded Wq@Wf, chunked [P rows][Dd]
__device__ __align__(256) __nv_bfloat16 g_wkf[(size_t)Ll*2*Pp*Dd];
__device__ float g_bqf[Ll*Pp];
__device__ float g_bkf[Ll*Pp];
__device__ float g_kvp[(size_t)Bb*KVS*Pp*Dd];
__device__ float g_ks [Bb*Pp];
__device__ float g_z  [BS];
__device__ float g_pp [Bb*32*Dd];
__device__ float g_pool[Bb*Dd];
__device__ float g_h1 [Bb*DHh];

__device__ __forceinline__ float gelu_tanh(float x){
    float u = 0.7978845608028654f*(x + 0.044715f*x*x*x);
    return 0.5f*x*(1.0f + tanhf(u));
}

// ===================== bulk-pipelined split-bf16 HMMA GEMM =====================
#define NSTG 3
#define STGB 65536
#define SMEMG (1024 + NSTG*STGB)

template<int EPI, int TOUT>  // EPI 0:+bias 1:+bias,elu+1 2:+bias,gelu 3:*1/(aux+eps); TOUT 0:chunked [M,N], 1:transposed chunked [N rows][Ss]
__global__ void __launch_bounds__(256)
gemm_mma(const __nv_bfloat16* __restrict__ A, int KCa,
         const __nv_bfloat16* __restrict__ Bw, int KCb, long b_batch,
         const float* __restrict__ bias, const float* __restrict__ aux,
         __nv_bfloat16* __restrict__ C, int N, int K)
{
    extern __shared__ __align__(1024) char smem[];
    const uint32_t sb = smem_to_u32(smem);
    const int tid = threadIdx.x, wid = tid >> 5, lane = tid & 31;
    const int rowblk = blockIdx.z*gridDim.y + blockIdx.y;
    const int nblk = blockIdx.x;
    const int row0 = rowblk*128, col0 = nblk*128;
    const int niter = K >> 6;
    const uint32_t FULL0 = sb, EMPTY0 = sb + 32;
    const uint32_t STG0 = sb + 1024;
    const __nv_bfloat16* Bt = Bw + (long)blockIdx.z*b_batch;

    if (tid == 0){
        #pragma unroll
        for (int s = 0; s < NSTG; ++s){ MBARRIER_INIT(FULL0+8*s, 1); MBARRIER_INIT(EMPTY0+8*s, 256); }
    }
    __syncthreads();

    auto issue = [&](int j){
        const int s = j % NSTG;
        if (j >= NSTG) MBARRIER_WAIT_PARITY(EMPTY0+8*s, ((j/NSTG)-1)&1);
        MBARRIER_EXPECT_TX(FULL0+8*s, 65536u);
        const uint32_t dst = STG0 + s*STGB;
        #pragma unroll
        for (int pl = 0; pl < 2; ++pl){
            bulk_g2s(dst + pl*16384,
                     A  + (((long)(rowblk*2+pl)*KCa + j*2) << 12), 16384u, FULL0+8*s);
            bulk_g2s(dst + 32768 + pl*16384,
                     Bt + (((long)(nblk*2+pl)*KCb + j*2) << 12), 16384u, FULL0+8*s);
        }
    };
    if (tid == 0){
        const int pro = (niter < NSTG-1) ? niter : NSTG-1;
        for (int j = 0; j < pro; ++j) issue(j);
    }

    float acc[2][8][4];
    #pragma unroll
    for (int mt=0;mt<2;mt++)
        #pragma unroll
        for (int ni=0;ni<8;ni++)
            #pragma unroll
            for (int r=0;r<4;r++) acc[mt][ni][r]=0.f;

    const int wm = (wid >> 1)*32, wn = (wid & 1)*64;
    const int a_mrow = wm + ((lane>>3)&1)*8 + (lane&7);
    const int a_kc   = (lane>>4);
    const int b_nrow = wn + ((lane>>4)&1)*8 + (lane&7);
    const int b_kc   = ((lane>>3)&1);

    for (int it = 0; it < niter; ++it){
        const int s = it % NSTG;
        if (tid == 0 && it + NSTG-1 < niter) issue(it + NSTG-1);
        MBARRIER_WAIT_PARITY(FULL0+8*s, (it/NSTG)&1);
        const uint32_t stg = STG0 + s*STGB;
        #pragma unroll
        for (int step = 0; step < 4; ++step){
            const int ga = a_kc + 2*step, gb = b_kc + 2*step;
            uint32_t ah[2][4], al[2][4];
            #pragma unroll
            for (int mt = 0; mt < 2; ++mt){
                const uint32_t aoff = stg + (uint32_t)((ga>>2)*8192 + (((ga&3)*128) + a_mrow + mt*16)*16);
                ldsm4(ah[mt], aoff);
                ldsm4(al[mt], aoff + 16384);
            }
            #pragma unroll
            for (int nt4 = 0; nt4 < 4; ++nt4){
                const uint32_t boff = stg + 32768 + (uint32_t)((gb>>2)*8192 + (((gb&3)*128) + b_nrow + nt4*16)*16);
                uint32_t bh[4], bl[4];
                ldsm4(bh, boff);
                ldsm4(bl, boff + 16384);
                #pragma unroll
                for (int mt = 0; mt < 2; ++mt){
                    mma_bf16(acc[mt][2*nt4  ], ah[mt], bh);
                    mma_bf16(acc[mt][2*nt4+1], ah[mt], bh+2);
                    mma_bf16(acc[mt][2*nt4  ], al[mt], bh);
                    mma_bf16(acc[mt][2*nt4+1], al[mt], bh+2);
                    mma_bf16(acc[mt][2*nt4  ], ah[mt], bl);
                    mma_bf16(acc[mt][2*nt4+1], ah[mt], bl+2);
                }
            }
        }
        MBARRIER_ARRIVE(EMPTY0+8*s);
    }

    // ---- epilogue ----
    float bv0[8], bv1[8];
    if (EPI != 3){
        #pragma unroll
        for (int ni = 0; ni < 8; ++ni){
            const int col = col0 + wn + ni*8 + (lane&3)*2;
            bv0[ni] = bias[col]; bv1[ni] = bias[col+1];
        }
    }

    if (TOUT == 0){
        const int KCo = N >> 5;
        #pragma unroll
        for (int mt = 0; mt < 2; ++mt){
            #pragma unroll
            for (int h = 0; h < 2; ++h){
                const long row = row0 + wm + mt*16 + h*8 + (lane>>2);
                float sc = 1.f;
                if (EPI == 3) sc = 1.f/(aux[row] + 1e-6f);
                const int r = (int)(row & 127);
                #pragma unroll
                for (int ni = 0; ni < 8; ++ni){
                    const int col = col0 + wn + ni*8 + (lane&3)*2;
                    float c0 = acc[mt][ni][2*h], c1 = acc[mt][ni][2*h+1];
                    if (EPI != 3){ c0 += bv0[ni]; c1 += bv1[ni]; }
                    if (EPI == 1){ c0 = (c0>0.f)?(c0+1.f):expf(c0); c1 = (c1>0.f)?(c1+1.f):expf(c1); }
                    if (EPI == 2){ c0 = gelu_tanh(c0); c1 = gelu_tanh(c1); }
                    if (EPI == 3){ c0 *= sc; c1 *= sc; }
                    __nv_bfloat16 h0 = __float2bfloat16(c0), h1 = __float2bfloat16(c1);
                    __nv_bfloat162 vh; vh.x = h0; vh.y = h1;
                    __nv_bfloat162 vl;
                    vl.x = __float2bfloat16(c0 - __bfloat162float(h0));
                    vl.y = __float2bfloat16(c1 - __bfloat162float(h1));
                    *(__nv_bfloat162*)(C + cidx(KCo, 0, rowblk, r, col)) = vh;
                    *(__nv_bfloat162*)(C + cidx(KCo, 1, rowblk, r, col)) = vl;
                }
            }
        }
    } else {
        // pre-apply bias + activation into acc
        #pragma unroll
        for (int mt = 0; mt < 2; ++mt)
            #pragma unroll
            for (int ni = 0; ni < 8; ++ni){
                #pragma unroll
                for (int h = 0; h < 2; ++h){
                    float c0 = acc[mt][ni][2*h] + bv0[ni];
                    float c1 = acc[mt][ni][2*h+1] + bv1[ni];
                    if (EPI == 1){ c0 = (c0>0.f)?(c0+1.f):expf(c0); c1 = (c1>0.f)?(c1+1.f):expf(c1); }
                    acc[mt][ni][2*h] = c0; acc[mt][ni][2*h+1] = c1;
                }
            }
        __syncthreads();
        __nv_bfloat16* sT = (__nv_bfloat16*)(smem + 1024);   // [128 col][136 tok]
        const int st0 = (int)(row0 & (Ss-1));
        const int cb = col0 >> 7;
        const int KCss = Ss >> 5;
        __nv_bfloat16* tB = C + (long)(row0 >> 12)*2*(long)N*Ss;
        #pragma unroll
        for (int pl = 0; pl < 2; ++pl){
            #pragma unroll
            for (int mt = 0; mt < 2; ++mt){
                #pragma unroll
                for (int h = 0; h < 2; ++h){
                    const int tok = wm + mt*16 + h*8 + (lane>>2);
                    #pragma unroll
                    for (int ni = 0; ni < 8; ++ni){
                        const int col = wn + ni*8 + (lane&3)*2;
                        float c0 = acc[mt][ni][2*h], c1 = acc[mt][ni][2*h+1];
                        __nv_bfloat16 h0 = __float2bfloat16(c0), h1 = __float2bfloat16(c1);
                        if (pl){
                            h0 = __float2bfloat16(c0 - __bfloat162float(h0));
                            h1 = __float2bfloat16(c1 - __bfloat162float(h1));
                        }
                        sT[col*136 + tok]     = h0;
                        sT[(col+1)*136 + tok] = h1;
                    }
                }
            }
            __syncthreads();
            #pragma unroll
            for (int j = 0; j < 8; ++j){
                const int idx = j*256 + tid;
                const int oct = idx >> 7, n = idx & 127;
                uint4 v = *(const uint4*)(sT + n*136 + oct*8);
                const int st = st0 + oct*8;
                long e = (((long)(cb*2+pl)*KCss + (st>>5)) << 12) + ((((st>>3)&3)*128 + n) << 3);
                *(uint4*)(tB + e) = v;
            }
            __syncthreads();
        }
    }
}

// ===================== kv gemm: kv^T[b] = vT[b] @ pkT[b]^T, split-K fp32 partials =====================
__global__ void __launch_bounds__(256)
gemm_kv(const __nv_bfloat16* __restrict__ vT, const __nv_bfloat16* __restrict__ pkT,
        float* __restrict__ part)
{
    extern __shared__ __align__(1024) char smem[];
    const uint32_t sb = smem_to_u32(smem);
    const int tid = threadIdx.x, wid = tid >> 5, lane = tid & 31;
    const int bz = blockIdx.z, b = bz >> 4, sp = bz & (KVS-1);
    const int ablk = blockIdx.y, row0 = ablk*128;
    const int niter = (Ss/KVS) >> 6;   // 4
    const int kchunk0 = sp*((Ss/KVS) >> 5);
    const uint32_t FULL0 = sb, EMPTY0 = sb + 32;
    const uint32_t STG0 = sb + 1024;
    const __nv_bfloat16* A  = vT  + (long)b*2*Dd*Ss;
    const __nv_bfloat16* Bp = pkT + (long)b*2*Pp*Ss;

    if (tid == 0){
        #pragma unroll
        for (int s = 0; s < NSTG; ++s){ MBARRIER_INIT(FULL0+8*s, 1); MBARRIER_INIT(EMPTY0+8*s, 256); }
    }
    __syncthreads();

    auto issue = [&](int j){
        const int s = j % NSTG;
        if (j >= NSTG) MBARRIER_WAIT_PARITY(EMPTY0+8*s, ((j/NSTG)-1)&1);
        MBARRIER_EXPECT_TX(FULL0+8*s, 65536u);
        const uint32_t dst = STG0 + s*STGB;
        #pragma unroll
        for (int pl = 0; pl < 2; ++pl){
            bulk_g2s(dst + pl*16384,
                     A  + (((long)(ablk*2+pl)*(Ss>>5) + kchunk0 + j*2) << 12), 16384u, FULL0+8*s);
            bulk_g2s(dst + 32768 + pl*16384,
                     Bp + (((long)pl*(Ss>>5) + kchunk0 + j*2) << 12), 16384u, FULL0+8*s);
        }
    };
    if (tid == 0){ for (int j = 0; j < NSTG-1; ++j) issue(j); }

    float acc[2][8][4];
    #pragma unroll
    for (int mt=0;mt<2;mt++)
        #pragma unroll
        for (int ni=0;ni<8;ni++)
            #pragma unroll
            for (int r=0;r<4;r++) acc[mt][ni][r]=0.f;

    const int wm = (wid >> 1)*32, wn = (wid & 1)*64;
    const int a_mrow = wm + ((lane>>3)&1)*8 + (lane&7);
    const int a_kc   = (lane>>4);
    const int b_nrow = wn + ((lane>>4)&1)*8 + (lane&7);
    const int b_kc   = ((lane>>3)&1);

    for (int it = 0; it < niter; ++it){
        const int s = it % NSTG;
        if (tid == 0 && it + NSTG-1 < niter) issue(it + NSTG-1);
        MBARRIER_WAIT_PARITY(FULL0+8*s, (it/NSTG)&1);
        const uint32_t stg = STG0 + s*STGB;
        #pragma unroll
        for (int step = 0; step < 4; ++step){
            const int ga = a_kc + 2*step, gb = b_kc + 2*step;
            uint32_t ah[2][4], al[2][4];
            #pragma unroll
            for (int mt = 0; mt < 2; ++mt){
                const uint32_t aoff = stg + (uint32_t)((ga>>2)*8192 + (((ga&3)*128) + a_mrow + mt*16)*16);
                ldsm4(ah[mt], aoff);
                ldsm4(al[mt], aoff + 16384);
            }
            #pragma unroll
            for (int nt4 = 0; nt4 < 4; ++nt4){
                const uint32_t boff = stg + 32768 + (uint32_t)((gb>>2)*8192 + (((gb&3)*128) + b_nrow + nt4*16)*16);
                uint32_t bh[4], bl[4];
                ldsm4(bh, boff);
                ldsm4(bl, boff + 16384);
                #pragma unroll
                for (int mt = 0; mt < 2; ++mt){
                    mma_bf16(acc[mt][2*nt4  ], ah[mt], bh);
                    mma_bf16(acc[mt][2*nt4+1], ah[mt], bh+2);
                    mma_bf16(acc[mt][2*nt4  ], al[mt], bh);
                    mma_bf16(acc[mt][2*nt4+1], al[mt], bh+2);
                    mma_bf16(acc[mt][2*nt4  ], ah[mt], bl);
                    mma_bf16(acc[mt][2*nt4+1], ah[mt], bl+2);
                }
            }
        }
        MBARRIER_ARRIVE(EMPTY0+8*s);
    }

    float* Cb = part + (long)bz*Dd*Pp;
    #pragma unroll
    for (int mt = 0; mt < 2; ++mt){
        #pragma unroll
        for (int h = 0; h < 2; ++h){
            const int row = row0 + wm + mt*16 + h*8 + (lane>>2);
            #pragma unroll
            for (int ni = 0; ni < 8; ++ni){
                const int col = wn + ni*8 + (lane&3)*2;
                *(float2*)(Cb + (long)row*Pp + col) =
                    make_float2(acc[mt][ni][2*h], acc[mt][ni][2*h+1]);
            }
        }
    }
}

// reduce partials -> kvtS chunked [D rows][P] per batch
__global__ void reduce_kvt(const float* __restrict__ part, __nv_bfloat16* __restrict__ kvt)
{
    long i = (long)blockIdx.x*256 + threadIdx.x;
    int b = (int)(i / (Dd*Pp)); int r0 = (int)(i % (Dd*Pp));
    int d = r0 >> 7, p = r0 & 127;
    const float* q = part + ((long)b*KVS)*Dd*Pp + r0;
    float s = 0.f;
    #pragma unroll
    for (int j = 0; j < KVS; j++) s += q[(long)j*Dd*Pp];
    __nv_bfloat16 h = __float2bfloat16(s);
    __nv_bfloat16* base = kvt + (long)b*2*Dd*Pp;
    base[cidx(4, 0, d>>7, d&127, p)] = h;
    base[cidx(4, 1, d>>7, d&127, p)] = __float2bfloat16(s - __bfloat162float(h));
}

// ===================== weight conversion: fp32 [L][K,N] -> chunked split [L][N rows][K] =====================
__global__ void wconv(const float* __restrict__ W, __nv_bfloat16* __restrict__ out, int K, int N)
{
    __shared__ float t[32][33];
    const int n0 = blockIdx.x*32, k0 = blockIdx.y*32, l = blockIdx.z;
    const float* Wl = W + (long)l*K*N;
    __nv_bfloat16* ob = out + (long)l*2*N*K;
    const int KC = K >> 5;
    for (int i = threadIdx.y; i < 32; i += 8)
        t[i][threadIdx.x] = Wl[(long)(k0+i)*N + n0 + threadIdx.x];
    __syncthreads();
    for (int i = threadIdx.y; i < 32; i += 8) {
        float v = t[threadIdx.x][i];
        const int n = n0 + i, k = k0 + threadIdx.x;
        __nv_bfloat16 h = __float2bfloat16(v);
        ob[cidx(KC, 0, n>>7, n&127, k)] = h;
        ob[cidx(KC, 1, n>>7, n&127, k)] = __float2bfloat16(v - __bfloat162float(h));
    }
}

// folded feature weights: Wqf[c,p] = sum_m Wq[c,m]*Wf[m,p], fp32, -> chunked split [P rows][Dd]
__global__ void wfold(const float* __restrict__ Wq, const float* __restrict__ Wk,
                      const float* __restrict__ Wf,
                      __nv_bfloat16* __restrict__ oq, __nv_bfloat16* __restrict__ ok)
{
    // grid (Pp/32, Dd/32, 2*Ll), block (32,8)
    const int which = blockIdx.z & 1, l = blockIdx.z >> 1;
    const float* Wa  = (which ? Wk : Wq) + (long)l*Dd*Dd;
    const float* Wfl = Wf + (long)l*Dd*Pp;
    __nv_bfloat16* out = (which ? ok : oq) + (long)l*2*Pp*Dd;
    const int p0 = blockIdx.x*32, c0 = blockIdx.y*32;
    __shared__ float a[32][33], bsm[32][33];
    const int tx = threadIdx.x, ty = threadIdx.y;
    float acc[4] = {0.f,0.f,0.f,0.f};
    for (int m0 = 0; m0 < Dd; m0 += 32){
        for (int i = ty; i < 32; i += 8) a[i][tx]   = Wa[(long)(c0+i)*Dd + m0+tx];
        for (int i = ty; i < 32; i += 8) bsm[i][tx] = Wfl[(long)(m0+i)*Pp + p0+tx];
        __syncthreads();
        #pragma unroll
        for (int mm = 0; mm < 32; ++mm){
            float bv = bsm[mm][tx];
            #pragma unroll
            for (int i = 0; i < 4; ++i) acc[i] = fmaf(a[ty+8*i][mm], bv, acc[i]);
        }
        __syncthreads();
    }
    #pragma unroll
    for (int i = 0; i < 4; ++i){
        const int k = c0 + ty + 8*i, n = p0 + tx;
        __nv_bfloat16 h = __float2bfloat16(acc[i]);
        out[cidx(16, 0, 0, n, k)] = h;
        out[cidx(16, 1, 0, n, k)] = __float2bfloat16(acc[i] - __bfloat162float(h));
    }
}

// folded bias: bqf[p] = bf[p] + sum_c bq[c]*Wf[c,p]
__global__ void bfold(const float* __restrict__ bq, const float* __restrict__ bk,
                      const float* __restrict__ bf, const float* __restrict__ Wf,
                      float* __restrict__ obq, float* __restrict__ obk)
{
    const int which = blockIdx.x & 1, l = blockIdx.x >> 1;
    const float* bb  = (which ? bk : bq) + l*Dd;
    const float* Wfl = Wf + (long)l*Dd*Pp;
    const int p = threadIdx.x;
    float s = bf[l*Pp + p];
    for (int c = 0; c < Dd; ++c) s = fmaf(bb[c], Wfl[(long)c*Pp + p], s);
    (which ? obk : obq)[l*Pp + p] = s;
}

// ksum[b,p] = sum_s pkT(hi+lo), chunked read, deterministic tree
__global__ void ksum_kernel(const __nv_bfloat16* __restrict__ pkT, float* __restrict__ ks)
{
    const int p = blockIdx.x, b = blockIdx.y, t = threadIdx.x;
    const __nv_bfloat16* base = pkT + (long)b*2*Pp*Ss;
    float s = 0.f;
    for (int o = t; o < 512; o += 256){
        #pragma unroll
        for (int pl = 0; pl < 2; ++pl){
            long e = (((long)(pl*(Ss>>5)) + (o>>2)) << 12) + (((o&3)*128 + p) << 3);
            uint4 v = *(const uint4*)(base + e);
            const __nv_bfloat162* pv = (const __nv_bfloat162*)&v;
            #pragma unroll
            for (int q = 0; q < 4; ++q)
                s += __bfloat162float(pv[q].x) + __bfloat162float(pv[q].y);
        }
    }
    __shared__ float sh[256];
    sh[t] = s; __syncthreads();
    #pragma unroll
    for (int o = 128; o > 0; o >>= 1){
        if (t < o) sh[t] += sh[t+o];
        __syncthreads();
    }
    if (!t) ks[b*Pp + p] = sh[0];
}

// z[b,s] = dot(pq(hi+lo), ksum)
__global__ void z_kernel(const __nv_bfloat16* __restrict__ pq, const float* __restrict__ ksum,
                         float* __restrict__ z)
{
    int gw = (int)((blockIdx.x*(long)blockDim.x + threadIdx.x) >> 5);
    int lane = threadIdx.x & 31;
    if (gw >= BS) return;
    const int b = gw >> 12, blk = gw >> 7, r = gw & 127;
    const float* kr = ksum + b*Pp;
    const int p0 = lane*4;
    float s = 0.f;
    #pragma unroll
    for (int pl = 0; pl < 2; ++pl){
        long e = (((long)(blk*2+pl)*4 + (p0>>5)) << 12) + ((((p0>>3)&3)*128 + r) << 3) + (p0&7);
        uint2 v = *(const uint2*)(pq + e);
        const __nv_bfloat162* pv = (const __nv_bfloat162*)&v;
        s = fmaf(__bfloat162float(pv[0].x), kr[p0],   s);
        s = fmaf(__bfloat162float(pv[0].y), kr[p0+1], s);
        s = fmaf(__bfloat162float(pv[1].x), kr[p0+2], s);
        s = fmaf(__bfloat162float(pv[1].y), kr[p0+3], s);
    }
    #pragma unroll
    for (int o = 16; o; o >>= 1) s += __shfl_xor_sync(0xffffffffu, s, o);
    if (!lane) z[gw] = s;
}

// layernorm on chunked split data
__global__ void ln_kernel(const __nv_bfloat16* __restrict__ in, const float* __restrict__ g,
                          const float* __restrict__ bta, __nv_bfloat16* __restrict__ out)
{
    const int row = blockIdx.x, t = threadIdx.x;
    const int blk = row >> 7, r = row & 127, d = 2*t;
    const long eh = cidx(16, 0, blk, r, d);
    const long el = cidx(16, 1, blk, r, d);
    __nv_bfloat162 h2 = *(const __nv_bfloat162*)(in + eh);
    __nv_bfloat162 l2 = *(const __nv_bfloat162*)(in + el);
    float vx = __bfloat162float(h2.x) + __bfloat162float(l2.x);
    float vy = __bfloat162float(h2.y) + __bfloat162float(l2.y);
    float s  = vx + vy, sq = vx*vx + vy*vy;
    #pragma unroll
    for (int o = 16; o; o >>= 1){
        s  += __shfl_xor_sync(0xffffffffu, s,  o);
        sq += __shfl_xor_sync(0xffffffffu, sq, o);
    }
    __shared__ float sh[8], shq[8];
    int w = t >> 5, lane = t & 31;
    if (!lane){ sh[w] = s; shq[w] = sq; }
    __syncthreads();
    float ts = 0.f, tq = 0.f;
    #pragma unroll
    for (int i = 0; i < 8; i++){ ts += sh[i]; tq += shq[i]; }
    float mu = ts*(1.f/Dd);
    float rv = rsqrtf(tq*(1.f/Dd) - mu*mu + 1e-5f);
    float ox = (vx-mu)*rv*g[d]   + bta[d];
    float oy = (vy-mu)*rv*g[d+1] + bta[d+1];
    __nv_bfloat16 hx = __float2bfloat16(ox), hy = __float2bfloat16(oy);
    __nv_bfloat162 oh; oh.x = hx; oh.y = hy;
    __nv_bfloat162 ol;
    ol.x = __float2bfloat16(ox - __bfloat162float(hx));
    ol.y = __float2bfloat16(oy - __bfloat162float(hy));
    *(__nv_bfloat162*)(out + eh) = oh;
    *(__nv_bfloat162*)(out + el) = ol;
}

__global__ void embed_kernel(const int* __restrict__ x, const float* __restrict__ emb,
                             const float* __restrict__ pos, __nv_bfloat16* __restrict__ h)
{
    const int token = blockIdx.x, t = threadIdx.x;
    const int s = token & (Ss-1), id = x[token];
    const int blk = token >> 7, r = token & 127, d = 2*t;
    float2 e = *(const float2*)(emb + (long)id*Dd + d);
    float2 p = *(const float2*)(pos + (long)s*Dd + d);
    float vx = e.x + p.x, vy = e.y + p.y;
    __nv_bfloat16 hx = __float2bfloat16(vx), hy = __float2bfloat16(vy);
    __nv_bfloat162 oh; oh.x = hx; oh.y = hy;
    __nv_bfloat162 ol;
    ol.x = __float2bfloat16(vx - __bfloat162float(hx));
    ol.y = __float2bfloat16(vy - __bfloat162float(hy));
    *(__nv_bfloat162*)(h + cidx(16, 0, blk, r, d)) = oh;
    *(__nv_bfloat162*)(h + cidx(16, 1, blk, r, d)) = ol;
}

// partial col sums of hS (chunked) for mean pool
__global__ void colsum_part(const __nv_bfloat16* __restrict__ in, float* __restrict__ part)
{
    const int b = blockIdx.y, ch = blockIdx.x, c = threadIdx.x;  // 512 threads
    const int blkg = b*32 + ch;
    float s = 0.f;
    #pragma unroll
    for (int pl = 0; pl < 2; ++pl){
        long base = (((long)(blkg*2+pl)*16 + (c>>5)) << 12) + (((c>>3)&3)*128 << 3) + (c&7);
        #pragma unroll 4
        for (int i = 0; i < 128; ++i)
            s += __bfloat162float(in[base + i*8]);
    }
    part[((long)b*32 + ch)*Dd + c] = s;
}
__global__ void colsum_fin(const float* __restrict__ part, float* __restrict__ out,
                           int cols, int chunks, float scale)
{
    int b = blockIdx.x, c = threadIdx.x;
    float s = 0.f;
    for (int ch = 0; ch < chunks; ch++) s += part[((long)b*chunks+ch)*cols + c];
    out[(long)b*cols + c] = s*scale;
}

__global__ void head1_kernel(const float* __restrict__ pool, const float* __restrict__ Wh1,
                             const float* __restrict__ bh1, float* __restrict__ h1)
{
    int b = blockIdx.x;
    __shared__ float xr[Dd];
    for (int i = threadIdx.x; i < Dd; i += blockDim.x) xr[i] = pool[(long)b*Dd + i];
    __syncthreads();
    int t = threadIdx.x;
    float s = bh1[t];
    #pragma unroll 4
    for (int k = 0; k < Dd; k++) s = fmaf(xr[k], Wh1[(long)k*DHh + t], s);
    h1[(long)b*DHh + t] = fmaxf(s, 0.f);
}
__global__ void head2_kernel(const float* __restrict__ h1, const float* __restrict__ Wh2,
                             const float* __restrict__ bh2, float* __restrict__ out)
{
    int t = threadIdx.x;
    if (t < Bb*CC){
        int b = t / CC, c = t % CC;
        float s = bh2[c];
        #pragma unroll 4
        for (int k = 0; k < DHh; k++) s = fmaf(h1[(long)b*DHh + k], Wh2[(long)k*CC + c], s);
        out[t] = s;
    }
}

// ===================== launch =====================
extern "C" void kernel_launch(void* const* d_in, const int* in_sizes, int n_in,
                              void* d_out, int out_size)
{
    const int*   x   = (const int*)  d_in[0];
    const float* emb = (const float*)d_in[1];
    const float* pos = (const float*)d_in[2];
    const float* Wq  = (const float*)d_in[3];   const float* bq = (const float*)d_in[4];
    const float* Wk  = (const float*)d_in[5];   const float* bk = (const float*)d_in[6];
    const float* Wv  = (const float*)d_in[7];   const float* bv = (const float*)d_in[8];
    const float* Wf  = (const float*)d_in[9];   const float* bf = (const float*)d_in[10];
    const float* Wo  = (const float*)d_in[11];  const float* bo = (const float*)d_in[12];
    const float* lng = (const float*)d_in[13];  const float* lnb= (const float*)d_in[14];
    const float* W1  = (const float*)d_in[15];  const float* b1 = (const float*)d_in[16];
    const float* W2  = (const float*)d_in[17];  const float* b2 = (const float*)d_in[18];
    const float* Wh1 = (const float*)d_in[19];  const float* bh1= (const float*)d_in[20];
    const float* Wh2 = (const float*)d_in[21];  const float* bh2= (const float*)d_in[22];

    __nv_bfloat16 *hS,*qS,*vT,*tS,*pqS,*pkT,*mS,*kvtS,*wv,*wo,*w1,*w2,*wqf,*wkf;
    float *bqf,*bkf,*kvp,*ks,*z,*pp,*pool,*h1;
    cudaGetSymbolAddress((void**)&hS,  g_hS);   cudaGetSymbolAddress((void**)&qS,  g_qS);
    cudaGetSymbolAddress((void**)&vT,  g_vT);   cudaGetSymbolAddress((void**)&tS,  g_tS);
    cudaGetSymbolAddress((void**)&pqS, g_pqS);  cudaGetSymbolAddress((void**)&pkT, g_pkT);
    cudaGetSymbolAddress((void**)&mS,  g_mS);   cudaGetSymbolAddress((void**)&kvtS,g_kvtS);
    cudaGetSymbolAddress((void**)&wv, g_wv); cudaGetSymbolAddress((void**)&wo, g_wo);
    cudaGetSymbolAddress((void**)&w1, g_w1); cudaGetSymbolAddress((void**)&w2, g_w2);
    cudaGetSymbolAddress((void**)&wqf, g_wqf); cudaGetSymbolAddress((void**)&wkf, g_wkf);
    cudaGetSymbolAddress((void**)&bqf, g_bqf); cudaGetSymbolAddress((void**)&bkf, g_bkf);
    cudaGetSymbolAddress((void**)&kvp, g_kvp);
    cudaGetSymbolAddress((void**)&ks,  g_ks);  cudaGetSymbolAddress((void**)&z,   g_z);
    cudaGetSymbolAddress((void**)&pp,  g_pp);  cudaGetSymbolAddress((void**)&pool,g_pool);
    cudaGetSymbolAddress((void**)&h1,  g_h1);

    cudaFuncSetAttribute(gemm_mma<0,0>, cudaFuncAttributeMaxDynamicSharedMemorySize, SMEMG);
    cudaFuncSetAttribute(gemm_mma<0,1>, cudaFuncAttributeMaxDynamicSharedMemorySize, SMEMG);
    cudaFuncSetAttribute(gemm_mma<1,0>, cudaFuncAttributeMaxDynamicSharedMemorySize, SMEMG);
    cudaFuncSetAttribute(gemm_mma<1,1>, cudaFuncAttributeMaxDynamicSharedMemorySize, SMEMG);
    cudaFuncSetAttribute(gemm_mma<2,0>, cudaFuncAttributeMaxDynamicSharedMemorySize, SMEMG);
    cudaFuncSetAttribute(gemm_mma<3,0>, cudaFuncAttributeMaxDynamicSharedMemorySize, SMEMG);
    cudaFuncSetAttribute(gemm_kv,       cudaFuncAttributeMaxDynamicSharedMemorySize, SMEMG);

    dim3 wt(32, 8);
    const dim3 gDD(Dd/128, BS/128, 1);
    const dim3 gDP(1,      BS/128, 1);
    const dim3 gDF(DFf/128,BS/128, 1);
    const dim3 gAT(Dd/128, Ss/128, Bb);
    const dim3 gKV(1, Dd/128, Bb*KVS);
    const long wDD = (long)2*Dd*Dd, wPD = (long)2*Pp*Dd, wDF = (long)2*DFf*Dd;

    // launch order: first gemm_mma lands at stream index 5 for ncu -s 5
    embed_kernel<<<BS,256>>>(x, emb, pos, hS);                          // 0
    wconv<<<dim3(Dd/32, Dd/32, Ll), wt>>>(Wv, wv, Dd, Dd);              // 1
    wfold<<<dim3(Pp/32, Dd/32, 2*Ll), wt>>>(Wq, Wk, Wf, wqf, wkf);      // 2
    bfold<<<2*Ll, Pp>>>(bq, bk, bf, Wf, bqf, bkf);                      // 3
    wconv<<<dim3(Dd/32, Dd/32, Ll), wt>>>(Wo, wo, Dd, Dd);              // 4

    for (int l = 0; l < Ll; l++){
        gemm_mma<0,1><<<gDD,256,SMEMG>>>(hS, 16, wv + l*wDD, 16, 0, bv + l*Dd, nullptr, vT, Dd, Dd);   // 5 at l=0
        if (l == 0){
            wconv<<<dim3(DFf/32, Dd/32,  Ll), wt>>>(W1, w1, Dd, DFf);
            wconv<<<dim3(Dd/32,  DFf/32, Ll), wt>>>(W2, w2, DFf, Dd);
        }
        gemm_mma<1,0><<<gDP,256,SMEMG>>>(hS, 16, wqf + l*wPD, 16, 0, bqf + l*Pp, nullptr, pqS, Pp, Dd);
        gemm_mma<1,1><<<gDP,256,SMEMG>>>(hS, 16, wkf + l*wPD, 16, 0, bkf + l*Pp, nullptr, pkT, Pp, Dd);
        ksum_kernel<<<dim3(Pp,Bb),256>>>(pkT, ks);
        gemm_kv<<<gKV,256,SMEMG>>>(vT, pkT, kvp);
        reduce_kvt<<<(Bb*Dd*Pp)/256,256>>>(kvp, kvtS);
        z_kernel<<<BS/8,256>>>(pqS, ks, z);
        gemm_mma<3,0><<<gAT,256,SMEMG>>>(pqS, 4, kvtS, 4, (long)2*Dd*Pp, nullptr, z, tS, Dd, Pp);
        gemm_mma<0,0><<<gDD,256,SMEMG>>>(tS, 16, wo + l*wDD, 16, 0, bo + l*Dd, nullptr, qS, Dd, Dd);
        ln_kernel<<<BS,256>>>(qS, lng + l*Dd, lnb + l*Dd, tS);
        gemm_mma<2,0><<<gDF,256,SMEMG>>>(tS, 16, w1 + l*wDF, 16, 0, b1 + l*DFf, nullptr, mS, DFf, Dd);
        gemm_mma<0,0><<<gDD,256,SMEMG>>>(mS, 64, w2 + l*wDF, 64, 0, b2 + l*Dd, nullptr, hS, Dd, DFf);
    }

    colsum_part<<<dim3(32,Bb),Dd>>>(hS, pp);
    colsum_fin <<<Bb,Dd>>>(pp, pool, Dd, 32, 1.0f/Ss);
    head1_kernel<<<Bb,DHh>>>(pool, Wh1, bh1, h1);
    head2_kernel<<<1,32>>>(h1, Wh2, bh2, (float*)d_out);
}

// round 8
// speedup vs baseline: 3.7942x; 1.0084x over previous
#include <cuda_runtime.h>
#include <cuda_bf16.h>
#include <math.h>
#include <stdint.h>

#define Bb  8
#define Ss  4096
#define Dd  512
#define Pp  128
#define Ll  4
#define DFf 2048
#define DHh 256
#define CC  2
#define BS  (Bb*Ss)
#define KVS 16

// ===================== PTX helpers (sm_90 core features only) =====================
__device__ __forceinline__ uint32_t smem_to_u32(const void* p) {
    uint32_t a;
    asm("{ .reg .u64 t; cvta.to.shared.u64 t, %1; cvt.u32.u64 %0, t; }" : "=r"(a) : "l"(p));
    return a;
}
#define MBARRIER_INIT(m, c) \
    asm volatile("mbarrier.init.shared.b64 [%0], %1;" :: "r"((uint32_t)(m)), "r"((uint32_t)(c)) : "memory")
#define MBARRIER_EXPECT_TX(m, b) \
    asm volatile("mbarrier.arrive.expect_tx.shared.b64 _, [%0], %1;" :: "r"((uint32_t)(m)), "r"((uint32_t)(b)) : "memory")
#define MBARRIER_ARRIVE(m) \
    asm volatile("mbarrier.arrive.shared.b64 _, [%0];" :: "r"((uint32_t)(m)) : "memory")
#define MBARRIER_WAIT_PARITY(m, par) do { \
    uint32_t _m=(uint32_t)(m), _p=(uint32_t)(par), _d; \
    asm volatile("{\n\t.reg .pred p;\n\tmbarrier.try_wait.parity.acquire.cta.shared::cta.b64 p, [%1], %2;\n\tselp.b32 %0,1,0,p;\n\t}" \
        : "=r"(_d) : "r"(_m), "r"(_p) : "memory"); \
    if (!_d) { \
        asm volatile("{\n\t.reg .pred P1;\n\tWL_%=:\n\tmbarrier.try_wait.parity.acquire.cta.shared::cta.b64 P1, [%0], %1, 0x989680;\n\t@P1 bra.uni WD_%=;\n\tbra.uni WL_%=;\n\tWD_%=:\n\t}" \
            :: "r"(_m), "r"(_p) : "memory"); \
    } \
} while(0)
__device__ __forceinline__ void bulk_g2s(uint32_t dst, const void* src, uint32_t bytes, uint32_t mbar){
    asm volatile("cp.async.bulk.shared::cluster.global.mbarrier::complete_tx::bytes [%0], [%1], %2, [%3];"
        :: "r"(dst), "l"(src), "r"(bytes), "r"(mbar) : "memory");
}
__device__ __forceinline__ void ldsm4(uint32_t* r, uint32_t addr){
    asm volatile("ldmatrix.sync.aligned.m8n8.x4.shared.b16 {%0,%1,%2,%3}, [%4];"
        : "=r"(r[0]),"=r"(r[1]),"=r"(r[2]),"=r"(r[3]) : "r"(addr));
}
__device__ __forceinline__ void mma_bf16(float* d, const uint32_t* a, const uint32_t* b){
    asm volatile("mma.sync.aligned.m16n8k16.row.col.f32.bf16.bf16.f32 "
        "{%0,%1,%2,%3}, {%4,%5,%6,%7}, {%8,%9}, {%0,%1,%2,%3};"
        : "+f"(d[0]),"+f"(d[1]),"+f"(d[2]),"+f"(d[3])
        : "r"(a[0]),"r"(a[1]),"r"(a[2]),"r"(a[3]), "r"(b[0]),"r"(b[1]));
}

// ===================== chunk-packed layout =====================
__device__ __forceinline__ long cidx(int KC, int pl, int blk, int r, int k){
    return (((long)(blk*2 + pl)*KC + (k>>5)) << 12) + ((((k>>3)&3)*128 + r) << 3) + (k&7);
}

// ===================== device globals =====================
__device__ __align__(256) __nv_bfloat16 g_hS [2*(size_t)BS*Dd];
__device__ __align__(256) __nv_bfloat16 g_qS [2*(size_t)BS*Dd];
__device__ __align__(256) __nv_bfloat16 g_vT [2*(size_t)BS*Dd];
__device__ __align__(256) __nv_bfloat16 g_tS [2*(size_t)BS*Dd];
__device__ __align__(256) __nv_bfloat16 g_pqS[2*(size_t)BS*Pp];
__device__ __align__(256) __nv_bfloat16 g_pkT[2*(size_t)BS*Pp];
__device__ __align__(256) __nv_bfloat16 g_mS [2*(size_t)BS*DFf];
__device__ __align__(256) __nv_bfloat16 g_kvtS[(size_t)Bb*2*Dd*Pp];
__device__ __align__(256) __nv_bfloat16 g_wv[(size_t)Ll*2*Dd*Dd];
__device__ __align__(256) __nv_bfloat16 g_wo[(size_t)Ll*2*Dd*Dd];
__device__ __align__(256) __nv_bfloat16 g_w1[(size_t)Ll*2*DFf*Dd];
__device__ __align__(256) __nv_bfloat16 g_w2[(size_t)Ll*2*Dd*DFf];
__device__ __align__(256) __nv_bfloat16 g_wqf[(size_t)Ll*2*Pp*Dd];
__device__ __align__(256) __nv_bfloat16 g_wkf[(size_t)Ll*2*Pp*Dd];
__device__ float g_bqf[Ll*Pp];
__device__ float g_bkf[Ll*Pp];
__device__ float g_kvp[(size_t)Bb*KVS*Pp*Dd];
__device__ float g_ks [Bb*Pp];
__device__ float g_z  [BS];
__device__ float g_pp [Bb*32*Dd];
__device__ float g_pool[Bb*Dd];
__device__ float g_h1 [Bb*DHh];

__device__ __forceinline__ float gelu_tanh(float x){
    float u = 0.7978845608028654f*(x + 0.044715f*x*x*x);
    return 0.5f*x*(1.0f + tanhf(u));
}

// ===================== bulk-pipelined split-bf16 HMMA GEMM =====================
#define NSTG 3
#define STGB 65536
#define SMEMG (1024 + NSTG*STGB)

template<int EPI, int TOUT>  // EPI 0:+bias 1:+bias,elu+1 2:+bias,gelu 3:*1/(aux+eps); TOUT 0:chunked, 1:transposed chunked
__global__ void __launch_bounds__(256)
gemm_mma(const __nv_bfloat16* __restrict__ A, int KCa,
         const __nv_bfloat16* __restrict__ Bw, int KCb, long b_batch,
         const float* __restrict__ bias, const float* __restrict__ aux,
         __nv_bfloat16* __restrict__ C, int N, int K)
{
    extern __shared__ __align__(1024) char smem[];
    const uint32_t sb = smem_to_u32(smem);
    const int tid = threadIdx.x, wid = tid >> 5, lane = tid & 31;
    const int rowblk = blockIdx.z*gridDim.y + blockIdx.y;
    const int nblk = blockIdx.x;
    const int row0 = rowblk*128, col0 = nblk*128;
    const int niter = K >> 6;
    const uint32_t FULL0 = sb, EMPTY0 = sb + 32;
    const uint32_t STG0 = sb + 1024;
    const __nv_bfloat16* Bt = Bw + (long)blockIdx.z*b_batch;

    if (tid == 0){
        #pragma unroll
        for (int s = 0; s < NSTG; ++s){ MBARRIER_INIT(FULL0+8*s, 1); MBARRIER_INIT(EMPTY0+8*s, 256); }
    }
    __syncthreads();

    auto issue = [&](int j){
        const int s = j % NSTG;
        if (j >= NSTG) MBARRIER_WAIT_PARITY(EMPTY0+8*s, ((j/NSTG)-1)&1);
        MBARRIER_EXPECT_TX(FULL0+8*s, 65536u);
        const uint32_t dst = STG0 + s*STGB;
        #pragma unroll
        for (int pl = 0; pl < 2; ++pl){
            bulk_g2s(dst + pl*16384,
                     A  + (((long)(rowblk*2+pl)*KCa + j*2) << 12), 16384u, FULL0+8*s);
            bulk_g2s(dst + 32768 + pl*16384,
                     Bt + (((long)(nblk*2+pl)*KCb + j*2) << 12), 16384u, FULL0+8*s);
        }
    };
    if (tid == 0){
        const int pro = (niter < NSTG-1) ? niter : NSTG-1;
        for (int j = 0; j < pro; ++j) issue(j);
    }

    float acc[2][8][4];
    #pragma unroll
    for (int mt=0;mt<2;mt++)
        #pragma unroll
        for (int ni=0;ni<8;ni++)
            #pragma unroll
            for (int r=0;r<4;r++) acc[mt][ni][r]=0.f;

    const int wm = (wid >> 1)*32, wn = (wid & 1)*64;
    const int a_mrow = wm + ((lane>>3)&1)*8 + (lane&7);
    const int a_kc   = (lane>>4);
    const int b_nrow = wn + ((lane>>4)&1)*8 + (lane&7);
    const int b_kc   = ((lane>>3)&1);

    for (int it = 0; it < niter; ++it){
        const int s = it % NSTG;
        if (tid == 0 && it + NSTG-1 < niter) issue(it + NSTG-1);
        MBARRIER_WAIT_PARITY(FULL0+8*s, (it/NSTG)&1);
        const uint32_t stg = STG0 + s*STGB;
        #pragma unroll
        for (int step = 0; step < 4; ++step){
            const int ga = a_kc + 2*step, gb = b_kc + 2*step;
            uint32_t ah[2][4], al[2][4], bh[4][4], bl[4][4];
            #pragma unroll
            for (int mt = 0; mt < 2; ++mt){
                const uint32_t aoff = stg + (uint32_t)((ga>>2)*8192 + (((ga&3)*128) + a_mrow + mt*16)*16);
                ldsm4(ah[mt], aoff);
                ldsm4(al[mt], aoff + 16384);
            }
            #pragma unroll
            for (int nt4 = 0; nt4 < 4; ++nt4){
                const uint32_t boff = stg + 32768 + (uint32_t)((gb>>2)*8192 + (((gb&3)*128) + b_nrow + nt4*16)*16);
                ldsm4(bh[nt4], boff);
                ldsm4(bl[nt4], boff + 16384);
            }
            // three passes over all 16 accumulators: reuse distance 16, per-acc order hh,lh,hl
            #pragma unroll
            for (int mt = 0; mt < 2; ++mt)
                #pragma unroll
                for (int ni = 0; ni < 8; ++ni)
                    mma_bf16(acc[mt][ni], ah[mt], bh[ni>>1] + (ni&1)*2);
            #pragma unroll
            for (int mt = 0; mt < 2; ++mt)
                #pragma unroll
                for (int ni = 0; ni < 8; ++ni)
                    mma_bf16(acc[mt][ni], al[mt], bh[ni>>1] + (ni&1)*2);
            #pragma unroll
            for (int mt = 0; mt < 2; ++mt)
                #pragma unroll
                for (int ni = 0; ni < 8; ++ni)
                    mma_bf16(acc[mt][ni], ah[mt], bl[ni>>1] + (ni&1)*2);
        }
        MBARRIER_ARRIVE(EMPTY0+8*s);
    }

    // ---- epilogue ----
    float bv0[8], bv1[8];
    if (EPI != 3){
        #pragma unroll
        for (int ni = 0; ni < 8; ++ni){
            const int col = col0 + wn + ni*8 + (lane&3)*2;
            bv0[ni] = bias[col]; bv1[ni] = bias[col+1];
        }
    }

    if (TOUT == 0){
        const int KCo = N >> 5;
        #pragma unroll
        for (int mt = 0; mt < 2; ++mt){
            #pragma unroll
            for (int h = 0; h < 2; ++h){
                const long row = row0 + wm + mt*16 + h*8 + (lane>>2);
                float sc = 1.f;
                if (EPI == 3) sc = 1.f/(aux[row] + 1e-6f);
                const int r = (int)(row & 127);
                #pragma unroll
                for (int ni = 0; ni < 8; ++ni){
                    const int col = col0 + wn + ni*8 + (lane&3)*2;
                    float c0 = acc[mt][ni][2*h], c1 = acc[mt][ni][2*h+1];
                    if (EPI != 3){ c0 += bv0[ni]; c1 += bv1[ni]; }
                    if (EPI == 1){ c0 = (c0>0.f)?(c0+1.f):expf(c0); c1 = (c1>0.f)?(c1+1.f):expf(c1); }
                    if (EPI == 2){ c0 = gelu_tanh(c0); c1 = gelu_tanh(c1); }
                    if (EPI == 3){ c0 *= sc; c1 *= sc; }
                    __nv_bfloat16 h0 = __float2bfloat16(c0), h1 = __float2bfloat16(c1);
                    __nv_bfloat162 vh; vh.x = h0; vh.y = h1;
                    __nv_bfloat162 vl;
                    vl.x = __float2bfloat16(c0 - __bfloat162float(h0));
                    vl.y = __float2bfloat16(c1 - __bfloat162float(h1));
                    *(__nv_bfloat162*)(C + cidx(KCo, 0, rowblk, r, col)) = vh;
                    *(__nv_bfloat162*)(C + cidx(KCo, 1, rowblk, r, col)) = vl;
                }
            }
        }
    } else {
        #pragma unroll
        for (int mt = 0; mt < 2; ++mt)
            #pragma unroll
            for (int ni = 0; ni < 8; ++ni){
                #pragma unroll
                for (int h = 0; h < 2; ++h){
                    float c0 = acc[mt][ni][2*h] + bv0[ni];
                    float c1 = acc[mt][ni][2*h+1] + bv1[ni];
                    if (EPI == 1){ c0 = (c0>0.f)?(c0+1.f):expf(c0); c1 = (c1>0.f)?(c1+1.f):expf(c1); }
                    acc[mt][ni][2*h] = c0; acc[mt][ni][2*h+1] = c1;
                }
            }
        __syncthreads();
        __nv_bfloat16* sT = (__nv_bfloat16*)(smem + 1024);   // [128 col][136 tok]
        const int st0 = (int)(row0 & (Ss-1));
        const int cb = col0 >> 7;
        const int KCss = Ss >> 5;
        __nv_bfloat16* tB = C + (long)(row0 >> 12)*2*(long)N*Ss;
        #pragma unroll
        for (int pl = 0; pl < 2; ++pl){
            #pragma unroll
            for (int mt = 0; mt < 2; ++mt){
                #pragma unroll
                for (int h = 0; h < 2; ++h){
                    const int tok = wm + mt*16 + h*8 + (lane>>2);
                    #pragma unroll
                    for (int ni = 0; ni < 8; ++ni){
                        const int col = wn + ni*8 + (lane&3)*2;
                        float c0 = acc[mt][ni][2*h], c1 = acc[mt][ni][2*h+1];
                        __nv_bfloat16 h0 = __float2bfloat16(c0), h1 = __float2bfloat16(c1);
                        if (pl){
                            h0 = __float2bfloat16(c0 - __bfloat162float(h0));
                            h1 = __float2bfloat16(c1 - __bfloat162float(h1));
                        }
                        sT[col*136 + tok]     = h0;
                        sT[(col+1)*136 + tok] = h1;
                    }
                }
            }
            __syncthreads();
            #pragma unroll
            for (int j = 0; j < 8; ++j){
                const int idx = j*256 + tid;
                const int oct = idx >> 7, n = idx & 127;
                uint4 v = *(const uint4*)(sT + n*136 + oct*8);
                const int st = st0 + oct*8;
                long e = (((long)(cb*2+pl)*KCss + (st>>5)) << 12) + ((((st>>3)&3)*128 + n) << 3);
                *(uint4*)(tB + e) = v;
            }
            __syncthreads();
        }
    }
}

// ===================== kv gemm: kv^T[b] = vT[b] @ pkT[b]^T, split-K fp32 partials =====================
__global__ void __launch_bounds__(256)
gemm_kv(const __nv_bfloat16* __restrict__ vT, const __nv_bfloat16* __restrict__ pkT,
        float* __restrict__ part)
{
    extern __shared__ __align__(1024) char smem[];
    const uint32_t sb = smem_to_u32(smem);
    const int tid = threadIdx.x, wid = tid >> 5, lane = tid & 31;
    const int bz = blockIdx.z, b = bz >> 4, sp = bz & (KVS-1);
    const int ablk = blockIdx.y, row0 = ablk*128;
    const int niter = (Ss/KVS) >> 6;
    const int kchunk0 = sp*((Ss/KVS) >> 5);
    const uint32_t FULL0 = sb, EMPTY0 = sb + 32;
    const uint32_t STG0 = sb + 1024;
    const __nv_bfloat16* A  = vT  + (long)b*2*Dd*Ss;
    const __nv_bfloat16* Bp = pkT + (long)b*2*Pp*Ss;

    if (tid == 0){
        #pragma unroll
        for (int s = 0; s < NSTG; ++s){ MBARRIER_INIT(FULL0+8*s, 1); MBARRIER_INIT(EMPTY0+8*s, 256); }
    }
    __syncthreads();

    auto issue = [&](int j){
        const int s = j % NSTG;
        if (j >= NSTG) MBARRIER_WAIT_PARITY(EMPTY0+8*s, ((j/NSTG)-1)&1);
        MBARRIER_EXPECT_TX(FULL0+8*s, 65536u);
        const uint32_t dst = STG0 + s*STGB;
        #pragma unroll
        for (int pl = 0; pl < 2; ++pl){
            bulk_g2s(dst + pl*16384,
                     A  + (((long)(ablk*2+pl)*(Ss>>5) + kchunk0 + j*2) << 12), 16384u, FULL0+8*s);
            bulk_g2s(dst + 32768 + pl*16384,
                     Bp + (((long)pl*(Ss>>5) + kchunk0 + j*2) << 12), 16384u, FULL0+8*s);
        }
    };
    if (tid == 0){ for (int j = 0; j < NSTG-1; ++j) issue(j); }

    float acc[2][8][4];
    #pragma unroll
    for (int mt=0;mt<2;mt++)
        #pragma unroll
        for (int ni=0;ni<8;ni++)
            #pragma unroll
            for (int r=0;r<4;r++) acc[mt][ni][r]=0.f;

    const int wm = (wid >> 1)*32, wn = (wid & 1)*64;
    const int a_mrow = wm + ((lane>>3)&1)*8 + (lane&7);
    const int a_kc   = (lane>>4);
    const int b_nrow = wn + ((lane>>4)&1)*8 + (lane&7);
    const int b_kc   = ((lane>>3)&1);

    for (int it = 0; it < niter; ++it){
        const int s = it % NSTG;
        if (tid == 0 && it + NSTG-1 < niter) issue(it + NSTG-1);
        MBARRIER_WAIT_PARITY(FULL0+8*s, (it/NSTG)&1);
        const uint32_t stg = STG0 + s*STGB;
        #pragma unroll
        for (int step = 0; step < 4; ++step){
            const int ga = a_kc + 2*step, gb = b_kc + 2*step;
            uint32_t ah[2][4], al[2][4], bh[4][4], bl[4][4];
            #pragma unroll
            for (int mt = 0; mt < 2; ++mt){
                const uint32_t aoff = stg + (uint32_t)((ga>>2)*8192 + (((ga&3)*128) + a_mrow + mt*16)*16);
                ldsm4(ah[mt], aoff);
                ldsm4(al[mt], aoff + 16384);
            }
            #pragma unroll
            for (int nt4 = 0; nt4 < 4; ++nt4){
                const uint32_t boff = stg + 32768 + (uint32_t)((gb>>2)*8192 + (((gb&3)*128) + b_nrow + nt4*16)*16);
                ldsm4(bh[nt4], boff);
                ldsm4(bl[nt4], boff + 16384);
            }
            #pragma unroll
            for (int mt = 0; mt < 2; ++mt)
                #pragma unroll
                for (int ni = 0; ni < 8; ++ni)
                    mma_bf16(acc[mt][ni], ah[mt], bh[ni>>1] + (ni&1)*2);
            #pragma unroll
            for (int mt = 0; mt < 2; ++mt)
                #pragma unroll
                for (int ni = 0; ni < 8; ++ni)
                    mma_bf16(acc[mt][ni], al[mt], bh[ni>>1] + (ni&1)*2);
            #pragma unroll
            for (int mt = 0; mt < 2; ++mt)
                #pragma unroll
                for (int ni = 0; ni < 8; ++ni)
                    mma_bf16(acc[mt][ni], ah[mt], bl[ni>>1] + (ni&1)*2);
        }
        MBARRIER_ARRIVE(EMPTY0+8*s);
    }

    float* Cb = part + (long)bz*Dd*Pp;
    #pragma unroll
    for (int mt = 0; mt < 2; ++mt){
        #pragma unroll
        for (int h = 0; h < 2; ++h){
            const int row = row0 + wm + mt*16 + h*8 + (lane>>2);
            #pragma unroll
            for (int ni = 0; ni < 8; ++ni){
                const int col = wn + ni*8 + (lane&3)*2;
                *(float2*)(Cb + (long)row*Pp + col) =
                    make_float2(acc[mt][ni][2*h], acc[mt][ni][2*h+1]);
            }
        }
    }
}

// reduce partials -> kvtS chunked [D rows][P] per batch
__global__ void reduce_kvt(const float* __restrict__ part, __nv_bfloat16* __restrict__ kvt)
{
    long i = (long)blockIdx.x*256 + threadIdx.x;
    int b = (int)(i / (Dd*Pp)); int r0 = (int)(i % (Dd*Pp));
    int d = r0 >> 7, p = r0 & 127;
    const float* q = part + ((long)b*KVS)*Dd*Pp + r0;
    float s = 0.f;
    #pragma unroll
    for (int j = 0; j < KVS; j++) s += q[(long)j*Dd*Pp];
    __nv_bfloat16 h = __float2bfloat16(s);
    __nv_bfloat16* base = kvt + (long)b*2*Dd*Pp;
    base[cidx(4, 0, d>>7, d&127, p)] = h;
    base[cidx(4, 1, d>>7, d&127, p)] = __float2bfloat16(s - __bfloat162float(h));
}

// ===================== weight conversion =====================
__global__ void wconv(const float* __restrict__ W, __nv_bfloat16* __restrict__ out, int K, int N)
{
    __shared__ float t[32][33];
    const int n0 = blockIdx.x*32, k0 = blockIdx.y*32, l = blockIdx.z;
    const float* Wl = W + (long)l*K*N;
    __nv_bfloat16* ob = out + (long)l*2*N*K;
    const int KC = K >> 5;
    for (int i = threadIdx.y; i < 32; i += 8)
        t[i][threadIdx.x] = Wl[(long)(k0+i)*N + n0 + threadIdx.x];
    __syncthreads();
    for (int i = threadIdx.y; i < 32; i += 8) {
        float v = t[threadIdx.x][i];
        const int n = n0 + i, k = k0 + threadIdx.x;
        __nv_bfloat16 h = __float2bfloat16(v);
        ob[cidx(KC, 0, n>>7, n&127, k)] = h;
        ob[cidx(KC, 1, n>>7, n&127, k)] = __float2bfloat16(v - __bfloat162float(h));
    }
}

// folded feature weights
__global__ void wfold(const float* __restrict__ Wq, const float* __restrict__ Wk,
                      const float* __restrict__ Wf,
                      __nv_bfloat16* __restrict__ oq, __nv_bfloat16* __restrict__ ok)
{
    const int which = blockIdx.z & 1, l = blockIdx.z >> 1;
    const float* Wa  = (which ? Wk : Wq) + (long)l*Dd*Dd;
    const float* Wfl = Wf + (long)l*Dd*Pp;
    __nv_bfloat16* out = (which ? ok : oq) + (long)l*2*Pp*Dd;
    const int p0 = blockIdx.x*32, c0 = blockIdx.y*32;
    __shared__ float a[32][33], bsm[32][33];
    const int tx = threadIdx.x, ty = threadIdx.y;
    float acc[4] = {0.f,0.f,0.f,0.f};
    for (int m0 = 0; m0 < Dd; m0 += 32){
        for (int i = ty; i < 32; i += 8) a[i][tx]   = Wa[(long)(c0+i)*Dd + m0+tx];
        for (int i = ty; i < 32; i += 8) bsm[i][tx] = Wfl[(long)(m0+i)*Pp + p0+tx];
        __syncthreads();
        #pragma unroll
        for (int mm = 0; mm < 32; ++mm){
            float bv = bsm[mm][tx];
            #pragma unroll
            for (int i = 0; i < 4; ++i) acc[i] = fmaf(a[ty+8*i][mm], bv, acc[i]);
        }
        __syncthreads();
    }
    #pragma unroll
    for (int i = 0; i < 4; ++i){
        const int k = c0 + ty + 8*i, n = p0 + tx;
        __nv_bfloat16 h = __float2bfloat16(acc[i]);
        out[cidx(16, 0, 0, n, k)] = h;
        out[cidx(16, 1, 0, n, k)] = __float2bfloat16(acc[i] - __bfloat162float(h));
    }
}

// folded bias: parallel over c with smem tree
__global__ void bfold(const float* __restrict__ bq, const float* __restrict__ bk,
                      const float* __restrict__ bf, const float* __restrict__ Wf,
                      float* __restrict__ obq, float* __restrict__ obk)
{
    const int which = blockIdx.x & 1, l = blockIdx.x >> 1;
    const float* bb  = (which ? bk : bq) + l*Dd;
    const float* Wfl = Wf + (long)l*Dd*Pp;
    const int p = threadIdx.x, ty = threadIdx.y;   // block (128, 8)
    float s = 0.f;
    #pragma unroll 8
    for (int c = ty; c < Dd; c += 8)
        s = fmaf(bb[c], Wfl[(long)c*Pp + p], s);
    __shared__ float sh[8][128];
    sh[ty][p] = s;
    __syncthreads();
    if (ty == 0){
        float t = bf[l*Pp + p];
        #pragma unroll
        for (int i = 0; i < 8; i++) t += sh[i][p];
        (which ? obk : obq)[l*Pp + p] = t;
    }
}

// ksum[b,p] = sum_s pkT(hi+lo)
__global__ void ksum_kernel(const __nv_bfloat16* __restrict__ pkT, float* __restrict__ ks)
{
    const int p = blockIdx.x, b = blockIdx.y, t = threadIdx.x;
    const __nv_bfloat16* base = pkT + (long)b*2*Pp*Ss;
    float s = 0.f;
    for (int o = t; o < 512; o += 256){
        #pragma unroll
        for (int pl = 0; pl < 2; ++pl){
            long e = (((long)(pl*(Ss>>5)) + (o>>2)) << 12) + (((o&3)*128 + p) << 3);
            uint4 v = *(const uint4*)(base + e);
            const __nv_bfloat162* pv = (const __nv_bfloat162*)&v;
            #pragma unroll
            for (int q = 0; q < 4; ++q)
                s += __bfloat162float(pv[q].x) + __bfloat162float(pv[q].y);
        }
    }
    __shared__ float sh[256];
    sh[t] = s; __syncthreads();
    #pragma unroll
    for (int o = 128; o > 0; o >>= 1){
        if (t < o) sh[t] += sh[t+o];
        __syncthreads();
    }
    if (!t) ks[b*Pp + p] = sh[0];
}

// z[b,s] = dot(pq(hi+lo), ksum)
__global__ void z_kernel(const __nv_bfloat16* __restrict__ pq, const float* __restrict__ ksum,
                         float* __restrict__ z)
{
    int gw = (int)((blockIdx.x*(long)blockDim.x + threadIdx.x) >> 5);
    int lane = threadIdx.x & 31;
    if (gw >= BS) return;
    const int b = gw >> 12, blk = gw >> 7, r = gw & 127;
    const float* kr = ksum + b*Pp;
    const int p0 = lane*4;
    float s = 0.f;
    #pragma unroll
    for (int pl = 0; pl < 2; ++pl){
        long e = (((long)(blk*2+pl)*4 + (p0>>5)) << 12) + ((((p0>>3)&3)*128 + r) << 3) + (p0&7);
        uint2 v = *(const uint2*)(pq + e);
        const __nv_bfloat162* pv = (const __nv_bfloat162*)&v;
        s = fmaf(__bfloat162float(pv[0].x), kr[p0],   s);
        s = fmaf(__bfloat162float(pv[0].y), kr[p0+1], s);
        s = fmaf(__bfloat162float(pv[1].x), kr[p0+2], s);
        s = fmaf(__bfloat162float(pv[1].y), kr[p0+3], s);
    }
    #pragma unroll
    for (int o = 16; o; o >>= 1) s += __shfl_xor_sync(0xffffffffu, s, o);
    if (!lane) z[gw] = s;
}

// layernorm on chunked split data
__global__ void ln_kernel(const __nv_bfloat16* __restrict__ in, const float* __restrict__ g,
                          const float* __restrict__ bta, __nv_bfloat16* __restrict__ out)
{
    const int row = blockIdx.x, t = threadIdx.x;
    const int blk = row >> 7, r = row & 127, d = 2*t;
    const long eh = cidx(16, 0, blk, r, d);
    const long el = cidx(16, 1, blk, r, d);
    __nv_bfloat162 h2 = *(const __nv_bfloat162*)(in + eh);
    __nv_bfloat162 l2 = *(const __nv_bfloat162*)(in + el);
    float vx = __bfloat162float(h2.x) + __bfloat162float(l2.x);
    float vy = __bfloat162float(h2.y) + __bfloat162float(l2.y);
    float s  = vx + vy, sq = vx*vx + vy*vy;
    #pragma unroll
    for (int o = 16; o; o >>= 1){
        s  += __shfl_xor_sync(0xffffffffu, s,  o);
        sq += __shfl_xor_sync(0xffffffffu, sq, o);
    }
    __shared__ float sh[8], shq[8];
    int w = t >> 5, lane = t & 31;
    if (!lane){ sh[w] = s; shq[w] = sq; }
    __syncthreads();
    float ts = 0.f, tq = 0.f;
    #pragma unroll
    for (int i = 0; i < 8; i++){ ts += sh[i]; tq += shq[i]; }
    float mu = ts*(1.f/Dd);
    float rv = rsqrtf(tq*(1.f/Dd) - mu*mu + 1e-5f);
    float ox = (vx-mu)*rv*g[d]   + bta[d];
    float oy = (vy-mu)*rv*g[d+1] + bta[d+1];
    __nv_bfloat16 hx = __float2bfloat16(ox), hy = __float2bfloat16(oy);
    __nv_bfloat162 oh; oh.x = hx; oh.y = hy;
    __nv_bfloat162 ol;
    ol.x = __float2bfloat16(ox - __bfloat162float(hx));
    ol.y = __float2bfloat16(oy - __bfloat162float(hy));
    *(__nv_bfloat162*)(out + eh) = oh;
    *(__nv_bfloat162*)(out + el) = ol;
}

__global__ void embed_kernel(const int* __restrict__ x, const float* __restrict__ emb,
                             const float* __restrict__ pos, __nv_bfloat16* __restrict__ h)
{
    const int token = blockIdx.x, t = threadIdx.x;
    const int s = token & (Ss-1), id = x[token];
    const int blk = token >> 7, r = token & 127, d = 2*t;
    float2 e = *(const float2*)(emb + (long)id*Dd + d);
    float2 p = *(const float2*)(pos + (long)s*Dd + d);
    float vx = e.x + p.x, vy = e.y + p.y;
    __nv_bfloat16 hx = __float2bfloat16(vx), hy = __float2bfloat16(vy);
    __nv_bfloat162 oh; oh.x = hx; oh.y = hy;
    __nv_bfloat162 ol;
    ol.x = __float2bfloat16(vx - __bfloat162float(hx));
    ol.y = __float2bfloat16(vy - __bfloat162float(hy));
    *(__nv_bfloat162*)(h + cidx(16, 0, blk, r, d)) = oh;
    *(__nv_bfloat162*)(h + cidx(16, 1, blk, r, d)) = ol;
}

// partial col sums of hS (chunked) for mean pool
__global__ void colsum_part(const __nv_bfloat16* __restrict__ in, float* __restrict__ part)
{
    const int b = blockIdx.y, ch = blockIdx.x, c = threadIdx.x;
    const int blkg = b*32 + ch;
    float s = 0.f;
    #pragma unroll
    for (int pl = 0; pl < 2; ++pl){
        long base = (((long)(blkg*2+pl)*16 + (c>>5)) << 12) + (((c>>3)&3)*128 << 3) + (c&7);
        #pragma unroll 4
        for (int i = 0; i < 128; ++i)
            s += __bfloat162float(in[base + i*8]);
    }
    part[((long)b*32 + ch)*Dd + c] = s;
}
__global__ void colsum_fin(const float* __restrict__ part, float* __restrict__ out,
                           int cols, int chunks, float scale)
{
    int b = blockIdx.x, c = threadIdx.x;
    float s = 0.f;
    for (int ch = 0; ch < chunks; ch++) s += part[((long)b*chunks+ch)*cols + c];
    out[(long)b*cols + c] = s*scale;
}

__global__ void head1_kernel(const float* __restrict__ pool, const float* __restrict__ Wh1,
                             const float* __restrict__ bh1, float* __restrict__ h1)
{
    int b = blockIdx.x;
    __shared__ float xr[Dd];
    for (int i = threadIdx.x; i < Dd; i += blockDim.x) xr[i] = pool[(long)b*Dd + i];
    __syncthreads();
    int t = threadIdx.x;
    float s = bh1[t];
    #pragma unroll 4
    for (int k = 0; k < Dd; k++) s = fmaf(xr[k], Wh1[(long)k*DHh + t], s);
    h1[(long)b*DHh + t] = fmaxf(s, 0.f);
}
__global__ void head2_kernel(const float* __restrict__ h1, const float* __restrict__ Wh2,
                             const float* __restrict__ bh2, float* __restrict__ out)
{
    int t = threadIdx.x;
    if (t < Bb*CC){
        int b = t / CC, c = t % CC;
        float s = bh2[c];
        #pragma unroll 4
        for (int k = 0; k < DHh; k++) s = fmaf(h1[(long)b*DHh + k], Wh2[(long)k*CC + c], s);
        out[t] = s;
    }
}

// ===================== launch =====================
extern "C" void kernel_launch(void* const* d_in, const int* in_sizes, int n_in,
                              void* d_out, int out_size)
{
    const int*   x   = (const int*)  d_in[0];
    const float* emb = (const float*)d_in[1];
    const float* pos = (const float*)d_in[2];
    const float* Wq  = (const float*)d_in[3];   const float* bq = (const float*)d_in[4];
    const float* Wk  = (const float*)d_in[5];   const float* bk = (const float*)d_in[6];
    const float* Wv  = (const float*)d_in[7];   const float* bv = (const float*)d_in[8];
    const float* Wf  = (const float*)d_in[9];   const float* bf = (const float*)d_in[10];
    const float* Wo  = (const float*)d_in[11];  const float* bo = (const float*)d_in[12];
    const float* lng = (const float*)d_in[13];  const float* lnb= (const float*)d_in[14];
    const float* W1  = (const float*)d_in[15];  const float* b1 = (const float*)d_in[16];
    const float* W2  = (const float*)d_in[17];  const float* b2 = (const float*)d_in[18];
    const float* Wh1 = (const float*)d_in[19];  const float* bh1= (const float*)d_in[20];
    const float* Wh2 = (const float*)d_in[21];  const float* bh2= (const float*)d_in[22];

    __nv_bfloat16 *hS,*qS,*vT,*tS,*pqS,*pkT,*mS,*kvtS,*wv,*wo,*w1,*w2,*wqf,*wkf;
    float *bqf,*bkf,*kvp,*ks,*z,*pp,*pool,*h1;
    cudaGetSymbolAddress((void**)&hS,  g_hS);   cudaGetSymbolAddress((void**)&qS,  g_qS);
    cudaGetSymbolAddress((void**)&vT,  g_vT);   cudaGetSymbolAddress((void**)&tS,  g_tS);
    cudaGetSymbolAddress((void**)&pqS, g_pqS);  cudaGetSymbolAddress((void**)&pkT, g_pkT);
    cudaGetSymbolAddress((void**)&mS,  g_mS);   cudaGetSymbolAddress((void**)&kvtS,g_kvtS);
    cudaGetSymbolAddress((void**)&wv, g_wv); cudaGetSymbolAddress((void**)&wo, g_wo);
    cudaGetSymbolAddress((void**)&w1, g_w1); cudaGetSymbolAddress((void**)&w2, g_w2);
    cudaGetSymbolAddress((void**)&wqf, g_wqf); cudaGetSymbolAddress((void**)&wkf, g_wkf);
    cudaGetSymbolAddress((void**)&bqf, g_bqf); cudaGetSymbolAddress((void**)&bkf, g_bkf);
    cudaGetSymbolAddress((void**)&kvp, g_kvp);
    cudaGetSymbolAddress((void**)&ks,  g_ks);  cudaGetSymbolAddress((void**)&z,   g_z);
    cudaGetSymbolAddress((void**)&pp,  g_pp);  cudaGetSymbolAddress((void**)&pool,g_pool);
    cudaGetSymbolAddress((void**)&h1,  g_h1);

    cudaFuncSetAttribute(gemm_mma<0,0>, cudaFuncAttributeMaxDynamicSharedMemorySize, SMEMG);
    cudaFuncSetAttribute(gemm_mma<0,1>, cudaFuncAttributeMaxDynamicSharedMemorySize, SMEMG);
    cudaFuncSetAttribute(gemm_mma<1,0>, cudaFuncAttributeMaxDynamicSharedMemorySize, SMEMG);
    cudaFuncSetAttribute(gemm_mma<1,1>, cudaFuncAttributeMaxDynamicSharedMemorySize, SMEMG);
    cudaFuncSetAttribute(gemm_mma<2,0>, cudaFuncAttributeMaxDynamicSharedMemorySize, SMEMG);
    cudaFuncSetAttribute(gemm_mma<3,0>, cudaFuncAttributeMaxDynamicSharedMemorySize, SMEMG);
    cudaFuncSetAttribute(gemm_kv,       cudaFuncAttributeMaxDynamicSharedMemorySize, SMEMG);

    dim3 wt(32, 8);
    const dim3 gDD(Dd/128, BS/128, 1);
    const dim3 gDP(1,      BS/128, 1);
    const dim3 gDF(DFf/128,BS/128, 1);
    const dim3 gAT(Dd/128, Ss/128, Bb);
    const dim3 gKV(1, Dd/128, Bb*KVS);
    const long wDD = (long)2*Dd*Dd, wPD = (long)2*Pp*Dd, wDF = (long)2*DFf*Dd;

    embed_kernel<<<BS,256>>>(x, emb, pos, hS);                          // 0
    wconv<<<dim3(Dd/32, Dd/32, Ll), wt>>>(Wv, wv, Dd, Dd);              // 1
    wfold<<<dim3(Pp/32, Dd/32, 2*Ll), wt>>>(Wq, Wk, Wf, wqf, wkf);      // 2
    bfold<<<2*Ll, dim3(128,8)>>>(bq, bk, bf, Wf, bqf, bkf);             // 3
    wconv<<<dim3(Dd/32, Dd/32, Ll), wt>>>(Wo, wo, Dd, Dd);              // 4

    for (int l = 0; l < Ll; l++){
        gemm_mma<0,1><<<gDD,256,SMEMG>>>(hS, 16, wv + l*wDD, 16, 0, bv + l*Dd, nullptr, vT, Dd, Dd);   // 5 at l=0
        if (l == 0){
            wconv<<<dim3(DFf/32, Dd/32,  Ll), wt>>>(W1, w1, Dd, DFf);
            wconv<<<dim3(Dd/32,  DFf/32, Ll), wt>>>(W2, w2, DFf, Dd);
        }
        gemm_mma<1,0><<<gDP,256,SMEMG>>>(hS, 16, wqf + l*wPD, 16, 0, bqf + l*Pp, nullptr, pqS, Pp, Dd);
        gemm_mma<1,1><<<gDP,256,SMEMG>>>(hS, 16, wkf + l*wPD, 16, 0, bkf + l*Pp, nullptr, pkT, Pp, Dd);
        ksum_kernel<<<dim3(Pp,Bb),256>>>(pkT, ks);
        gemm_kv<<<gKV,256,SMEMG>>>(vT, pkT, kvp);
        reduce_kvt<<<(Bb*Dd*Pp)/256,256>>>(kvp, kvtS);
        z_kernel<<<BS/8,256>>>(pqS, ks, z);
        gemm_mma<3,0><<<gAT,256,SMEMG>>>(pqS, 4, kvtS, 4, (long)2*Dd*Pp, nullptr, z, tS, Dd, Pp);
        gemm_mma<0,0><<<gDD,256,SMEMG>>>(tS, 16, wo + l*wDD, 16, 0, bo + l*Dd, nullptr, qS, Dd, Dd);
        ln_kernel<<<BS,256>>>(qS, lng + l*Dd, lnb + l*Dd, tS);
        gemm_mma<2,0><<<gDF,256,SMEMG>>>(tS, 16, w1 + l*wDF, 16, 0, b1 + l*DFf, nullptr, mS, DFf, Dd);
        gemm_mma<0,0><<<gDD,256,SMEMG>>>(mS, 64, w2 + l*wDF, 64, 0, b2 + l*Dd, nullptr, hS, Dd, DFf);
    }

    colsum_part<<<dim3(32,Bb),Dd>>>(hS, pp);
    colsum_fin <<<Bb,Dd>>>(pp, pool, Dd, 32, 1.0f/Ss);
    head1_kernel<<<Bb,DHh>>>(pool, Wh1, bh1, h1);
    head2_kernel<<<1,32>>>(h1, Wh2, bh2, (float*)d_out);
}